// round 9
// baseline (speedup 1.0000x reference)
#include <cuda_runtime.h>
#include <cuda_fp16.h>
#include <math.h>
#include <stdint.h>

#define MODEL_DIM 2048
#define INNER_DIM 512
#define NUM_HEADS 16
#define FFN_DIM   8192
#define MEM_TOKENS 64
#define BATCH 2
#define SEQ   2048
#define NTOK  (BATCH*SEQ)            // 4096
#define DH    (MODEL_DIM/NUM_HEADS)  // 128
#define EPSV  1e-6f

#define NCHUNK 32
#define CS     (SEQ/NCHUNK)          // 64
#define NBH    (BATCH*NUM_HEADS)     // 32

// ---------------- fp32 scratch -------------------------------------------------
__device__ float g_z    [NTOK*MODEL_DIM];
__device__ float g_glin [NTOK*MODEL_DIM];
__device__ float g_t    [NTOK*MODEL_DIM];
__device__ float g_gamma[NTOK*MODEL_DIM];
__device__ float g_ht   [NTOK*MODEL_DIM];
__device__ float g_xres [NTOK*MODEL_DIM];
__device__ float g_kvbias[2*MODEL_DIM];
__device__ float g_cp_tot [NBH*NCHUNK*DH];
__device__ float g_cp_pref[NBH*NCHUNK*DH];

// ---------------- fp16 activations ----------------------------------------------
__device__ __half g_xh  [NTOK*MODEL_DIM];
__device__ __half g_xnh [NTOK*MODEL_DIM];
__device__ __half g_zh  [NTOK*MODEL_DIM];
__device__ __half g_kh  [NTOK*MODEL_DIM];
__device__ __half g_uh  [NTOK*INNER_DIM];
__device__ __half g_hth [NTOK*MODEL_DIM];
__device__ __half g_memh[BATCH*MEM_TOKENS*MODEL_DIM];
__device__ __half g_qah [NTOK*MODEL_DIM];
__device__ __half g_kvh [BATCH*MEM_TOKENS*2*MODEL_DIM];
__device__ __half g_ctxh[NTOK*MODEL_DIM];
__device__ __half g_xn2h[NTOK*MODEL_DIM];
__device__ __half g_a1h [NTOK*FFN_DIM];

// ---------------- fp16 transposed weights [Dout, K] ----------------------------
#define DD (MODEL_DIM*MODEL_DIM)
__device__ __half g_wk [DD], g_wz [DD], g_wg [DD], g_mcw[DD];
__device__ __half g_awq[DD], g_awo[DD];
__device__ __half g_awkv[2*MODEL_DIM*MODEL_DIM];
__device__ __half g_md1[MODEL_DIM*INNER_DIM];
__device__ __half g_md2[INNER_DIM*MODEL_DIM];
__device__ __half g_f1 [MODEL_DIM*FFN_DIM];
__device__ __half g_f2 [FFN_DIM*MODEL_DIM];

// ---------------- helpers -------------------------------------------------------
__device__ __forceinline__ uint32_t smem_to_u32(const void* p) {
    uint32_t a;
    asm("{ .reg .u64 t; cvta.to.shared.u64 t, %1; cvt.u32.u64 %0, t; }" : "=r"(a) : "l"(p));
    return a;
}
#define SMEM_SWIZZLE_128B(o) ((o) ^ (((o) >> 3) & 0x70))

__device__ __forceinline__ float gelu_f(float v) {
    float t = 0.7978845608028654f * (v + 0.044715f * v * v * v);
    return 0.5f * v * (1.0f + tanhf(t));
}
__device__ __forceinline__ float sigmoid_f(float v) { return 1.0f / (1.0f + expf(-v)); }

__device__ __forceinline__ void mma16816h(float* c, const uint32_t* a, const uint32_t* b) {
    asm volatile("mma.sync.aligned.m16n8k16.row.col.f32.f16.f16.f32 "
        "{%0,%1,%2,%3}, {%4,%5,%6,%7}, {%8,%9}, {%0,%1,%2,%3};"
        : "+f"(c[0]), "+f"(c[1]), "+f"(c[2]), "+f"(c[3])
        : "r"(a[0]), "r"(a[1]), "r"(a[2]), "r"(a[3]), "r"(b[0]), "r"(b[1]));
}
#define LDMATRIX_X4(r0, r1, r2, r3, addr) \
    asm volatile("ldmatrix.sync.aligned.m8n8.x4.shared.b16 {%0,%1,%2,%3}, [%4];" \
        : "=r"(r0), "=r"(r1), "=r"(r2), "=r"(r3) : "r"(addr))
#define CP_ASYNC_16(dst, src) \
    asm volatile("cp.async.cg.shared.global [%0], [%1], 16;" :: "r"(dst), "l"(src))
#define CP_COMMIT()  asm volatile("cp.async.commit_group;" ::: "memory")
#define CP_WAIT(n)   asm volatile("cp.async.wait_group %0;" :: "n"(n) : "memory")

// ---------------- batched 2048x2048 weight transpose (8 matrices, 1 launch) -----
struct TP8 { const float* s[8]; __half* d[8]; };
__global__ void transpose_all(TP8 tp) {
    __shared__ float t[64][65];
    const float* W = tp.s[blockIdx.z];
    __half* T = tp.d[blockIdx.z];
    int d0 = blockIdx.x * 64, k0 = blockIdx.y * 64;
    int tx = threadIdx.x, ty = threadIdx.y;     // 32 x 8
    #pragma unroll
    for (int i = 0; i < 64; i += 8) {
        const float* row = W + (size_t)(k0 + ty + i) * MODEL_DIM + d0;
        t[ty + i][tx]      = row[tx];
        t[ty + i][tx + 32] = row[tx + 32];
    }
    __syncthreads();
    #pragma unroll
    for (int i = 0; i < 64; i += 8) {
        int dl = ty + i;
        float v0 = t[tx * 2][dl];
        float v1 = t[tx * 2 + 1][dl];
        *(__half2*)(T + (size_t)(d0 + dl) * MODEL_DIM + k0 + tx * 2) = __floats2half2_rn(v0, v1);
    }
}

// ---------------- generic transpose: W[K,D] -> T[D,K] fp16 ----------------------
__global__ void transpose_h2(const float* __restrict__ W, __half* __restrict__ T,
                             int K, int D) {
    __shared__ float t[64][65];
    int d0 = blockIdx.x * 64, k0 = blockIdx.y * 64;
    int tx = threadIdx.x, ty = threadIdx.y;
    #pragma unroll
    for (int i = 0; i < 64; i += 8) {
        const float* row = W + (size_t)(k0 + ty + i) * D + d0;
        t[ty + i][tx]      = row[tx];
        t[ty + i][tx + 32] = row[tx + 32];
    }
    __syncthreads();
    #pragma unroll
    for (int i = 0; i < 64; i += 8) {
        int dl = ty + i;
        float v0 = t[tx * 2][dl];
        float v1 = t[tx * 2 + 1][dl];
        *(__half2*)(T + (size_t)(d0 + dl) * K + k0 + tx * 2) = __floats2half2_rn(v0, v1);
    }
}

// ---------------- fp32 -> fp16 --------------------------------------------------
__global__ void cvt_h(const float* __restrict__ src, __half* __restrict__ H) {
    size_t i = (size_t)(blockIdx.x * blockDim.x + threadIdx.x);
    float4 v = ((const float4*)src)[i];
    ((__half2*)H)[i * 2 + 0] = __floats2half2_rn(v.x, v.y);
    ((__half2*)H)[i * 2 + 1] = __floats2half2_rn(v.z, v.w);
}

__global__ void concat_bias(const float* __restrict__ a, const float* __restrict__ b) {
    int i = blockIdx.x * blockDim.x + threadIdx.x;
    g_kvbias[i] = (i < MODEL_DIM) ? a[i] : b[i - MODEL_DIM];
}

// ---------------- fp16 HMMA GEMM: BN=256/128, BK=64, 4-stage single-barrier ------
// EPI: 0 none, 1 gelu, 2 +add1+add2, 3 +add1, 4 fused gamma/ht
template <int BN>
__device__ __forceinline__ void hg_issue(uint32_t base,
        const __half* Ab, const __half* Bb, int K, int k0, int tid) {
    #pragma unroll
    for (int i = 0; i < 4; i++) {
        int idx = tid + i * 256;
        int r = idx >> 3, u = idx & 7;
        uint32_t sw = SMEM_SWIZZLE_128B((uint32_t)(r * 128 + u * 16));
        CP_ASYNC_16(base + sw, Ab + (size_t)r * K + k0 + u * 8);
    }
    #pragma unroll
    for (int i = 0; i < (BN * 8) / 256; i++) {
        int idx = tid + i * 256;
        int r = idx >> 3, u = idx & 7;
        uint32_t sw = SMEM_SWIZZLE_128B((uint32_t)(r * 128 + u * 16));
        CP_ASYNC_16(base + 16384 + sw, Bb + (size_t)r * K + k0 + u * 8);
    }
    CP_COMMIT();
}

template <int BN, int EPI, bool WF32, bool WPL>
__global__ void __launch_bounds__(256, 1)
hgemm(const __half* __restrict__ A, const __half* __restrict__ Bp,
      const float* __restrict__ bias,
      float* __restrict__ C, __half* __restrict__ PH,
      int K, int Dout,
      const float* __restrict__ add1, const float* __restrict__ add2,
      const float* __restrict__ e3, const float* __restrict__ e4,
      float* __restrict__ og, __half* __restrict__ ohh) {
    constexpr int NJ = BN / 32;
    constexpr int STAGE = 16384 + BN * 128;
    extern __shared__ __align__(1024) char sm[];
    uint32_t sb = smem_to_u32(sm);
    int tid = threadIdx.x;
    int wid = tid >> 5, lane = tid & 31;
    int wm = wid & 1, wn = wid >> 1;       // 2 (M) x 4 (N) warps

    const __half* Ab = A  + (size_t)blockIdx.y * 128 * K;
    const __half* Bb = Bp + (size_t)blockIdx.x * BN * K;

    float acc[4][NJ][4];
    #pragma unroll
    for (int i = 0; i < 4; i++)
        #pragma unroll
        for (int j = 0; j < NJ; j++)
            #pragma unroll
            for (int q = 0; q < 4; q++) acc[i][j][q] = 0.0f;

    int NS = K >> 6;
    hg_issue<BN>(sb + 0u * STAGE, Ab, Bb, K, 0,   tid);
    hg_issue<BN>(sb + 1u * STAGE, Ab, Bb, K, 64,  tid);
    hg_issue<BN>(sb + 2u * STAGE, Ab, Bb, K, 128, tid);

    for (int s = 0; s < NS; s++) {
        CP_WAIT(2);
        __syncthreads();
        if (s + 3 < NS) hg_issue<BN>(sb + (uint32_t)((s + 3) & 3) * STAGE, Ab, Bb, K, (s + 3) * 64, tid);
        else CP_COMMIT();
        uint32_t aA = sb + (uint32_t)(s & 3) * STAGE;
        uint32_t bB = aA + 16384;
        #pragma unroll
        for (int ks = 0; ks < 4; ks++) {
            uint32_t af[4][4], bf[NJ][2];
            #pragma unroll
            for (int i = 0; i < 4; i++) {
                int row = wm * 64 + i * 16 + (lane & 15);
                int kb = ks * 32 + (lane >> 4) * 16;
                uint32_t sw = SMEM_SWIZZLE_128B((uint32_t)(row * 128 + kb));
                LDMATRIX_X4(af[i][0], af[i][1], af[i][2], af[i][3], aA + sw);
            }
            #pragma unroll
            for (int jp = 0; jp < NJ / 2; jp++) {
                int n = wn * (BN / 4) + jp * 16 + (lane >> 4) * 8 + (lane & 7);
                int kb = ks * 32 + ((lane >> 3) & 1) * 16;
                uint32_t sw = SMEM_SWIZZLE_128B((uint32_t)(n * 128 + kb));
                LDMATRIX_X4(bf[2*jp][0], bf[2*jp][1], bf[2*jp+1][0], bf[2*jp+1][1], bB + sw);
            }
            #pragma unroll
            for (int i = 0; i < 4; i++)
                #pragma unroll
                for (int j = 0; j < NJ; j++) mma16816h(acc[i][j], af[i], bf[j]);
        }
    }

    // ---- epilogue
    int gr = lane >> 2;
    int gc = (lane & 3) * 2;
    #pragma unroll
    for (int i = 0; i < 4; i++) {
        int row0 = blockIdx.y * 128 + wm * 64 + i * 16 + gr;
        #pragma unroll
        for (int j = 0; j < NJ; j++) {
            int col = blockIdx.x * BN + wn * (BN / 4) + j * 8 + gc;
            float2 bv = *(const float2*)(bias + col);
            #pragma unroll
            for (int half = 0; half < 2; half++) {
                int row = row0 + half * 8;
                size_t idx = (size_t)row * Dout + col;
                float2 o;
                o.x = acc[i][j][half * 2 + 0] + bv.x;
                o.y = acc[i][j][half * 2 + 1] + bv.y;
                if (EPI == 4) {
                    // fused gamma/ht: o = m2; gamma = sigmoid(m2+t); ht = z*sig(glin)+gamma*x
                    float2 tv = *(const float2*)(add1 + idx);
                    float2 zv = *(const float2*)(add2 + idx);
                    float2 gv = *(const float2*)(e3 + idx);
                    float2 xv = *(const float2*)(e4 + idx);
                    float gmx = sigmoid_f(o.x + tv.x);
                    float gmy = sigmoid_f(o.y + tv.y);
                    float hx = zv.x * sigmoid_f(gv.x) + gmx * xv.x;
                    float hy = zv.y * sigmoid_f(gv.y) + gmy * xv.y;
                    *(float2*)(C + idx)  = make_float2(gmx, gmy);
                    *(float2*)(og + idx) = make_float2(hx, hy);
                    *(__half2*)(ohh + idx) = __floats2half2_rn(hx, hy);
                } else {
                    if (EPI == 1) { o.x = gelu_f(o.x); o.y = gelu_f(o.y); }
                    if (EPI == 2) {
                        float2 a1 = *(const float2*)(add1 + idx);
                        float2 a2 = *(const float2*)(add2 + idx);
                        o.x += a1.x + a2.x; o.y += a1.y + a2.y;
                    }
                    if (EPI == 3) {
                        float2 a1 = *(const float2*)(add1 + idx);
                        o.x += a1.x; o.y += a1.y;
                    }
                    if (WF32) *(float2*)(C + idx) = o;
                    if (WPL)  *(__half2*)(PH + idx) = __floats2half2_rn(o.x, o.y);
                }
            }
        }
    }
}

// ---------------- RMSNorm -> fp16 (optionally also emit cvt(x)) -------------------
__global__ void rmsnorm_h(const float* __restrict__ x,
                          const float* __restrict__ w,
                          __half* __restrict__ H,
                          __half* __restrict__ XH) {
    int row = blockIdx.x;
    int t = threadIdx.x;  // 256
    const float4* xr = (const float4*)(x + (size_t)row * MODEL_DIM);
    float4 v0 = xr[t];
    float4 v1 = xr[t + 256];
    if (XH) {
        __half2* Xr = (__half2*)(XH + (size_t)row * MODEL_DIM);
        Xr[t*2]       = __floats2half2_rn(v0.x, v0.y);
        Xr[t*2+1]     = __floats2half2_rn(v0.z, v0.w);
        Xr[512+t*2]   = __floats2half2_rn(v1.x, v1.y);
        Xr[512+t*2+1] = __floats2half2_rn(v1.z, v1.w);
    }
    float s = v0.x*v0.x + v0.y*v0.y + v0.z*v0.z + v0.w*v0.w
            + v1.x*v1.x + v1.y*v1.y + v1.z*v1.z + v1.w*v1.w;
    #pragma unroll
    for (int o = 16; o > 0; o >>= 1) s += __shfl_xor_sync(0xffffffffu, s, o);
    __shared__ float red[8];
    if ((t & 31) == 0) red[t >> 5] = s;
    __syncthreads();
    float tot = red[0]+red[1]+red[2]+red[3]+red[4]+red[5]+red[6]+red[7];
    float inv = 1.0f / (sqrtf(tot / (float)MODEL_DIM) + EPSV);
    const float4* wr = (const float4*)w;
    float4 w0 = wr[t], w1 = wr[t + 256];
    __half2* Hr = (__half2*)(H + (size_t)row * MODEL_DIM);
    Hr[t*2]       = __floats2half2_rn(w0.x*v0.x*inv, w0.y*v0.y*inv);
    Hr[t*2+1]     = __floats2half2_rn(w0.z*v0.z*inv, w0.w*v0.w*inv);
    Hr[512+t*2]   = __floats2half2_rn(w1.x*v1.x*inv, w1.y*v1.y*inv);
    Hr[512+t*2+1] = __floats2half2_rn(w1.z*v1.z*inv, w1.w*v1.w*inv);
}

// ---------------- cumprod ---------------------------------------------------------
__global__ void cumprod_local(const float* __restrict__ gamma, float* __restrict__ outp) {
    int c = blockIdx.x, bh = blockIdx.y, d2 = threadIdx.x;
    size_t base = (size_t)bh * SEQ * DH + (size_t)c * CS * DH + d2;
    float p = 1.0f;
    for (int i = 0; i < CS; i++) {
        p *= gamma[base + (size_t)i * DH];
        outp[base + (size_t)i * DH] = p;
    }
    g_cp_tot[(bh * NCHUNK + c) * DH + d2] = p;
}
__global__ void cumprod_scan() {
    int lane = blockIdx.x * blockDim.x + threadIdx.x;
    int bh = lane / DH, d2 = lane % DH;
    float r = 1.0f;
    for (int c = 0; c < NCHUNK; c++) {
        int idx = (bh * NCHUNK + c) * DH + d2;
        g_cp_pref[idx] = r;
        r *= g_cp_tot[idx];
    }
}
__global__ void cumprod_apply(float* __restrict__ outp) {
    int c = blockIdx.x, bh = blockIdx.y, d2 = threadIdx.x;
    if (c == 0) return;
    float pref = g_cp_pref[(bh * NCHUNK + c) * DH + d2];
    size_t base = (size_t)bh * SEQ * DH + (size_t)c * CS * DH + d2;
    for (int i = 0; i < CS; i++) outp[base + (size_t)i * DH] *= pref;
}

// ---------------- tensor-core attention over 64 memory tokens ---------------------
#define AQ_OFF 0u
#define AK_OFF 16384u
#define AV_OFF 32768u
#define ASC_OFF 49152u
#define APS_OFF (49152u + 64u*68u*4u)
#define ATTN_SMEM2 (49152 + 64*68*4 + 8192)
__global__ void __launch_bounds__(128, 1)
attn_mma(const __half* __restrict__ qah,
         const __half* __restrict__ kvh,
         __half* __restrict__ ctxh) {
    extern __shared__ __align__(1024) char smc[];
    uint32_t sb = smem_to_u32(smc);
    float* sc = (float*)(smc + ASC_OFF);
    int stile = blockIdx.x, h = blockIdx.y, b = blockIdx.z;
    int s0 = stile * 64;
    int tid = threadIdx.x, lane = tid & 31, wid = tid >> 5;
    int wm = wid & 1, wn = wid >> 1;

    #pragma unroll
    for (int i = 0; i < 8; i++) {
        int idx = tid + i * 128;
        int r = idx >> 4, u = idx & 15;
        int c = u >> 3, uc = u & 7;
        uint32_t sw = SMEM_SWIZZLE_128B((uint32_t)(r * 128 + uc * 16));
        CP_ASYNC_16(sb + AQ_OFF + c * 8192 + sw,
                    qah + (size_t)(b * SEQ + s0 + r) * MODEL_DIM + h * 128 + u * 8);
        CP_ASYNC_16(sb + AK_OFF + c * 8192 + sw,
                    kvh + (size_t)(b * MEM_TOKENS + r) * (2 * MODEL_DIM) + h * 128 + u * 8);
    }
    CP_COMMIT();
    for (int idx = tid; idx < 8192; idx += 128) {
        int m = idx >> 7, d = idx & 127;
        __half v = kvh[(size_t)(b * MEM_TOKENS + m) * (2 * MODEL_DIM) + MODEL_DIM + h * 128 + d];
        *(__half*)(smc + AV_OFF + SMEM_SWIZZLE_128B((uint32_t)(d * 128 + m * 2))) = v;
    }
    CP_WAIT(0);
    __syncthreads();

    float acc[2][4][4];
    #pragma unroll
    for (int i = 0; i < 2; i++)
        #pragma unroll
        for (int j = 0; j < 4; j++)
            #pragma unroll
            for (int q = 0; q < 4; q++) acc[i][j][q] = 0.0f;
    #pragma unroll
    for (int c = 0; c < 2; c++) {
        uint32_t qA = sb + AQ_OFF + c * 8192;
        uint32_t kB = sb + AK_OFF + c * 8192;
        #pragma unroll
        for (int ks = 0; ks < 4; ks++) {
            uint32_t af[2][4], bf[4][2];
            #pragma unroll
            for (int i = 0; i < 2; i++) {
                int row = wm * 32 + i * 16 + (lane & 15);
                int kb = ks * 32 + (lane >> 4) * 16;
                LDMATRIX_X4(af[i][0], af[i][1], af[i][2], af[i][3],
                            qA + SMEM_SWIZZLE_128B((uint32_t)(row * 128 + kb)));
            }
            #pragma unroll
            for (int jp = 0; jp < 2; jp++) {
                int n = wn * 32 + jp * 16 + (lane >> 4) * 8 + (lane & 7);
                int kb = ks * 32 + ((lane >> 3) & 1) * 16;
                LDMATRIX_X4(bf[2*jp][0], bf[2*jp][1], bf[2*jp+1][0], bf[2*jp+1][1],
                            kB + SMEM_SWIZZLE_128B((uint32_t)(n * 128 + kb)));
            }
            #pragma unroll
            for (int i = 0; i < 2; i++)
                #pragma unroll
                for (int j = 0; j < 4; j++) mma16816h(acc[i][j], af[i], bf[j]);
        }
    }
    const float scale = 0.08838834764831845f;
    int gr = lane >> 2, gc = (lane & 3) * 2;
    #pragma unroll
    for (int i = 0; i < 2; i++)
        #pragma unroll
        for (int j = 0; j < 4; j++)
            #pragma unroll
            for (int half = 0; half < 2; half++) {
                int row = wm * 32 + i * 16 + gr + half * 8;
                int col = wn * 32 + j * 8 + gc;
                sc[row * 68 + col]     = acc[i][j][half * 2 + 0] * scale;
                sc[row * 68 + col + 1] = acc[i][j][half * 2 + 1] * scale;
            }
    __syncthreads();

    if (tid < 64) {
        float* row = &sc[tid * 68];
        float mx = -1e30f;
        for (int m = 0; m < 64; m++) mx = fmaxf(mx, row[m]);
        float s = 0.0f;
        for (int m = 0; m < 64; m++) { float e = expf(row[m] - mx); row[m] = e; s += e; }
        float inv = 1.0f / s;
        for (int m = 0; m < 64; m++)
            *(__half*)(smc + APS_OFF + SMEM_SWIZZLE_128B((uint32_t)(tid * 128 + m * 2))) =
                __float2half_rn(row[m] * inv);
    }
    __syncthreads();

    float acc2[2][8][4];
    #pragma unroll
    for (int i = 0; i < 2; i++)
        #pragma unroll
        for (int j = 0; j < 8; j++)
            #pragma unroll
            for (int q = 0; q < 4; q++) acc2[i][j][q] = 0.0f;
    #pragma unroll
    for (int ks = 0; ks < 4; ks++) {
        uint32_t af[2][4], bf[8][2];
        #pragma unroll
        for (int i = 0; i < 2; i++) {
            int row = wm * 32 + i * 16 + (lane & 15);
            int kb = ks * 32 + (lane >> 4) * 16;
            LDMATRIX_X4(af[i][0], af[i][1], af[i][2], af[i][3],
                        sb + APS_OFF + SMEM_SWIZZLE_128B((uint32_t)(row * 128 + kb)));
        }
        #pragma unroll
        for (int jp = 0; jp < 4; jp++) {
            int n = wn * 64 + jp * 16 + (lane >> 4) * 8 + (lane & 7);
            int kb = ks * 32 + ((lane >> 3) & 1) * 16;
            LDMATRIX_X4(bf[2*jp][0], bf[2*jp][1], bf[2*jp+1][0], bf[2*jp+1][1],
                        sb + AV_OFF + SMEM_SWIZZLE_128B((uint32_t)(n * 128 + kb)));
        }
        #pragma unroll
        for (int i = 0; i < 2; i++)
            #pragma unroll
            for (int j = 0; j < 8; j++) mma16816h(acc2[i][j], af[i], bf[j]);
    }
    #pragma unroll
    for (int i = 0; i < 2; i++)
        #pragma unroll
        for (int j = 0; j < 8; j++)
            #pragma unroll
            for (int half = 0; half < 2; half++) {
                int row = wm * 32 + i * 16 + gr + half * 8;
                int d = wn * 64 + j * 8 + gc;
                size_t idx = (size_t)(b * SEQ + s0 + row) * MODEL_DIM + h * 128 + d;
                *(__half2*)(ctxh + idx) =
                    __floats2half2_rn(acc2[i][j][half * 2 + 0], acc2[i][j][half * 2 + 1]);
            }
}

// ---------------- host launcher -----------------------------------------------------
extern "C" void kernel_launch(void* const* d_in, const int* in_sizes, int n_in,
                              void* d_out, int out_size) {
    bool sig = (in_sizes[3] == MODEL_DIM);
    const float *x, *memory, *wk, *bk, *wz, *bz, *wg, *bg, *n1w, *n2w;
    const float *md1, *mb1, *md2, *mb2, *mcw, *mcb;
    const float *awq, *abq, *awk, *abk, *awv, *abv, *awo, *abo;
    const float *f1, *fb1, *f2, *fb2;
    #define IN(i) ((const float*)d_in[(i)])
    if (sig) {
        x = IN(0);  memory = IN(1);
        wk = IN(4);  bk = IN(5);  wz = IN(8);  bz = IN(9);  wg = IN(10); bg = IN(11);
        n1w = IN(12); n2w = IN(13);
        md1 = IN(14); mb1 = IN(15); md2 = IN(16); mb2 = IN(17); mcw = IN(18); mcb = IN(19);
        awq = IN(20); abq = IN(21); awk = IN(22); abk = IN(23); awv = IN(24); abv = IN(25);
        awo = IN(26); abo = IN(27);
        f1 = IN(28); fb1 = IN(29); f2 = IN(30); fb2 = IN(31);
    } else {
        x = IN(0);  memory = IN(1);
        wk = IN(3);  wz = IN(5);  wg = IN(6);
        md1 = IN(7); md2 = IN(8); mcw = IN(9);
        awq = IN(10); awk = IN(11); awv = IN(12); awo = IN(13);
        f1 = IN(14); f2 = IN(15);
        bk = IN(17); bz = IN(19); bg = IN(20);
        mb1 = IN(21); mb2 = IN(22); mcb = IN(23);
        abq = IN(24); abk = IN(25); abv = IN(26); abo = IN(27);
        fb1 = IN(28); fb2 = IN(29);
        n1w = IN(30); n2w = IN(31);
    }
    #undef IN

    float *zb, *glin, *tb, *gammab, *htb, *xresb, *kvbias;
    cudaGetSymbolAddress((void**)&zb,    g_z);
    cudaGetSymbolAddress((void**)&glin,  g_glin);
    cudaGetSymbolAddress((void**)&tb,    g_t);
    cudaGetSymbolAddress((void**)&gammab,g_gamma);
    cudaGetSymbolAddress((void**)&htb,   g_ht);
    cudaGetSymbolAddress((void**)&xresb, g_xres);
    cudaGetSymbolAddress((void**)&kvbias,g_kvbias);

    __half *xh,*xnh,*zh,*kh,*uh,*hth,*memh,*qah,*kvh,*ctxh,*xn2h,*a1h;
    cudaGetSymbolAddress((void**)&xh,  g_xh);
    cudaGetSymbolAddress((void**)&xnh, g_xnh);
    cudaGetSymbolAddress((void**)&zh,  g_zh);
    cudaGetSymbolAddress((void**)&kh,  g_kh);
    cudaGetSymbolAddress((void**)&uh,  g_uh);
    cudaGetSymbolAddress((void**)&hth, g_hth);
    cudaGetSymbolAddress((void**)&memh,g_memh);
    cudaGetSymbolAddress((void**)&qah, g_qah);
    cudaGetSymbolAddress((void**)&kvh, g_kvh);
    cudaGetSymbolAddress((void**)&ctxh,g_ctxh);
    cudaGetSymbolAddress((void**)&xn2h,g_xn2h);
    cudaGetSymbolAddress((void**)&a1h, g_a1h);

    __half *wkT,*wzT,*wgT,*mcwT,*awqT,*awoT,*awkvT,*md1T,*md2T,*f1T,*f2T;
    cudaGetSymbolAddress((void**)&wkT,  g_wk);
    cudaGetSymbolAddress((void**)&wzT,  g_wz);
    cudaGetSymbolAddress((void**)&wgT,  g_wg);
    cudaGetSymbolAddress((void**)&mcwT, g_mcw);
    cudaGetSymbolAddress((void**)&awqT, g_awq);
    cudaGetSymbolAddress((void**)&awoT, g_awo);
    cudaGetSymbolAddress((void**)&awkvT,g_awkv);
    cudaGetSymbolAddress((void**)&md1T, g_md1);
    cudaGetSymbolAddress((void**)&md2T, g_md2);
    cudaGetSymbolAddress((void**)&f1T,  g_f1);
    cudaGetSymbolAddress((void**)&f2T,  g_f2);

    float* out = (float*)d_out;
    float* cum = out + (size_t)NTOK * MODEL_DIM;

    const int SM256 = 4 * (16384 + 256 * 128);   // 196608
    const int SM128 = 4 * (16384 + 128 * 128);   // 131072
    cudaFuncSetAttribute((const void*)hgemm<256,0,false,true>,  cudaFuncAttributeMaxDynamicSharedMemorySize, SM256);
    cudaFuncSetAttribute((const void*)hgemm<256,0,true,true>,   cudaFuncAttributeMaxDynamicSharedMemorySize, SM256);
    cudaFuncSetAttribute((const void*)hgemm<256,0,true,false>,  cudaFuncAttributeMaxDynamicSharedMemorySize, SM256);
    cudaFuncSetAttribute((const void*)hgemm<256,1,false,true>,  cudaFuncAttributeMaxDynamicSharedMemorySize, SM256);
    cudaFuncSetAttribute((const void*)hgemm<256,2,true,false>,  cudaFuncAttributeMaxDynamicSharedMemorySize, SM256);
    cudaFuncSetAttribute((const void*)hgemm<256,3,true,false>,  cudaFuncAttributeMaxDynamicSharedMemorySize, SM256);
    cudaFuncSetAttribute((const void*)hgemm<256,4,false,false>, cudaFuncAttributeMaxDynamicSharedMemorySize, SM256);
    cudaFuncSetAttribute((const void*)hgemm<128,1,false,true>,  cudaFuncAttributeMaxDynamicSharedMemorySize, SM128);
    cudaFuncSetAttribute((const void*)hgemm<128,0,false,true>,  cudaFuncAttributeMaxDynamicSharedMemorySize, SM128);
    cudaFuncSetAttribute(attn_mma, cudaFuncAttributeMaxDynamicSharedMemorySize, ATTN_SMEM2);

    dim3 tb8(32, 8);
    dim3 gDD(MODEL_DIM / 256, NTOK / 128);   // (8, 32)
    dim3 gDF(FFN_DIM / 256,  NTOK / 128);    // (32, 32)

    // ---- batched transposes (all eight 2048x2048 in one launch)
    TP8 tp;
    tp.s[0] = wk;  tp.d[0] = wkT;
    tp.s[1] = wz;  tp.d[1] = wzT;
    tp.s[2] = wg;  tp.d[2] = wgT;
    tp.s[3] = mcw; tp.d[3] = mcwT;
    tp.s[4] = awq; tp.d[4] = awqT;
    tp.s[5] = awo; tp.d[5] = awoT;
    tp.s[6] = awk; tp.d[6] = awkvT;
    tp.s[7] = awv; tp.d[7] = awkvT + (size_t)MODEL_DIM * MODEL_DIM;
    transpose_all<<<dim3(32, 32, 8), tb8>>>(tp);
    transpose_h2<<<dim3(INNER_DIM / 64, MODEL_DIM / 64), tb8>>>(md1, md1T, MODEL_DIM, INNER_DIM);
    transpose_h2<<<dim3(MODEL_DIM / 64, INNER_DIM / 64), tb8>>>(md2, md2T, INNER_DIM, MODEL_DIM);
    rmsnorm_h<<<NTOK, 256>>>(x, n1w, xnh, xh);   // xn + cvt(x) in one pass
    concat_bias<<<(2 * MODEL_DIM) / 256, 256>>>(abk, abv);

    // ---- projections
    hgemm<256,0,false,true><<<gDD, 256, SM256>>>(xnh, wkT, bk, nullptr, kh, MODEL_DIM, MODEL_DIM, nullptr, nullptr, nullptr, nullptr, nullptr, nullptr);
    hgemm<256,0,true,true><<<gDD, 256, SM256>>>(xnh, wzT, bz, zb, zh, MODEL_DIM, MODEL_DIM, nullptr, nullptr, nullptr, nullptr, nullptr, nullptr);
    hgemm<256,0,true,false><<<gDD, 256, SM256>>>(xh, wgT, bg, glin, nullptr, MODEL_DIM, MODEL_DIM, nullptr, nullptr, nullptr, nullptr, nullptr, nullptr);
    // ---- decay net
    hgemm<128,1,false,true><<<dim3(INNER_DIM/128, NTOK/128), 256, SM128>>>(zh, md1T, mb1, nullptr, uh, MODEL_DIM, INNER_DIM, nullptr, nullptr, nullptr, nullptr, nullptr, nullptr);
    hgemm<256,0,true,false><<<gDD, 256, SM256>>>(uh, md2T, mb2, tb, nullptr, INNER_DIM, MODEL_DIM, nullptr, nullptr, nullptr, nullptr, nullptr, nullptr);
    // ---- mcw GEMM with fused gamma/ht epilogue
    hgemm<256,4,false,false><<<gDD, 256, SM256>>>(kh, mcwT, mcb, gammab, nullptr, MODEL_DIM, MODEL_DIM, tb, zb, glin, x, htb, hth);
    // ---- cumprod (second output)
    cumprod_local<<<dim3(NCHUNK, NBH), DH>>>(gammab, cum);
    cumprod_scan<<<(NBH * DH) / 256, 256>>>();
    cumprod_apply<<<dim3(NCHUNK, NBH), DH>>>(cum);
    // ---- attention
    hgemm<256,0,false,true><<<gDD, 256, SM256>>>(hth, awqT, abq, nullptr, qah, MODEL_DIM, MODEL_DIM, nullptr, nullptr, nullptr, nullptr, nullptr, nullptr);
    cvt_h<<<(BATCH * MEM_TOKENS * MODEL_DIM / 4) / 64, 64>>>(memory, memh);
    hgemm<128,0,false,true><<<dim3(2*MODEL_DIM/128, 1), 256, SM128>>>(memh, awkvT, kvbias, nullptr, kvh, MODEL_DIM, 2*MODEL_DIM, nullptr, nullptr, nullptr, nullptr, nullptr, nullptr);
    attn_mma<<<dim3(SEQ / 64, NUM_HEADS, BATCH), 128, ATTN_SMEM2>>>(qah, kvh, ctxh);
    // ---- x_res = x + h_t + (ctx@awo + abo)
    hgemm<256,2,true,false><<<gDD, 256, SM256>>>(ctxh, awoT, abo, xresb, nullptr, MODEL_DIM, MODEL_DIM, x, htb, nullptr, nullptr, nullptr, nullptr);
    // ---- FFN + residual -> first output
    rmsnorm_h<<<NTOK, 256>>>(xresb, n2w, xn2h, nullptr);
    transpose_h2<<<dim3(FFN_DIM / 64,  MODEL_DIM / 64), tb8>>>(f1, f1T, MODEL_DIM, FFN_DIM);
    hgemm<256,1,false,true><<<gDF, 256, SM256>>>(xn2h, f1T, fb1, nullptr, a1h, MODEL_DIM, FFN_DIM, nullptr, nullptr, nullptr, nullptr, nullptr, nullptr);
    transpose_h2<<<dim3(MODEL_DIM / 64, FFN_DIM / 64),  tb8>>>(f2, f2T, FFN_DIM, MODEL_DIM);
    hgemm<256,3,true,false><<<gDD, 256, SM256>>>(a1h, f2T, fb2, out, nullptr, FFN_DIM, MODEL_DIM, xresb, nullptr, nullptr, nullptr, nullptr, nullptr);
}

// round 10
// speedup vs baseline: 1.0138x; 1.0138x over previous
#include <cuda_runtime.h>
#include <cuda_fp16.h>
#include <math.h>
#include <stdint.h>

#define MODEL_DIM 2048
#define INNER_DIM 512
#define NUM_HEADS 16
#define FFN_DIM   8192
#define MEM_TOKENS 64
#define BATCH 2
#define SEQ   2048
#define NTOK  (BATCH*SEQ)            // 4096
#define DH    (MODEL_DIM/NUM_HEADS)  // 128
#define EPSV  1e-6f

#define NCHUNK 32
#define CS     (SEQ/NCHUNK)          // 64
#define NBH    (BATCH*NUM_HEADS)     // 32

// ---------------- fp32 scratch -------------------------------------------------
__device__ float g_z    [NTOK*MODEL_DIM];
__device__ float g_glin [NTOK*MODEL_DIM];
__device__ float g_t    [NTOK*MODEL_DIM];
__device__ float g_gamma[NTOK*MODEL_DIM];
__device__ float g_ht   [NTOK*MODEL_DIM];
__device__ float g_xres [NTOK*MODEL_DIM];
__device__ float g_kvbias[2*MODEL_DIM];
__device__ float g_cp_tot [NBH*NCHUNK*DH];
__device__ float g_cp_pref[NBH*NCHUNK*DH];

// ---------------- fp16 activations ----------------------------------------------
__device__ __half g_xh  [NTOK*MODEL_DIM];
__device__ __half g_xnh [NTOK*MODEL_DIM];
__device__ __half g_zh  [NTOK*MODEL_DIM];
__device__ __half g_kh  [NTOK*MODEL_DIM];
__device__ __half g_uh  [NTOK*INNER_DIM];
__device__ __half g_hth [NTOK*MODEL_DIM];
__device__ __half g_memh[BATCH*MEM_TOKENS*MODEL_DIM];
__device__ __half g_qah [NTOK*MODEL_DIM];
__device__ __half g_kvh [BATCH*MEM_TOKENS*2*MODEL_DIM];   // [128, 4096] k|v
__device__ __half g_ctxh[NTOK*MODEL_DIM];
__device__ __half g_xn2h[NTOK*MODEL_DIM];
__device__ __half g_a1h [NTOK*FFN_DIM];

// ---------------- fp16 transposed weights [Dout, K] ----------------------------
#define DD (MODEL_DIM*MODEL_DIM)
__device__ __half g_wk [DD], g_wz [DD], g_wg [DD], g_mcw[DD];
__device__ __half g_awq[DD], g_awo[DD];
__device__ __half g_awkv[2*MODEL_DIM*MODEL_DIM];
__device__ __half g_md1[MODEL_DIM*INNER_DIM];
__device__ __half g_md2[INNER_DIM*MODEL_DIM];
__device__ __half g_f1 [MODEL_DIM*FFN_DIM];
__device__ __half g_f2 [FFN_DIM*MODEL_DIM];

// ---------------- helpers -------------------------------------------------------
__device__ __forceinline__ uint32_t smem_to_u32(const void* p) {
    uint32_t a;
    asm("{ .reg .u64 t; cvta.to.shared.u64 t, %1; cvt.u32.u64 %0, t; }" : "=r"(a) : "l"(p));
    return a;
}
#define SMEM_SWIZZLE_128B(o) ((o) ^ (((o) >> 3) & 0x70))

__device__ __forceinline__ float gelu_f(float v) {
    float t = 0.7978845608028654f * (v + 0.044715f * v * v * v);
    return 0.5f * v * (1.0f + tanhf(t));
}
__device__ __forceinline__ float sigmoid_f(float v) { return 1.0f / (1.0f + expf(-v)); }

__device__ __forceinline__ void mma16816h(float* c, const uint32_t* a, const uint32_t* b) {
    asm volatile("mma.sync.aligned.m16n8k16.row.col.f32.f16.f16.f32 "
        "{%0,%1,%2,%3}, {%4,%5,%6,%7}, {%8,%9}, {%0,%1,%2,%3};"
        : "+f"(c[0]), "+f"(c[1]), "+f"(c[2]), "+f"(c[3])
        : "r"(a[0]), "r"(a[1]), "r"(a[2]), "r"(a[3]), "r"(b[0]), "r"(b[1]));
}
#define LDMATRIX_X4(r0, r1, r2, r3, addr) \
    asm volatile("ldmatrix.sync.aligned.m8n8.x4.shared.b16 {%0,%1,%2,%3}, [%4];" \
        : "=r"(r0), "=r"(r1), "=r"(r2), "=r"(r3) : "r"(addr))
#define CP_ASYNC_16(dst, src) \
    asm volatile("cp.async.cg.shared.global [%0], [%1], 16;" :: "r"(dst), "l"(src))
#define CP_COMMIT()  asm volatile("cp.async.commit_group;" ::: "memory")
#define CP_WAIT(n)   asm volatile("cp.async.wait_group %0;" :: "n"(n) : "memory")

// ---------------- weight transpose: W[K,D] -> T[D,K] fp16, 64x64 tiles ----------
__global__ void transpose_h2(const float* __restrict__ W, __half* __restrict__ T,
                             int K, int D) {
    __shared__ float t[64][65];
    int d0 = blockIdx.x * 64, k0 = blockIdx.y * 64;
    int tx = threadIdx.x, ty = threadIdx.y;     // 32 x 8
    #pragma unroll
    for (int i = 0; i < 64; i += 8) {
        const float* row = W + (size_t)(k0 + ty + i) * D + d0;
        t[ty + i][tx]      = row[tx];
        t[ty + i][tx + 32] = row[tx + 32];
    }
    __syncthreads();
    #pragma unroll
    for (int i = 0; i < 64; i += 8) {
        int dl = ty + i;
        float v0 = t[tx * 2][dl];
        float v1 = t[tx * 2 + 1][dl];
        *(__half2*)(T + (size_t)(d0 + dl) * K + k0 + tx * 2) = __floats2half2_rn(v0, v1);
    }
}

// ---------------- fp32 -> fp16 --------------------------------------------------
__global__ void cvt_h(const float* __restrict__ src, __half* __restrict__ H) {
    size_t i = (size_t)(blockIdx.x * blockDim.x + threadIdx.x);
    float4 v = ((const float4*)src)[i];
    ((__half2*)H)[i * 2 + 0] = __floats2half2_rn(v.x, v.y);
    ((__half2*)H)[i * 2 + 1] = __floats2half2_rn(v.z, v.w);
}

__global__ void concat_bias(const float* __restrict__ a, const float* __restrict__ b) {
    int i = blockIdx.x * blockDim.x + threadIdx.x;
    g_kvbias[i] = (i < MODEL_DIM) ? a[i] : b[i - MODEL_DIM];
}

// ---------------- fp16 HMMA GEMM (exact R7 kernel) --------------------------------
// C[M,Dout] = A[M,K] @ W[Dout,K]^T + bias.  Tile 128 x BN, BK=64, 8 warps, 4-stage.
// EPI: 0 none, 1 gelu, 2 +add1+add2, 3 +add1
template <int BN>
__device__ __forceinline__ void hg_issue(uint32_t base,
        const __half* Ab, const __half* Bb, int K, int k0, int tid) {
    #pragma unroll
    for (int i = 0; i < 4; i++) {           // A: 128 rows x 8 units
        int idx = tid + i * 256;
        int r = idx >> 3, u = idx & 7;
        uint32_t sw = SMEM_SWIZZLE_128B((uint32_t)(r * 128 + u * 16));
        CP_ASYNC_16(base + sw, Ab + (size_t)r * K + k0 + u * 8);
    }
    #pragma unroll
    for (int i = 0; i < (BN * 8) / 256; i++) {  // B: BN rows x 8 units
        int idx = tid + i * 256;
        int r = idx >> 3, u = idx & 7;
        uint32_t sw = SMEM_SWIZZLE_128B((uint32_t)(r * 128 + u * 16));
        CP_ASYNC_16(base + 16384 + sw, Bb + (size_t)r * K + k0 + u * 8);
    }
    CP_COMMIT();
}

template <int BN, int EPI, bool WF32, bool WPL>
__global__ void __launch_bounds__(256, 1)
hgemm(const __half* __restrict__ A, const __half* __restrict__ Bp,
      const float* __restrict__ bias,
      float* __restrict__ C, __half* __restrict__ PH,
      int K, int Dout, const float* __restrict__ add1, const float* __restrict__ add2) {
    constexpr int NJ = BN / 32;
    constexpr int STAGE = 16384 + BN * 128;
    extern __shared__ __align__(1024) char sm[];
    uint32_t sb = smem_to_u32(sm);
    int tid = threadIdx.x;
    int wid = tid >> 5, lane = tid & 31;
    int wm = wid & 1, wn = wid >> 1;       // 2 (M) x 4 (N) warps

    const __half* Ab = A  + (size_t)blockIdx.y * 128 * K;
    const __half* Bb = Bp + (size_t)blockIdx.x * BN * K;

    float acc[4][NJ][4];
    #pragma unroll
    for (int i = 0; i < 4; i++)
        #pragma unroll
        for (int j = 0; j < NJ; j++)
            #pragma unroll
            for (int q = 0; q < 4; q++) acc[i][j][q] = 0.0f;

    int NS = K >> 6;
    hg_issue<BN>(sb + 0u * STAGE, Ab, Bb, K, 0,   tid);
    hg_issue<BN>(sb + 1u * STAGE, Ab, Bb, K, 64,  tid);
    hg_issue<BN>(sb + 2u * STAGE, Ab, Bb, K, 128, tid);

    for (int s = 0; s < NS; s++) {
        CP_WAIT(2);
        __syncthreads();
        if (s + 3 < NS) hg_issue<BN>(sb + (uint32_t)((s + 3) & 3) * STAGE, Ab, Bb, K, (s + 3) * 64, tid);
        else CP_COMMIT();
        uint32_t aA = sb + (uint32_t)(s & 3) * STAGE;
        uint32_t bB = aA + 16384;
        #pragma unroll
        for (int ks = 0; ks < 4; ks++) {
            uint32_t af[4][4], bf[NJ][2];
            #pragma unroll
            for (int i = 0; i < 4; i++) {
                int row = wm * 64 + i * 16 + (lane & 15);
                int kb = ks * 32 + (lane >> 4) * 16;
                uint32_t sw = SMEM_SWIZZLE_128B((uint32_t)(row * 128 + kb));
                LDMATRIX_X4(af[i][0], af[i][1], af[i][2], af[i][3], aA + sw);
            }
            #pragma unroll
            for (int jp = 0; jp < NJ / 2; jp++) {
                int n = wn * (BN / 4) + jp * 16 + (lane >> 4) * 8 + (lane & 7);
                int kb = ks * 32 + ((lane >> 3) & 1) * 16;
                uint32_t sw = SMEM_SWIZZLE_128B((uint32_t)(n * 128 + kb));
                LDMATRIX_X4(bf[2*jp][0], bf[2*jp][1], bf[2*jp+1][0], bf[2*jp+1][1], bB + sw);
            }
            #pragma unroll
            for (int i = 0; i < 4; i++)
                #pragma unroll
                for (int j = 0; j < NJ; j++) mma16816h(acc[i][j], af[i], bf[j]);
        }
    }

    int gr = lane >> 2;
    int gc = (lane & 3) * 2;
    #pragma unroll
    for (int i = 0; i < 4; i++) {
        int row0 = blockIdx.y * 128 + wm * 64 + i * 16 + gr;
        #pragma unroll
        for (int j = 0; j < NJ; j++) {
            int col = blockIdx.x * BN + wn * (BN / 4) + j * 8 + gc;
            float2 bv = *(const float2*)(bias + col);
            #pragma unroll
            for (int half = 0; half < 2; half++) {
                int row = row0 + half * 8;
                size_t idx = (size_t)row * Dout + col;
                float2 o;
                o.x = acc[i][j][half * 2 + 0] + bv.x;
                o.y = acc[i][j][half * 2 + 1] + bv.y;
                if (EPI == 1) { o.x = gelu_f(o.x); o.y = gelu_f(o.y); }
                if (EPI == 2) {
                    float2 a1 = *(const float2*)(add1 + idx);
                    float2 a2 = *(const float2*)(add2 + idx);
                    o.x += a1.x + a2.x; o.y += a1.y + a2.y;
                }
                if (EPI == 3) {
                    float2 a1 = *(const float2*)(add1 + idx);
                    o.x += a1.x; o.y += a1.y;
                }
                if (WF32) *(float2*)(C + idx) = o;
                if (WPL)  *(__half2*)(PH + idx) = __floats2half2_rn(o.x, o.y);
            }
        }
    }
}

// ---------------- dedicated mcw GEMM with fused gamma/ht epilogue ----------------
// Same mainloop as hgemm<256>; epilogue: m2 = acc+bias; gamma = sigmoid(m2+t);
// ht = z*sigmoid(glin) + gamma*x; writes gamma (f32), ht (f32), ht (f16).
__global__ void __launch_bounds__(256, 1)
hgemm_gamma(const __half* __restrict__ A, const __half* __restrict__ Bp,
            const float* __restrict__ bias,
            const float* __restrict__ t, const float* __restrict__ z,
            const float* __restrict__ glin, const float* __restrict__ x,
            float* __restrict__ gamma, float* __restrict__ ht,
            __half* __restrict__ hth, int K, int Dout) {
    constexpr int BN = 256;
    constexpr int NJ = BN / 32;
    constexpr int STAGE = 16384 + BN * 128;
    extern __shared__ __align__(1024) char sm[];
    uint32_t sb = smem_to_u32(sm);
    int tid = threadIdx.x;
    int wid = tid >> 5, lane = tid & 31;
    int wm = wid & 1, wn = wid >> 1;

    const __half* Ab = A  + (size_t)blockIdx.y * 128 * K;
    const __half* Bb = Bp + (size_t)blockIdx.x * BN * K;

    float acc[4][NJ][4];
    #pragma unroll
    for (int i = 0; i < 4; i++)
        #pragma unroll
        for (int j = 0; j < NJ; j++)
            #pragma unroll
            for (int q = 0; q < 4; q++) acc[i][j][q] = 0.0f;

    int NS = K >> 6;
    hg_issue<BN>(sb + 0u * STAGE, Ab, Bb, K, 0,   tid);
    hg_issue<BN>(sb + 1u * STAGE, Ab, Bb, K, 64,  tid);
    hg_issue<BN>(sb + 2u * STAGE, Ab, Bb, K, 128, tid);

    for (int s = 0; s < NS; s++) {
        CP_WAIT(2);
        __syncthreads();
        if (s + 3 < NS) hg_issue<BN>(sb + (uint32_t)((s + 3) & 3) * STAGE, Ab, Bb, K, (s + 3) * 64, tid);
        else CP_COMMIT();
        uint32_t aA = sb + (uint32_t)(s & 3) * STAGE;
        uint32_t bB = aA + 16384;
        #pragma unroll
        for (int ks = 0; ks < 4; ks++) {
            uint32_t af[4][4], bf[NJ][2];
            #pragma unroll
            for (int i = 0; i < 4; i++) {
                int row = wm * 64 + i * 16 + (lane & 15);
                int kb = ks * 32 + (lane >> 4) * 16;
                uint32_t sw = SMEM_SWIZZLE_128B((uint32_t)(row * 128 + kb));
                LDMATRIX_X4(af[i][0], af[i][1], af[i][2], af[i][3], aA + sw);
            }
            #pragma unroll
            for (int jp = 0; jp < NJ / 2; jp++) {
                int n = wn * (BN / 4) + jp * 16 + (lane >> 4) * 8 + (lane & 7);
                int kb = ks * 32 + ((lane >> 3) & 1) * 16;
                uint32_t sw = SMEM_SWIZZLE_128B((uint32_t)(n * 128 + kb));
                LDMATRIX_X4(bf[2*jp][0], bf[2*jp][1], bf[2*jp+1][0], bf[2*jp+1][1], bB + sw);
            }
            #pragma unroll
            for (int i = 0; i < 4; i++)
                #pragma unroll
                for (int j = 0; j < NJ; j++) mma16816h(acc[i][j], af[i], bf[j]);
        }
    }

    int gr = lane >> 2;
    int gc = (lane & 3) * 2;
    #pragma unroll
    for (int i = 0; i < 4; i++) {
        int row0 = blockIdx.y * 128 + wm * 64 + i * 16 + gr;
        #pragma unroll
        for (int j = 0; j < NJ; j++) {
            int col = blockIdx.x * BN + wn * (BN / 4) + j * 8 + gc;
            float2 bv = *(const float2*)(bias + col);
            #pragma unroll
            for (int half = 0; half < 2; half++) {
                int row = row0 + half * 8;
                size_t idx = (size_t)row * Dout + col;
                float m2x = acc[i][j][half * 2 + 0] + bv.x;
                float m2y = acc[i][j][half * 2 + 1] + bv.y;
                float2 tv = *(const float2*)(t + idx);
                float2 zv = *(const float2*)(z + idx);
                float2 gv = *(const float2*)(glin + idx);
                float2 xv = *(const float2*)(x + idx);
                float gmx = sigmoid_f(m2x + tv.x);
                float gmy = sigmoid_f(m2y + tv.y);
                float hx = zv.x * sigmoid_f(gv.x) + gmx * xv.x;
                float hy = zv.y * sigmoid_f(gv.y) + gmy * xv.y;
                *(float2*)(gamma + idx) = make_float2(gmx, gmy);
                *(float2*)(ht + idx)    = make_float2(hx, hy);
                *(__half2*)(hth + idx)  = __floats2half2_rn(hx, hy);
            }
        }
    }
}

// ---------------- RMSNorm -> fp16 -----------------------------------------------
__global__ void rmsnorm_h(const float* __restrict__ x,
                          const float* __restrict__ w,
                          __half* __restrict__ H) {
    int row = blockIdx.x;
    int t = threadIdx.x;  // 256
    const float4* xr = (const float4*)(x + (size_t)row * MODEL_DIM);
    float4 v0 = xr[t];
    float4 v1 = xr[t + 256];
    float s = v0.x*v0.x + v0.y*v0.y + v0.z*v0.z + v0.w*v0.w
            + v1.x*v1.x + v1.y*v1.y + v1.z*v1.z + v1.w*v1.w;
    #pragma unroll
    for (int o = 16; o > 0; o >>= 1) s += __shfl_xor_sync(0xffffffffu, s, o);
    __shared__ float red[8];
    if ((t & 31) == 0) red[t >> 5] = s;
    __syncthreads();
    float tot = red[0]+red[1]+red[2]+red[3]+red[4]+red[5]+red[6]+red[7];
    float inv = 1.0f / (sqrtf(tot / (float)MODEL_DIM) + EPSV);
    const float4* wr = (const float4*)w;
    float4 w0 = wr[t], w1 = wr[t + 256];
    __half2* Hr = (__half2*)(H + (size_t)row * MODEL_DIM);
    Hr[t*2]       = __floats2half2_rn(w0.x*v0.x*inv, w0.y*v0.y*inv);
    Hr[t*2+1]     = __floats2half2_rn(w0.z*v0.z*inv, w0.w*v0.w*inv);
    Hr[512+t*2]   = __floats2half2_rn(w1.x*v1.x*inv, w1.y*v1.y*inv);
    Hr[512+t*2+1] = __floats2half2_rn(w1.z*v1.z*inv, w1.w*v1.w*inv);
}

// ---------------- cumprod ---------------------------------------------------------
__global__ void cumprod_local(const float* __restrict__ gamma, float* __restrict__ outp) {
    int c = blockIdx.x, bh = blockIdx.y, d2 = threadIdx.x;
    size_t base = (size_t)bh * SEQ * DH + (size_t)c * CS * DH + d2;
    float p = 1.0f;
    for (int i = 0; i < CS; i++) {
        p *= gamma[base + (size_t)i * DH];
        outp[base + (size_t)i * DH] = p;
    }
    g_cp_tot[(bh * NCHUNK + c) * DH + d2] = p;
}
__global__ void cumprod_scan() {
    int lane = blockIdx.x * blockDim.x + threadIdx.x;
    int bh = lane / DH, d2 = lane % DH;
    float r = 1.0f;
    for (int c = 0; c < NCHUNK; c++) {
        int idx = (bh * NCHUNK + c) * DH + d2;
        g_cp_pref[idx] = r;
        r *= g_cp_tot[idx];
    }
}
__global__ void cumprod_apply(float* __restrict__ outp) {
    int c = blockIdx.x, bh = blockIdx.y, d2 = threadIdx.x;
    if (c == 0) return;
    float pref = g_cp_pref[(bh * NCHUNK + c) * DH + d2];
    size_t base = (size_t)bh * SEQ * DH + (size_t)c * CS * DH + d2;
    for (int i = 0; i < CS; i++) outp[base + (size_t)i * DH] *= pref;
}

// ---------------- tensor-core attention over 64 memory tokens ---------------------
#define AQ_OFF 0u
#define AK_OFF 16384u
#define AV_OFF 32768u
#define ASC_OFF 49152u
#define APS_OFF (49152u + 64u*68u*4u)
#define ATTN_SMEM2 (49152 + 64*68*4 + 8192)
__global__ void __launch_bounds__(128, 1)
attn_mma(const __half* __restrict__ qah,
         const __half* __restrict__ kvh,
         __half* __restrict__ ctxh) {
    extern __shared__ __align__(1024) char smc[];
    uint32_t sb = smem_to_u32(smc);
    float* sc = (float*)(smc + ASC_OFF);
    int stile = blockIdx.x, h = blockIdx.y, b = blockIdx.z;
    int s0 = stile * 64;
    int tid = threadIdx.x, lane = tid & 31, wid = tid >> 5;
    int wm = wid & 1, wn = wid >> 1;

    #pragma unroll
    for (int i = 0; i < 8; i++) {
        int idx = tid + i * 128;
        int r = idx >> 4, u = idx & 15;
        int c = u >> 3, uc = u & 7;
        uint32_t sw = SMEM_SWIZZLE_128B((uint32_t)(r * 128 + uc * 16));
        CP_ASYNC_16(sb + AQ_OFF + c * 8192 + sw,
                    qah + (size_t)(b * SEQ + s0 + r) * MODEL_DIM + h * 128 + u * 8);
        CP_ASYNC_16(sb + AK_OFF + c * 8192 + sw,
                    kvh + (size_t)(b * MEM_TOKENS + r) * (2 * MODEL_DIM) + h * 128 + u * 8);
    }
    CP_COMMIT();
    for (int idx = tid; idx < 8192; idx += 128) {
        int m = idx >> 7, d = idx & 127;
        __half v = kvh[(size_t)(b * MEM_TOKENS + m) * (2 * MODEL_DIM) + MODEL_DIM + h * 128 + d];
        *(__half*)(smc + AV_OFF + SMEM_SWIZZLE_128B((uint32_t)(d * 128 + m * 2))) = v;
    }
    CP_WAIT(0);
    __syncthreads();

    float acc[2][4][4];
    #pragma unroll
    for (int i = 0; i < 2; i++)
        #pragma unroll
        for (int j = 0; j < 4; j++)
            #pragma unroll
            for (int q = 0; q < 4; q++) acc[i][j][q] = 0.0f;
    #pragma unroll
    for (int c = 0; c < 2; c++) {
        uint32_t qA = sb + AQ_OFF + c * 8192;
        uint32_t kB = sb + AK_OFF + c * 8192;
        #pragma unroll
        for (int ks = 0; ks < 4; ks++) {
            uint32_t af[2][4], bf[4][2];
            #pragma unroll
            for (int i = 0; i < 2; i++) {
                int row = wm * 32 + i * 16 + (lane & 15);
                int kb = ks * 32 + (lane >> 4) * 16;
                LDMATRIX_X4(af[i][0], af[i][1], af[i][2], af[i][3],
                            qA + SMEM_SWIZZLE_128B((uint32_t)(row * 128 + kb)));
            }
            #pragma unroll
            for (int jp = 0; jp < 2; jp++) {
                int n = wn * 32 + jp * 16 + (lane >> 4) * 8 + (lane & 7);
                int kb = ks * 32 + ((lane >> 3) & 1) * 16;
                LDMATRIX_X4(bf[2*jp][0], bf[2*jp][1], bf[2*jp+1][0], bf[2*jp+1][1],
                            kB + SMEM_SWIZZLE_128B((uint32_t)(n * 128 + kb)));
            }
            #pragma unroll
            for (int i = 0; i < 2; i++)
                #pragma unroll
                for (int j = 0; j < 4; j++) mma16816h(acc[i][j], af[i], bf[j]);
        }
    }
    const float scale = 0.08838834764831845f;
    int gr = lane >> 2, gc = (lane & 3) * 2;
    #pragma unroll
    for (int i = 0; i < 2; i++)
        #pragma unroll
        for (int j = 0; j < 4; j++)
            #pragma unroll
            for (int half = 0; half < 2; half++) {
                int row = wm * 32 + i * 16 + gr + half * 8;
                int col = wn * 32 + j * 8 + gc;
                sc[row * 68 + col]     = acc[i][j][half * 2 + 0] * scale;
                sc[row * 68 + col + 1] = acc[i][j][half * 2 + 1] * scale;
            }
    __syncthreads();

    if (tid < 64) {
        float* row = &sc[tid * 68];
        float mx = -1e30f;
        for (int m = 0; m < 64; m++) mx = fmaxf(mx, row[m]);
        float s = 0.0f;
        for (int m = 0; m < 64; m++) { float e = expf(row[m] - mx); row[m] = e; s += e; }
        float inv = 1.0f / s;
        for (int m = 0; m < 64; m++)
            *(__half*)(smc + APS_OFF + SMEM_SWIZZLE_128B((uint32_t)(tid * 128 + m * 2))) =
                __float2half_rn(row[m] * inv);
    }
    __syncthreads();

    float acc2[2][8][4];
    #pragma unroll
    for (int i = 0; i < 2; i++)
        #pragma unroll
        for (int j = 0; j < 8; j++)
            #pragma unroll
            for (int q = 0; q < 4; q++) acc2[i][j][q] = 0.0f;
    #pragma unroll
    for (int ks = 0; ks < 4; ks++) {
        uint32_t af[2][4], bf[8][2];
        #pragma unroll
        for (int i = 0; i < 2; i++) {
            int row = wm * 32 + i * 16 + (lane & 15);
            int kb = ks * 32 + (lane >> 4) * 16;
            LDMATRIX_X4(af[i][0], af[i][1], af[i][2], af[i][3],
                        sb + APS_OFF + SMEM_SWIZZLE_128B((uint32_t)(row * 128 + kb)));
        }
        #pragma unroll
        for (int jp = 0; jp < 4; jp++) {
            int n = wn * 64 + jp * 16 + (lane >> 4) * 8 + (lane & 7);
            int kb = ks * 32 + ((lane >> 3) & 1) * 16;
            LDMATRIX_X4(bf[2*jp][0], bf[2*jp][1], bf[2*jp+1][0], bf[2*jp+1][1],
                        sb + AV_OFF + SMEM_SWIZZLE_128B((uint32_t)(n * 128 + kb)));
        }
        #pragma unroll
        for (int i = 0; i < 2; i++)
            #pragma unroll
            for (int j = 0; j < 8; j++) mma16816h(acc2[i][j], af[i], bf[j]);
    }
    #pragma unroll
    for (int i = 0; i < 2; i++)
        #pragma unroll
        for (int j = 0; j < 8; j++)
            #pragma unroll
            for (int half = 0; half < 2; half++) {
                int row = wm * 32 + i * 16 + gr + half * 8;
                int d = wn * 64 + j * 8 + gc;
                size_t idx = (size_t)(b * SEQ + s0 + row) * MODEL_DIM + h * 128 + d;
                *(__half2*)(ctxh + idx) =
                    __floats2half2_rn(acc2[i][j][half * 2 + 0], acc2[i][j][half * 2 + 1]);
            }
}

// ---------------- host launcher -----------------------------------------------------
extern "C" void kernel_launch(void* const* d_in, const int* in_sizes, int n_in,
                              void* d_out, int out_size) {
    bool sig = (in_sizes[3] == MODEL_DIM);
    const float *x, *memory, *wk, *bk, *wz, *bz, *wg, *bg, *n1w, *n2w;
    const float *md1, *mb1, *md2, *mb2, *mcw, *mcb;
    const float *awq, *abq, *awk, *abk, *awv, *abv, *awo, *abo;
    const float *f1, *fb1, *f2, *fb2;
    #define IN(i) ((const float*)d_in[(i)])
    if (sig) {
        x = IN(0);  memory = IN(1);
        wk = IN(4);  bk = IN(5);  wz = IN(8);  bz = IN(9);  wg = IN(10); bg = IN(11);
        n1w = IN(12); n2w = IN(13);
        md1 = IN(14); mb1 = IN(15); md2 = IN(16); mb2 = IN(17); mcw = IN(18); mcb = IN(19);
        awq = IN(20); abq = IN(21); awk = IN(22); abk = IN(23); awv = IN(24); abv = IN(25);
        awo = IN(26); abo = IN(27);
        f1 = IN(28); fb1 = IN(29); f2 = IN(30); fb2 = IN(31);
    } else {
        x = IN(0);  memory = IN(1);
        wk = IN(3);  wz = IN(5);  wg = IN(6);
        md1 = IN(7); md2 = IN(8); mcw = IN(9);
        awq = IN(10); awk = IN(11); awv = IN(12); awo = IN(13);
        f1 = IN(14); f2 = IN(15);
        bk = IN(17); bz = IN(19); bg = IN(20);
        mb1 = IN(21); mb2 = IN(22); mcb = IN(23);
        abq = IN(24); abk = IN(25); abv = IN(26); abo = IN(27);
        fb1 = IN(28); fb2 = IN(29);
        n1w = IN(30); n2w = IN(31);
    }
    #undef IN

    float *zb, *glin, *tb, *gammab, *htb, *xresb, *kvbias;
    cudaGetSymbolAddress((void**)&zb,    g_z);
    cudaGetSymbolAddress((void**)&glin,  g_glin);
    cudaGetSymbolAddress((void**)&tb,    g_t);
    cudaGetSymbolAddress((void**)&gammab,g_gamma);
    cudaGetSymbolAddress((void**)&htb,   g_ht);
    cudaGetSymbolAddress((void**)&xresb, g_xres);
    cudaGetSymbolAddress((void**)&kvbias,g_kvbias);

    __half *xh,*xnh,*zh,*kh,*uh,*hth,*memh,*qah,*kvh,*ctxh,*xn2h,*a1h;
    cudaGetSymbolAddress((void**)&xh,  g_xh);
    cudaGetSymbolAddress((void**)&xnh, g_xnh);
    cudaGetSymbolAddress((void**)&zh,  g_zh);
    cudaGetSymbolAddress((void**)&kh,  g_kh);
    cudaGetSymbolAddress((void**)&uh,  g_uh);
    cudaGetSymbolAddress((void**)&hth, g_hth);
    cudaGetSymbolAddress((void**)&memh,g_memh);
    cudaGetSymbolAddress((void**)&qah, g_qah);
    cudaGetSymbolAddress((void**)&kvh, g_kvh);
    cudaGetSymbolAddress((void**)&ctxh,g_ctxh);
    cudaGetSymbolAddress((void**)&xn2h,g_xn2h);
    cudaGetSymbolAddress((void**)&a1h, g_a1h);

    __half *wkT,*wzT,*wgT,*mcwT,*awqT,*awoT,*awkvT,*md1T,*md2T,*f1T,*f2T;
    cudaGetSymbolAddress((void**)&wkT,  g_wk);
    cudaGetSymbolAddress((void**)&wzT,  g_wz);
    cudaGetSymbolAddress((void**)&wgT,  g_wg);
    cudaGetSymbolAddress((void**)&mcwT, g_mcw);
    cudaGetSymbolAddress((void**)&awqT, g_awq);
    cudaGetSymbolAddress((void**)&awoT, g_awo);
    cudaGetSymbolAddress((void**)&awkvT,g_awkv);
    cudaGetSymbolAddress((void**)&md1T, g_md1);
    cudaGetSymbolAddress((void**)&md2T, g_md2);
    cudaGetSymbolAddress((void**)&f1T,  g_f1);
    cudaGetSymbolAddress((void**)&f2T,  g_f2);

    float* out = (float*)d_out;
    float* cum = out + (size_t)NTOK * MODEL_DIM;

    const int SM256 = 4 * (16384 + 256 * 128);   // 196608
    const int SM128 = 4 * (16384 + 128 * 128);   // 131072
    cudaFuncSetAttribute((const void*)hgemm<256,0,false,true>,  cudaFuncAttributeMaxDynamicSharedMemorySize, SM256);
    cudaFuncSetAttribute((const void*)hgemm<256,0,true,true>,   cudaFuncAttributeMaxDynamicSharedMemorySize, SM256);
    cudaFuncSetAttribute((const void*)hgemm<256,0,true,false>,  cudaFuncAttributeMaxDynamicSharedMemorySize, SM256);
    cudaFuncSetAttribute((const void*)hgemm<256,1,false,true>,  cudaFuncAttributeMaxDynamicSharedMemorySize, SM256);
    cudaFuncSetAttribute((const void*)hgemm<256,2,true,false>,  cudaFuncAttributeMaxDynamicSharedMemorySize, SM256);
    cudaFuncSetAttribute((const void*)hgemm<256,3,true,false>,  cudaFuncAttributeMaxDynamicSharedMemorySize, SM256);
    cudaFuncSetAttribute((const void*)hgemm<128,1,false,true>,  cudaFuncAttributeMaxDynamicSharedMemorySize, SM128);
    cudaFuncSetAttribute((const void*)hgemm<128,0,false,true>,  cudaFuncAttributeMaxDynamicSharedMemorySize, SM128);
    cudaFuncSetAttribute((const void*)hgemm_gamma, cudaFuncAttributeMaxDynamicSharedMemorySize, SM256);
    cudaFuncSetAttribute(attn_mma, cudaFuncAttributeMaxDynamicSharedMemorySize, ATTN_SMEM2);

    dim3 tb8(32, 8);
    dim3 gT64(MODEL_DIM / 64, MODEL_DIM / 64);
    dim3 gDD(MODEL_DIM / 256, NTOK / 128);   // (8, 32)
    dim3 gDF(FFN_DIM / 256,  NTOK / 128);    // (32, 32)

    // --- launches 1-5 (R7 ordering) ---
    transpose_h2<<<gT64, tb8>>>(wk,  wkT,  MODEL_DIM, MODEL_DIM);           // 1
    transpose_h2<<<gT64, tb8>>>(wz,  wzT,  MODEL_DIM, MODEL_DIM);           // 2
    cvt_h<<<(NTOK * MODEL_DIM / 4) / 256, 256>>>(x, xh);                    // 3
    rmsnorm_h<<<NTOK, 256>>>(x, n1w, xnh);                                  // 4
    concat_bias<<<(2 * MODEL_DIM) / 256, 256>>>(abk, abv);                  // 5
    // --- projections ---
    hgemm<256,0,false,true><<<gDD, 256, SM256>>>(xnh, wkT, bk, nullptr, kh, MODEL_DIM, MODEL_DIM, nullptr, nullptr);  // 6
    hgemm<256,0,true,true><<<gDD, 256, SM256>>>(xnh, wzT, bz, zb, zh, MODEL_DIM, MODEL_DIM, nullptr, nullptr);
    transpose_h2<<<gT64, tb8>>>(wg,  wgT,  MODEL_DIM, MODEL_DIM);
    hgemm<256,0,true,false><<<gDD, 256, SM256>>>(xh, wgT, bg, glin, nullptr, MODEL_DIM, MODEL_DIM, nullptr, nullptr);
    // --- decay net ---
    transpose_h2<<<dim3(INNER_DIM / 64, MODEL_DIM / 64), tb8>>>(md1, md1T, MODEL_DIM, INNER_DIM);
    hgemm<128,1,false,true><<<dim3(INNER_DIM/128, NTOK/128), 256, SM128>>>(zh, md1T, mb1, nullptr, uh, MODEL_DIM, INNER_DIM, nullptr, nullptr);
    transpose_h2<<<dim3(MODEL_DIM / 64, INNER_DIM / 64), tb8>>>(md2, md2T, INNER_DIM, MODEL_DIM);
    hgemm<256,0,true,false><<<gDD, 256, SM256>>>(uh, md2T, mb2, tb, nullptr, INNER_DIM, MODEL_DIM, nullptr, nullptr);
    transpose_h2<<<gT64, tb8>>>(mcw, mcwT, MODEL_DIM, MODEL_DIM);
    // --- mcw GEMM with fused gamma/ht epilogue (replaces mcw GEMM + gamma_ht) ---
    hgemm_gamma<<<gDD, 256, SM256>>>(kh, mcwT, mcb, tb, zb, glin, x, gammab, htb, hth, MODEL_DIM, MODEL_DIM);
    // --- cumprod (second output) ---
    cumprod_local<<<dim3(NCHUNK, NBH), DH>>>(gammab, cum);
    cumprod_scan<<<(NBH * DH) / 256, 256>>>();
    cumprod_apply<<<dim3(NCHUNK, NBH), DH>>>(cum);
    // --- attention ---
    transpose_h2<<<gT64, tb8>>>(awq, awqT, MODEL_DIM, MODEL_DIM);
    hgemm<256,0,false,true><<<gDD, 256, SM256>>>(hth, awqT, abq, nullptr, qah, MODEL_DIM, MODEL_DIM, nullptr, nullptr);
    transpose_h2<<<gT64, tb8>>>(awk, awkvT,                               MODEL_DIM, MODEL_DIM);
    transpose_h2<<<gT64, tb8>>>(awv, awkvT + (size_t)MODEL_DIM*MODEL_DIM, MODEL_DIM, MODEL_DIM);
    cvt_h<<<(BATCH * MEM_TOKENS * MODEL_DIM / 4) / 64, 64>>>(memory, memh);
    hgemm<128,0,false,true><<<dim3(2*MODEL_DIM/128, 1), 256, SM128>>>(memh, awkvT, kvbias, nullptr, kvh, MODEL_DIM, 2*MODEL_DIM, nullptr, nullptr);
    attn_mma<<<dim3(SEQ / 64, NUM_HEADS, BATCH), 128, ATTN_SMEM2>>>(qah, kvh, ctxh);
    // --- x_res = x + h_t + (ctx@awo + abo) ---
    transpose_h2<<<gT64, tb8>>>(awo, awoT, MODEL_DIM, MODEL_DIM);
    hgemm<256,2,true,false><<<gDD, 256, SM256>>>(ctxh, awoT, abo, xresb, nullptr, MODEL_DIM, MODEL_DIM, x, htb);
    // --- FFN + residual -> first output ---
    rmsnorm_h<<<NTOK, 256>>>(xresb, n2w, xn2h);
    transpose_h2<<<dim3(FFN_DIM / 64,  MODEL_DIM / 64), tb8>>>(f1, f1T, MODEL_DIM, FFN_DIM);
    hgemm<256,1,false,true><<<gDF, 256, SM256>>>(xn2h, f1T, fb1, nullptr, a1h, MODEL_DIM, FFN_DIM, nullptr, nullptr);
    transpose_h2<<<dim3(MODEL_DIM / 64, FFN_DIM / 64),  tb8>>>(f2, f2T, FFN_DIM, MODEL_DIM);
    hgemm<256,3,true,false><<<gDD, 256, SM256>>>(a1h, f2T, fb2, out, nullptr, FFN_DIM, MODEL_DIM, xresb, nullptr);
}

// round 13
// speedup vs baseline: 1.1556x; 1.1398x over previous
#include <cuda_runtime.h>
#include <cuda_fp16.h>
#include <math.h>
#include <stdint.h>

#define MODEL_DIM 2048
#define INNER_DIM 512
#define NUM_HEADS 16
#define FFN_DIM   8192
#define MEM_TOKENS 64
#define BATCH 2
#define SEQ   2048
#define NTOK  (BATCH*SEQ)            // 4096
#define DH    (MODEL_DIM/NUM_HEADS)  // 128
#define EPSV  1e-6f

#define NCHUNK 32
#define CS     (SEQ/NCHUNK)          // 64
#define NBH    (BATCH*NUM_HEADS)     // 32

// ---------------- fp32 scratch -------------------------------------------------
__device__ float g_z    [NTOK*MODEL_DIM];
__device__ float g_glin [NTOK*MODEL_DIM];
__device__ float g_t    [NTOK*MODEL_DIM];
__device__ float g_m2   [NTOK*MODEL_DIM];
__device__ float g_gamma[NTOK*MODEL_DIM];
__device__ float g_ht   [NTOK*MODEL_DIM];
__device__ float g_xres [NTOK*MODEL_DIM];
__device__ float g_kvbias[2*MODEL_DIM];
__device__ float g_cp_tot [NBH*NCHUNK*DH];
__device__ float g_cp_pref[NBH*NCHUNK*DH];

// ---------------- fp16 activations ----------------------------------------------
__device__ __half g_xh  [NTOK*MODEL_DIM];
__device__ __half g_xnh [NTOK*MODEL_DIM];
__device__ __half g_zh  [NTOK*MODEL_DIM];
__device__ __half g_kh  [NTOK*MODEL_DIM];
__device__ __half g_uh  [NTOK*INNER_DIM];
__device__ __half g_hth [NTOK*MODEL_DIM];
__device__ __half g_memh[BATCH*MEM_TOKENS*MODEL_DIM];
__device__ __half g_qah [NTOK*MODEL_DIM];
__device__ __half g_kvh [BATCH*MEM_TOKENS*2*MODEL_DIM];   // [128, 4096] k|v
__device__ __half g_ctxh[NTOK*MODEL_DIM];
__device__ __half g_xn2h[NTOK*MODEL_DIM];
__device__ __half g_a1h [NTOK*FFN_DIM];

// ---------------- fp16 transposed weights [Dout, K] ----------------------------
#define DD (MODEL_DIM*MODEL_DIM)
__device__ __half g_wk [DD], g_wz [DD], g_wg [DD], g_mcw[DD];
__device__ __half g_awq[DD], g_awo[DD];
__device__ __half g_awkv[2*MODEL_DIM*MODEL_DIM];
__device__ __half g_md1[MODEL_DIM*INNER_DIM];
__device__ __half g_md2[INNER_DIM*MODEL_DIM];
__device__ __half g_f1 [MODEL_DIM*FFN_DIM];
__device__ __half g_f2 [FFN_DIM*MODEL_DIM];

// ---------------- helpers -------------------------------------------------------
__device__ __forceinline__ uint32_t smem_to_u32(const void* p) {
    uint32_t a;
    asm("{ .reg .u64 t; cvta.to.shared.u64 t, %1; cvt.u32.u64 %0, t; }" : "=r"(a) : "l"(p));
    return a;
}
#define SMEM_SWIZZLE_128B(o) ((o) ^ (((o) >> 3) & 0x70))

__device__ __forceinline__ float gelu_f(float v) {
    float t = 0.7978845608028654f * (v + 0.044715f * v * v * v);
    return 0.5f * v * (1.0f + tanhf(t));
}
__device__ __forceinline__ float sigmoid_f(float v) { return 1.0f / (1.0f + expf(-v)); }

__device__ __forceinline__ void mma16816h(float* c, const uint32_t* a, const uint32_t* b) {
    asm volatile("mma.sync.aligned.m16n8k16.row.col.f32.f16.f16.f32 "
        "{%0,%1,%2,%3}, {%4,%5,%6,%7}, {%8,%9}, {%0,%1,%2,%3};"
        : "+f"(c[0]), "+f"(c[1]), "+f"(c[2]), "+f"(c[3])
        : "r"(a[0]), "r"(a[1]), "r"(a[2]), "r"(a[3]), "r"(b[0]), "r"(b[1]));
}
#define LDMATRIX_X4(r0, r1, r2, r3, addr) \
    asm volatile("ldmatrix.sync.aligned.m8n8.x4.shared.b16 {%0,%1,%2,%3}, [%4];" \
        : "=r"(r0), "=r"(r1), "=r"(r2), "=r"(r3) : "r"(addr))
#define CP_ASYNC_16(dst, src) \
    asm volatile("cp.async.cg.shared.global [%0], [%1], 16;" :: "r"(dst), "l"(src))
#define CP_COMMIT()  asm volatile("cp.async.commit_group;" ::: "memory")
#define CP_WAIT(n)   asm volatile("cp.async.wait_group %0;" :: "n"(n) : "memory")

// ---------------- weight transpose: W[K,D] -> T[D,K] fp16, 64x64 tiles ----------
__global__ void transpose_h2(const float* __restrict__ W, __half* __restrict__ T,
                             int K, int D) {
    __shared__ float t[64][65];
    int d0 = blockIdx.x * 64, k0 = blockIdx.y * 64;
    int tx = threadIdx.x, ty = threadIdx.y;     // 32 x 8
    #pragma unroll
    for (int i = 0; i < 64; i += 8) {
        const float* row = W + (size_t)(k0 + ty + i) * D + d0;
        t[ty + i][tx]      = row[tx];
        t[ty + i][tx + 32] = row[tx + 32];
    }
    __syncthreads();
    #pragma unroll
    for (int i = 0; i < 64; i += 8) {
        int dl = ty + i;
        float v0 = t[tx * 2][dl];
        float v1 = t[tx * 2 + 1][dl];
        *(__half2*)(T + (size_t)(d0 + dl) * K + k0 + tx * 2) = __floats2half2_rn(v0, v1);
    }
}

// ---------------- fp32 -> fp16 --------------------------------------------------
__global__ void cvt_h(const float* __restrict__ src, __half* __restrict__ H) {
    size_t i = (size_t)(blockIdx.x * blockDim.x + threadIdx.x);
    float4 v = ((const float4*)src)[i];
    ((__half2*)H)[i * 2 + 0] = __floats2half2_rn(v.x, v.y);
    ((__half2*)H)[i * 2 + 1] = __floats2half2_rn(v.z, v.w);
}

__global__ void concat_bias(const float* __restrict__ a, const float* __restrict__ b) {
    int i = blockIdx.x * blockDim.x + threadIdx.x;
    g_kvbias[i] = (i < MODEL_DIM) ? a[i] : b[i - MODEL_DIM];
}

// ---------------- fp16 HMMA GEMM (exact R7 kernel) --------------------------------
// C[M,Dout] = A[M,K] @ W[Dout,K]^T + bias.  Tile 128 x BN, BK=64, 8 warps, 4-stage.
// EPI: 0 none, 1 gelu, 2 +add1+add2, 3 +add1
template <int BN>
__device__ __forceinline__ void hg_issue(uint32_t base,
        const __half* Ab, const __half* Bb, int K, int k0, int tid) {
    #pragma unroll
    for (int i = 0; i < 4; i++) {           // A: 128 rows x 8 units
        int idx = tid + i * 256;
        int r = idx >> 3, u = idx & 7;
        uint32_t sw = SMEM_SWIZZLE_128B((uint32_t)(r * 128 + u * 16));
        CP_ASYNC_16(base + sw, Ab + (size_t)r * K + k0 + u * 8);
    }
    #pragma unroll
    for (int i = 0; i < (BN * 8) / 256; i++) {  // B: BN rows x 8 units
        int idx = tid + i * 256;
        int r = idx >> 3, u = idx & 7;
        uint32_t sw = SMEM_SWIZZLE_128B((uint32_t)(r * 128 + u * 16));
        CP_ASYNC_16(base + 16384 + sw, Bb + (size_t)r * K + k0 + u * 8);
    }
    CP_COMMIT();
}

template <int BN, int EPI, bool WF32, bool WPL>
__global__ void __launch_bounds__(256, 1)
hgemm(const __half* __restrict__ A, const __half* __restrict__ Bp,
      const float* __restrict__ bias,
      float* __restrict__ C, __half* __restrict__ PH,
      int K, int Dout, const float* __restrict__ add1, const float* __restrict__ add2) {
    constexpr int NJ = BN / 32;
    constexpr int STAGE = 16384 + BN * 128;
    extern __shared__ __align__(1024) char sm[];
    uint32_t sb = smem_to_u32(sm);
    int tid = threadIdx.x;
    int wid = tid >> 5, lane = tid & 31;
    int wm = wid & 1, wn = wid >> 1;       // 2 (M) x 4 (N) warps

    const __half* Ab = A  + (size_t)blockIdx.y * 128 * K;
    const __half* Bb = Bp + (size_t)blockIdx.x * BN * K;

    float acc[4][NJ][4];
    #pragma unroll
    for (int i = 0; i < 4; i++)
        #pragma unroll
        for (int j = 0; j < NJ; j++)
            #pragma unroll
            for (int q = 0; q < 4; q++) acc[i][j][q] = 0.0f;

    int NS = K >> 6;
    hg_issue<BN>(sb + 0u * STAGE, Ab, Bb, K, 0,   tid);
    hg_issue<BN>(sb + 1u * STAGE, Ab, Bb, K, 64,  tid);
    hg_issue<BN>(sb + 2u * STAGE, Ab, Bb, K, 128, tid);

    for (int s = 0; s < NS; s++) {
        CP_WAIT(2);
        __syncthreads();
        if (s + 3 < NS) hg_issue<BN>(sb + (uint32_t)((s + 3) & 3) * STAGE, Ab, Bb, K, (s + 3) * 64, tid);
        else CP_COMMIT();
        uint32_t aA = sb + (uint32_t)(s & 3) * STAGE;
        uint32_t bB = aA + 16384;
        #pragma unroll
        for (int ks = 0; ks < 4; ks++) {
            uint32_t af[4][4], bf[NJ][2];
            #pragma unroll
            for (int i = 0; i < 4; i++) {
                int row = wm * 64 + i * 16 + (lane & 15);
                int kb = ks * 32 + (lane >> 4) * 16;
                uint32_t sw = SMEM_SWIZZLE_128B((uint32_t)(row * 128 + kb));
                LDMATRIX_X4(af[i][0], af[i][1], af[i][2], af[i][3], aA + sw);
            }
            #pragma unroll
            for (int jp = 0; jp < NJ / 2; jp++) {
                int n = wn * (BN / 4) + jp * 16 + (lane >> 4) * 8 + (lane & 7);
                int kb = ks * 32 + ((lane >> 3) & 1) * 16;
                uint32_t sw = SMEM_SWIZZLE_128B((uint32_t)(n * 128 + kb));
                LDMATRIX_X4(bf[2*jp][0], bf[2*jp][1], bf[2*jp+1][0], bf[2*jp+1][1], bB + sw);
            }
            #pragma unroll
            for (int i = 0; i < 4; i++)
                #pragma unroll
                for (int j = 0; j < NJ; j++) mma16816h(acc[i][j], af[i], bf[j]);
        }
    }

    int gr = lane >> 2;
    int gc = (lane & 3) * 2;
    #pragma unroll
    for (int i = 0; i < 4; i++) {
        int row0 = blockIdx.y * 128 + wm * 64 + i * 16 + gr;
        #pragma unroll
        for (int j = 0; j < NJ; j++) {
            int col = blockIdx.x * BN + wn * (BN / 4) + j * 8 + gc;
            float2 bv = *(const float2*)(bias + col);
            #pragma unroll
            for (int half = 0; half < 2; half++) {
                int row = row0 + half * 8;
                size_t idx = (size_t)row * Dout + col;
                float2 o;
                o.x = acc[i][j][half * 2 + 0] + bv.x;
                o.y = acc[i][j][half * 2 + 1] + bv.y;
                if (EPI == 1) { o.x = gelu_f(o.x); o.y = gelu_f(o.y); }
                if (EPI == 2) {
                    float2 a1 = *(const float2*)(add1 + idx);
                    float2 a2 = *(const float2*)(add2 + idx);
                    o.x += a1.x + a2.x; o.y += a1.y + a2.y;
                }
                if (EPI == 3) {
                    float2 a1 = *(const float2*)(add1 + idx);
                    o.x += a1.x; o.y += a1.y;
                }
                if (WF32) *(float2*)(C + idx) = o;
                if (WPL)  *(__half2*)(PH + idx) = __floats2half2_rn(o.x, o.y);
            }
        }
    }
}

// ---------------- RMSNorm -> fp16 -----------------------------------------------
__global__ void rmsnorm_h(const float* __restrict__ x,
                          const float* __restrict__ w,
                          __half* __restrict__ H) {
    int row = blockIdx.x;
    int t = threadIdx.x;  // 256
    const float4* xr = (const float4*)(x + (size_t)row * MODEL_DIM);
    float4 v0 = xr[t];
    float4 v1 = xr[t + 256];
    float s = v0.x*v0.x + v0.y*v0.y + v0.z*v0.z + v0.w*v0.w
            + v1.x*v1.x + v1.y*v1.y + v1.z*v1.z + v1.w*v1.w;
    #pragma unroll
    for (int o = 16; o > 0; o >>= 1) s += __shfl_xor_sync(0xffffffffu, s, o);
    __shared__ float red[8];
    if ((t & 31) == 0) red[t >> 5] = s;
    __syncthreads();
    float tot = red[0]+red[1]+red[2]+red[3]+red[4]+red[5]+red[6]+red[7];
    float inv = 1.0f / (sqrtf(tot / (float)MODEL_DIM) + EPSV);
    const float4* wr = (const float4*)w;
    float4 w0 = wr[t], w1 = wr[t + 256];
    __half2* Hr = (__half2*)(H + (size_t)row * MODEL_DIM);
    Hr[t*2]       = __floats2half2_rn(w0.x*v0.x*inv, w0.y*v0.y*inv);
    Hr[t*2+1]     = __floats2half2_rn(w0.z*v0.z*inv, w0.w*v0.w*inv);
    Hr[512+t*2]   = __floats2half2_rn(w1.x*v1.x*inv, w1.y*v1.y*inv);
    Hr[512+t*2+1] = __floats2half2_rn(w1.z*v1.z*inv, w1.w*v1.w*inv);
}

// ---------------- gamma / h_t elementwise (+ ht fp16) ----------------------------
__global__ void gamma_ht_kernel(const float* __restrict__ t,
                                const float* __restrict__ m2,
                                const float* __restrict__ z,
                                const float* __restrict__ glin,
                                const float* __restrict__ x,
                                float* __restrict__ gamma,
                                float* __restrict__ ht,
                                __half* __restrict__ hth) {
    size_t i = (size_t)(blockIdx.x * blockDim.x + threadIdx.x);
    float4 tv = ((const float4*)t)[i];
    float4 mv = ((const float4*)m2)[i];
    float4 zv = ((const float4*)z)[i];
    float4 gv = ((const float4*)glin)[i];
    float4 xv = ((const float4*)x)[i];
    float4 gm, h;
    gm.x = sigmoid_f(tv.x + mv.x); gm.y = sigmoid_f(tv.y + mv.y);
    gm.z = sigmoid_f(tv.z + mv.z); gm.w = sigmoid_f(tv.w + mv.w);
    h.x = zv.x * sigmoid_f(gv.x) + gm.x * xv.x;
    h.y = zv.y * sigmoid_f(gv.y) + gm.y * xv.y;
    h.z = zv.z * sigmoid_f(gv.z) + gm.z * xv.z;
    h.w = zv.w * sigmoid_f(gv.w) + gm.w * xv.w;
    ((float4*)gamma)[i] = gm;
    ((float4*)ht)[i] = h;
    ((__half2*)hth)[i*2]   = __floats2half2_rn(h.x, h.y);
    ((__half2*)hth)[i*2+1] = __floats2half2_rn(h.z, h.w);
}

// ---------------- cumprod ---------------------------------------------------------
__global__ void cumprod_local(const float* __restrict__ gamma, float* __restrict__ outp) {
    int c = blockIdx.x, bh = blockIdx.y, d2 = threadIdx.x;
    size_t base = (size_t)bh * SEQ * DH + (size_t)c * CS * DH + d2;
    float p = 1.0f;
    for (int i = 0; i < CS; i++) {
        p *= gamma[base + (size_t)i * DH];
        outp[base + (size_t)i * DH] = p;
    }
    g_cp_tot[(bh * NCHUNK + c) * DH + d2] = p;
}
__global__ void cumprod_scan() {
    int lane = blockIdx.x * blockDim.x + threadIdx.x;
    int bh = lane / DH, d2 = lane % DH;
    float r = 1.0f;
    for (int c = 0; c < NCHUNK; c++) {
        int idx = (bh * NCHUNK + c) * DH + d2;
        g_cp_pref[idx] = r;
        r *= g_cp_tot[idx];
    }
}
__global__ void cumprod_apply(float* __restrict__ outp) {
    int c = blockIdx.x, bh = blockIdx.y, d2 = threadIdx.x;
    if (c == 0) return;
    float pref = g_cp_pref[(bh * NCHUNK + c) * DH + d2];
    size_t base = (size_t)bh * SEQ * DH + (size_t)c * CS * DH + d2;
    for (int i = 0; i < CS; i++) outp[base + (size_t)i * DH] *= pref;
}

// ---------------- tensor-core attention over 64 memory tokens ---------------------
#define AQ_OFF 0u
#define AK_OFF 16384u
#define AV_OFF 32768u
#define ASC_OFF 49152u
#define APS_OFF (49152u + 64u*68u*4u)
#define ATTN_SMEM2 (49152 + 64*68*4 + 8192)
__global__ void __launch_bounds__(128, 1)
attn_mma(const __half* __restrict__ qah,
         const __half* __restrict__ kvh,
         __half* __restrict__ ctxh) {
    extern __shared__ __align__(1024) char smc[];
    uint32_t sb = smem_to_u32(smc);
    float* sc = (float*)(smc + ASC_OFF);
    int stile = blockIdx.x, h = blockIdx.y, b = blockIdx.z;
    int s0 = stile * 64;
    int tid = threadIdx.x, lane = tid & 31, wid = tid >> 5;
    int wm = wid & 1, wn = wid >> 1;

    #pragma unroll
    for (int i = 0; i < 8; i++) {
        int idx = tid + i * 128;
        int r = idx >> 4, u = idx & 15;
        int c = u >> 3, uc = u & 7;
        uint32_t sw = SMEM_SWIZZLE_128B((uint32_t)(r * 128 + uc * 16));
        CP_ASYNC_16(sb + AQ_OFF + c * 8192 + sw,
                    qah + (size_t)(b * SEQ + s0 + r) * MODEL_DIM + h * 128 + u * 8);
        CP_ASYNC_16(sb + AK_OFF + c * 8192 + sw,
                    kvh + (size_t)(b * MEM_TOKENS + r) * (2 * MODEL_DIM) + h * 128 + u * 8);
    }
    CP_COMMIT();
    for (int idx = tid; idx < 8192; idx += 128) {
        int m = idx >> 7, d = idx & 127;
        __half v = kvh[(size_t)(b * MEM_TOKENS + m) * (2 * MODEL_DIM) + MODEL_DIM + h * 128 + d];
        *(__half*)(smc + AV_OFF + SMEM_SWIZZLE_128B((uint32_t)(d * 128 + m * 2))) = v;
    }
    CP_WAIT(0);
    __syncthreads();

    float acc[2][4][4];
    #pragma unroll
    for (int i = 0; i < 2; i++)
        #pragma unroll
        for (int j = 0; j < 4; j++)
            #pragma unroll
            for (int q = 0; q < 4; q++) acc[i][j][q] = 0.0f;
    #pragma unroll
    for (int c = 0; c < 2; c++) {
        uint32_t qA = sb + AQ_OFF + c * 8192;
        uint32_t kB = sb + AK_OFF + c * 8192;
        #pragma unroll
        for (int ks = 0; ks < 4; ks++) {
            uint32_t af[2][4], bf[4][2];
            #pragma unroll
            for (int i = 0; i < 2; i++) {
                int row = wm * 32 + i * 16 + (lane & 15);
                int kb = ks * 32 + (lane >> 4) * 16;
                LDMATRIX_X4(af[i][0], af[i][1], af[i][2], af[i][3],
                            qA + SMEM_SWIZZLE_128B((uint32_t)(row * 128 + kb)));
            }
            #pragma unroll
            for (int jp = 0; jp < 2; jp++) {
                int n = wn * 32 + jp * 16 + (lane >> 4) * 8 + (lane & 7);
                int kb = ks * 32 + ((lane >> 3) & 1) * 16;
                LDMATRIX_X4(bf[2*jp][0], bf[2*jp][1], bf[2*jp+1][0], bf[2*jp+1][1],
                            kB + SMEM_SWIZZLE_128B((uint32_t)(n * 128 + kb)));
            }
            #pragma unroll
            for (int i = 0; i < 2; i++)
                #pragma unroll
                for (int j = 0; j < 4; j++) mma16816h(acc[i][j], af[i], bf[j]);
        }
    }
    const float scale = 0.08838834764831845f;
    int gr = lane >> 2, gc = (lane & 3) * 2;
    #pragma unroll
    for (int i = 0; i < 2; i++)
        #pragma unroll
        for (int j = 0; j < 4; j++)
            #pragma unroll
            for (int half = 0; half < 2; half++) {
                int row = wm * 32 + i * 16 + gr + half * 8;
                int col = wn * 32 + j * 8 + gc;
                sc[row * 68 + col]     = acc[i][j][half * 2 + 0] * scale;
                sc[row * 68 + col + 1] = acc[i][j][half * 2 + 1] * scale;
            }
    __syncthreads();

    if (tid < 64) {
        float* row = &sc[tid * 68];
        float mx = -1e30f;
        for (int m = 0; m < 64; m++) mx = fmaxf(mx, row[m]);
        float s = 0.0f;
        for (int m = 0; m < 64; m++) { float e = expf(row[m] - mx); row[m] = e; s += e; }
        float inv = 1.0f / s;
        for (int m = 0; m < 64; m++)
            *(__half*)(smc + APS_OFF + SMEM_SWIZZLE_128B((uint32_t)(tid * 128 + m * 2))) =
                __float2half_rn(row[m] * inv);
    }
    __syncthreads();

    float acc2[2][8][4];
    #pragma unroll
    for (int i = 0; i < 2; i++)
        #pragma unroll
        for (int j = 0; j < 8; j++)
            #pragma unroll
            for (int q = 0; q < 4; q++) acc2[i][j][q] = 0.0f;
    #pragma unroll
    for (int ks = 0; ks < 4; ks++) {
        uint32_t af[2][4], bf[8][2];
        #pragma unroll
        for (int i = 0; i < 2; i++) {
            int row = wm * 32 + i * 16 + (lane & 15);
            int kb = ks * 32 + (lane >> 4) * 16;
            LDMATRIX_X4(af[i][0], af[i][1], af[i][2], af[i][3],
                        sb + APS_OFF + SMEM_SWIZZLE_128B((uint32_t)(row * 128 + kb)));
        }
        #pragma unroll
        for (int jp = 0; jp < 4; jp++) {
            int n = wn * 64 + jp * 16 + (lane >> 4) * 8 + (lane & 7);
            int kb = ks * 32 + ((lane >> 3) & 1) * 16;
            LDMATRIX_X4(bf[2*jp][0], bf[2*jp][1], bf[2*jp+1][0], bf[2*jp+1][1],
                        sb + AV_OFF + SMEM_SWIZZLE_128B((uint32_t)(n * 128 + kb)));
        }
        #pragma unroll
        for (int i = 0; i < 2; i++)
            #pragma unroll
            for (int j = 0; j < 8; j++) mma16816h(acc2[i][j], af[i], bf[j]);
    }
    #pragma unroll
    for (int i = 0; i < 2; i++)
        #pragma unroll
        for (int j = 0; j < 8; j++)
            #pragma unroll
            for (int half = 0; half < 2; half++) {
                int row = wm * 32 + i * 16 + gr + half * 8;
                int d = wn * 64 + j * 8 + gc;
                size_t idx = (size_t)(b * SEQ + s0 + row) * MODEL_DIM + h * 128 + d;
                *(__half2*)(ctxh + idx) =
                    __floats2half2_rn(acc2[i][j][half * 2 + 0], acc2[i][j][half * 2 + 1]);
            }
}

// ---------------- one-time stream/event resources --------------------------------
// Created once on the first call (correctness run, before the harness's pre-capture
// memory baseline); reused on every later call, so nothing is allocated during
// capture or replay. Every call issues the identical launch DAG.
static cudaStream_t g_s1 = nullptr, g_s2 = nullptr;
static cudaEvent_t  ge0, ge_rms, ge_twz, ge_tmd1, ge_tmd2, ge_tmcw, ge_twg, ge_tawq,
                    ge_tawo, ge_tf1, ge_tf2, ge_prep, ge_glin, ge_gamma, ge_kv, ge_cum;

// ---------------- host launcher -----------------------------------------------------
extern "C" void kernel_launch(void* const* d_in, const int* in_sizes, int n_in,
                              void* d_out, int out_size) {
    bool sig = (in_sizes[3] == MODEL_DIM);
    const float *x, *memory, *wk, *bk, *wz, *bz, *wg, *bg, *n1w, *n2w;
    const float *md1, *mb1, *md2, *mb2, *mcw, *mcb;
    const float *awq, *abq, *awk, *abk, *awv, *abv, *awo, *abo;
    const float *f1, *fb1, *f2, *fb2;
    #define IN(i) ((const float*)d_in[(i)])
    if (sig) {
        x = IN(0);  memory = IN(1);
        wk = IN(4);  bk = IN(5);  wz = IN(8);  bz = IN(9);  wg = IN(10); bg = IN(11);
        n1w = IN(12); n2w = IN(13);
        md1 = IN(14); mb1 = IN(15); md2 = IN(16); mb2 = IN(17); mcw = IN(18); mcb = IN(19);
        awq = IN(20); abq = IN(21); awk = IN(22); abk = IN(23); awv = IN(24); abv = IN(25);
        awo = IN(26); abo = IN(27);
        f1 = IN(28); fb1 = IN(29); f2 = IN(30); fb2 = IN(31);
    } else {
        x = IN(0);  memory = IN(1);
        wk = IN(3);  wz = IN(5);  wg = IN(6);
        md1 = IN(7); md2 = IN(8); mcw = IN(9);
        awq = IN(10); awk = IN(11); awv = IN(12); awo = IN(13);
        f1 = IN(14); f2 = IN(15);
        bk = IN(17); bz = IN(19); bg = IN(20);
        mb1 = IN(21); mb2 = IN(22); mcb = IN(23);
        abq = IN(24); abk = IN(25); abv = IN(26); abo = IN(27);
        fb1 = IN(28); fb2 = IN(29);
        n1w = IN(30); n2w = IN(31);
    }
    #undef IN

    float *zb, *glin, *tb, *m2b, *gammab, *htb, *xresb, *kvbias;
    cudaGetSymbolAddress((void**)&zb,    g_z);
    cudaGetSymbolAddress((void**)&glin,  g_glin);
    cudaGetSymbolAddress((void**)&tb,    g_t);
    cudaGetSymbolAddress((void**)&m2b,   g_m2);
    cudaGetSymbolAddress((void**)&gammab,g_gamma);
    cudaGetSymbolAddress((void**)&htb,   g_ht);
    cudaGetSymbolAddress((void**)&xresb, g_xres);
    cudaGetSymbolAddress((void**)&kvbias,g_kvbias);

    __half *xh,*xnh,*zh,*kh,*uh,*hth,*memh,*qah,*kvh,*ctxh,*xn2h,*a1h;
    cudaGetSymbolAddress((void**)&xh,  g_xh);
    cudaGetSymbolAddress((void**)&xnh, g_xnh);
    cudaGetSymbolAddress((void**)&zh,  g_zh);
    cudaGetSymbolAddress((void**)&kh,  g_kh);
    cudaGetSymbolAddress((void**)&uh,  g_uh);
    cudaGetSymbolAddress((void**)&hth, g_hth);
    cudaGetSymbolAddress((void**)&memh,g_memh);
    cudaGetSymbolAddress((void**)&qah, g_qah);
    cudaGetSymbolAddress((void**)&kvh, g_kvh);
    cudaGetSymbolAddress((void**)&ctxh,g_ctxh);
    cudaGetSymbolAddress((void**)&xn2h,g_xn2h);
    cudaGetSymbolAddress((void**)&a1h, g_a1h);

    __half *wkT,*wzT,*wgT,*mcwT,*awqT,*awoT,*awkvT,*md1T,*md2T,*f1T,*f2T;
    cudaGetSymbolAddress((void**)&wkT,  g_wk);
    cudaGetSymbolAddress((void**)&wzT,  g_wz);
    cudaGetSymbolAddress((void**)&wgT,  g_wg);
    cudaGetSymbolAddress((void**)&mcwT, g_mcw);
    cudaGetSymbolAddress((void**)&awqT, g_awq);
    cudaGetSymbolAddress((void**)&awoT, g_awo);
    cudaGetSymbolAddress((void**)&awkvT,g_awkv);
    cudaGetSymbolAddress((void**)&md1T, g_md1);
    cudaGetSymbolAddress((void**)&md2T, g_md2);
    cudaGetSymbolAddress((void**)&f1T,  g_f1);
    cudaGetSymbolAddress((void**)&f2T,  g_f2);

    float* out = (float*)d_out;
    float* cum = out + (size_t)NTOK * MODEL_DIM;

    const int SM256 = 4 * (16384 + 256 * 128);   // 196608
    const int SM128 = 4 * (16384 + 128 * 128);   // 131072
    cudaFuncSetAttribute((const void*)hgemm<256,0,false,true>,  cudaFuncAttributeMaxDynamicSharedMemorySize, SM256);
    cudaFuncSetAttribute((const void*)hgemm<256,0,true,true>,   cudaFuncAttributeMaxDynamicSharedMemorySize, SM256);
    cudaFuncSetAttribute((const void*)hgemm<256,0,true,false>,  cudaFuncAttributeMaxDynamicSharedMemorySize, SM256);
    cudaFuncSetAttribute((const void*)hgemm<256,1,false,true>,  cudaFuncAttributeMaxDynamicSharedMemorySize, SM256);
    cudaFuncSetAttribute((const void*)hgemm<256,2,true,false>,  cudaFuncAttributeMaxDynamicSharedMemorySize, SM256);
    cudaFuncSetAttribute((const void*)hgemm<256,3,true,false>,  cudaFuncAttributeMaxDynamicSharedMemorySize, SM256);
    cudaFuncSetAttribute((const void*)hgemm<128,1,false,true>,  cudaFuncAttributeMaxDynamicSharedMemorySize, SM128);
    cudaFuncSetAttribute((const void*)hgemm<128,0,false,true>,  cudaFuncAttributeMaxDynamicSharedMemorySize, SM128);
    cudaFuncSetAttribute(attn_mma, cudaFuncAttributeMaxDynamicSharedMemorySize, ATTN_SMEM2);

    dim3 tb8(32, 8);
    dim3 gT64(MODEL_DIM / 64, MODEL_DIM / 64);
    dim3 gDD(MODEL_DIM / 256, NTOK / 128);   // (8, 32)
    dim3 gDF(FFN_DIM / 256,  NTOK / 128);    // (32, 32)

    // one-time resource creation (first call; before pre-capture baseline)
    if (g_s1 == nullptr) {
        cudaStreamCreateWithFlags(&g_s1, cudaStreamNonBlocking);
        cudaStreamCreateWithFlags(&g_s2, cudaStreamNonBlocking);
        cudaEvent_t* evs[16] = {&ge0,&ge_rms,&ge_twz,&ge_tmd1,&ge_tmd2,&ge_tmcw,&ge_twg,&ge_tawq,
                                &ge_tawo,&ge_tf1,&ge_tf2,&ge_prep,&ge_glin,&ge_gamma,&ge_kv,&ge_cum};
        for (int i = 0; i < 16; i++) cudaEventCreateWithFlags(evs[i], cudaEventDisableTiming);
    }
    cudaStream_t s1 = g_s1, s2 = g_s2;

    // ---------- fork (every event is RECORDED before any WAIT on it, in host order)
    cudaEventRecord(ge0, 0);
    cudaStreamWaitEvent(s1, ge0, 0);
    cudaStreamWaitEvent(s2, ge0, 0);

    // ---- s2: prep (records ge_prep BEFORE s1 waits on it) ----
    cvt_h<<<(NTOK * MODEL_DIM / 4) / 256, 256, 0, s2>>>(x, xh);
    concat_bias<<<(2 * MODEL_DIM) / 256, 256, 0, s2>>>(abk, abv);
    cvt_h<<<(BATCH * MEM_TOKENS * MODEL_DIM / 4) / 64, 64, 0, s2>>>(memory, memh);
    cudaEventRecord(ge_prep, s2);

    // ---- main: rmsnorm (records ge_rms BEFORE s2 waits on it) ----
    rmsnorm_h<<<NTOK, 256>>>(x, n1w, xnh);
    cudaEventRecord(ge_rms, 0);

    // ---- s1: weight transposes (in consumption order) + kv GEMM ----
    transpose_h2<<<gT64, tb8, 0, s1>>>(wk,  wkT,  MODEL_DIM, MODEL_DIM);
    transpose_h2<<<gT64, tb8, 0, s1>>>(wz,  wzT,  MODEL_DIM, MODEL_DIM);
    cudaEventRecord(ge_twz, s1);
    transpose_h2<<<dim3(INNER_DIM / 64, MODEL_DIM / 64), tb8, 0, s1>>>(md1, md1T, MODEL_DIM, INNER_DIM);
    cudaEventRecord(ge_tmd1, s1);
    transpose_h2<<<dim3(MODEL_DIM / 64, INNER_DIM / 64), tb8, 0, s1>>>(md2, md2T, INNER_DIM, MODEL_DIM);
    cudaEventRecord(ge_tmd2, s1);
    transpose_h2<<<gT64, tb8, 0, s1>>>(mcw, mcwT, MODEL_DIM, MODEL_DIM);
    cudaEventRecord(ge_tmcw, s1);
    transpose_h2<<<gT64, tb8, 0, s1>>>(wg,  wgT,  MODEL_DIM, MODEL_DIM);
    cudaEventRecord(ge_twg, s1);
    transpose_h2<<<gT64, tb8, 0, s1>>>(awq, awqT, MODEL_DIM, MODEL_DIM);
    cudaEventRecord(ge_tawq, s1);
    transpose_h2<<<gT64, tb8, 0, s1>>>(awk, awkvT,                               MODEL_DIM, MODEL_DIM);
    transpose_h2<<<gT64, tb8, 0, s1>>>(awv, awkvT + (size_t)MODEL_DIM*MODEL_DIM, MODEL_DIM, MODEL_DIM);
    cudaStreamWaitEvent(s1, ge_prep, 0);   // ge_prep recorded above
    hgemm<128,0,false,true><<<dim3(2*MODEL_DIM/128, 1), 256, SM128, s1>>>(memh, awkvT, kvbias, nullptr, kvh, MODEL_DIM, 2*MODEL_DIM, nullptr, nullptr);
    cudaEventRecord(ge_kv, s1);
    transpose_h2<<<gT64, tb8, 0, s1>>>(awo, awoT, MODEL_DIM, MODEL_DIM);
    cudaEventRecord(ge_tawo, s1);
    transpose_h2<<<dim3(FFN_DIM / 64,  MODEL_DIM / 64), tb8, 0, s1>>>(f1, f1T, MODEL_DIM, FFN_DIM);
    cudaEventRecord(ge_tf1, s1);
    transpose_h2<<<dim3(MODEL_DIM / 64, FFN_DIM / 64),  tb8, 0, s1>>>(f2, f2T, FFN_DIM, MODEL_DIM);
    cudaEventRecord(ge_tf2, s1);

    // ---- s2: wk GEMM -> mcw GEMM -> wg GEMM ----
    cudaStreamWaitEvent(s2, ge_rms, 0);
    cudaStreamWaitEvent(s2, ge_twz, 0);
    hgemm<256,0,false,true><<<gDD, 256, SM256, s2>>>(xnh, wkT, bk, nullptr, kh, MODEL_DIM, MODEL_DIM, nullptr, nullptr);
    cudaStreamWaitEvent(s2, ge_tmcw, 0);
    hgemm<256,0,true,false><<<gDD, 256, SM256, s2>>>(kh, mcwT, mcb, m2b, nullptr, MODEL_DIM, MODEL_DIM, nullptr, nullptr);
    cudaStreamWaitEvent(s2, ge_twg, 0);
    hgemm<256,0,true,false><<<gDD, 256, SM256, s2>>>(xh, wgT, bg, glin, nullptr, MODEL_DIM, MODEL_DIM, nullptr, nullptr);
    cudaEventRecord(ge_glin, s2);

    // ---- main: wz -> md1 -> md2 ----
    cudaStreamWaitEvent(0, ge_twz, 0);
    hgemm<256,0,true,true><<<gDD, 256, SM256>>>(xnh, wzT, bz, zb, zh, MODEL_DIM, MODEL_DIM, nullptr, nullptr);
    cudaStreamWaitEvent(0, ge_tmd1, 0);
    hgemm<128,1,false,true><<<dim3(INNER_DIM/128, NTOK/128), 256, SM128>>>(zh, md1T, mb1, nullptr, uh, MODEL_DIM, INNER_DIM, nullptr, nullptr);
    cudaStreamWaitEvent(0, ge_tmd2, 0);
    hgemm<256,0,true,false><<<gDD, 256, SM256>>>(uh, md2T, mb2, tb, nullptr, INNER_DIM, MODEL_DIM, nullptr, nullptr);

    // ---- main: gamma + h_t ----
    cudaStreamWaitEvent(0, ge_glin, 0);
    gamma_ht_kernel<<<(NTOK * MODEL_DIM) / (256 * 4), 256>>>(tb, m2b, zb, glin, x, gammab, htb, hth);
    cudaEventRecord(ge_gamma, 0);

    // ---- s2: cumprod chain (second output), overlaps attention path ----
    cudaStreamWaitEvent(s2, ge_gamma, 0);
    cumprod_local<<<dim3(NCHUNK, NBH), DH, 0, s2>>>(gammab, cum);
    cumprod_scan<<<(NBH * DH) / 256, 256, 0, s2>>>();
    cumprod_apply<<<dim3(NCHUNK, NBH), DH, 0, s2>>>(cum);
    cudaEventRecord(ge_cum, s2);

    // ---- main: attention path ----
    cudaStreamWaitEvent(0, ge_tawq, 0);
    hgemm<256,0,false,true><<<gDD, 256, SM256>>>(hth, awqT, abq, nullptr, qah, MODEL_DIM, MODEL_DIM, nullptr, nullptr);
    cudaStreamWaitEvent(0, ge_kv, 0);
    attn_mma<<<dim3(SEQ / 64, NUM_HEADS, BATCH), 128, ATTN_SMEM2>>>(qah, kvh, ctxh);
    cudaStreamWaitEvent(0, ge_tawo, 0);
    hgemm<256,2,true,false><<<gDD, 256, SM256>>>(ctxh, awoT, abo, xresb, nullptr, MODEL_DIM, MODEL_DIM, x, htb);
    // ---- main: FFN + residual -> first output ----
    rmsnorm_h<<<NTOK, 256>>>(xresb, n2w, xn2h);
    cudaStreamWaitEvent(0, ge_tf1, 0);
    hgemm<256,1,false,true><<<gDF, 256, SM256>>>(xn2h, f1T, fb1, nullptr, a1h, MODEL_DIM, FFN_DIM, nullptr, nullptr);
    cudaStreamWaitEvent(0, ge_tf2, 0);
    hgemm<256,3,true,false><<<gDD, 256, SM256>>>(a1h, f2T, fb2, out, nullptr, FFN_DIM, MODEL_DIM, xresb, nullptr);

    // join s2 (s1 joins via ge_tf2 above)
    cudaStreamWaitEvent(0, ge_cum, 0);
}

// round 14
// speedup vs baseline: 1.1673x; 1.0101x over previous
#include <cuda_runtime.h>
#include <cuda_fp16.h>
#include <math.h>
#include <stdint.h>

#define MODEL_DIM 2048
#define INNER_DIM 512
#define NUM_HEADS 16
#define FFN_DIM   8192
#define MEM_TOKENS 64
#define BATCH 2
#define SEQ   2048
#define NTOK  (BATCH*SEQ)            // 4096
#define HTOK  (NTOK/2)               // 2048 (one batch)
#define DH    (MODEL_DIM/NUM_HEADS)  // 128
#define EPSV  1e-6f

#define NCHUNK 32
#define CS     (SEQ/NCHUNK)          // 64
#define NBH    (BATCH*NUM_HEADS)     // 32

// ---------------- fp32 scratch -------------------------------------------------
__device__ float g_z    [NTOK*MODEL_DIM];
__device__ float g_glin [NTOK*MODEL_DIM];
__device__ float g_t    [NTOK*MODEL_DIM];
__device__ float g_m2   [NTOK*MODEL_DIM];
__device__ float g_gamma[NTOK*MODEL_DIM];
__device__ float g_ht   [NTOK*MODEL_DIM];
__device__ float g_xres [NTOK*MODEL_DIM];
__device__ float g_kvbias[2*MODEL_DIM];
__device__ float g_cp_tot [NBH*NCHUNK*DH];
__device__ float g_cp_pref[NBH*NCHUNK*DH];

// ---------------- fp16 activations ----------------------------------------------
__device__ __half g_xh  [NTOK*MODEL_DIM];
__device__ __half g_xnh [NTOK*MODEL_DIM];
__device__ __half g_zh  [NTOK*MODEL_DIM];
__device__ __half g_kh  [NTOK*MODEL_DIM];
__device__ __half g_uh  [NTOK*INNER_DIM];
__device__ __half g_hth [NTOK*MODEL_DIM];
__device__ __half g_memh[BATCH*MEM_TOKENS*MODEL_DIM];
__device__ __half g_qah [NTOK*MODEL_DIM];
__device__ __half g_kvh [BATCH*MEM_TOKENS*2*MODEL_DIM];   // [128, 4096] k|v
__device__ __half g_ctxh[NTOK*MODEL_DIM];
__device__ __half g_xn2h[NTOK*MODEL_DIM];
__device__ __half g_a1h [NTOK*FFN_DIM];

// ---------------- fp16 transposed weights [Dout, K] ----------------------------
#define DD (MODEL_DIM*MODEL_DIM)
__device__ __half g_wk [DD], g_wz [DD], g_wg [DD], g_mcw[DD];
__device__ __half g_awq[DD], g_awo[DD];
__device__ __half g_awkv[2*MODEL_DIM*MODEL_DIM];
__device__ __half g_md1[MODEL_DIM*INNER_DIM];
__device__ __half g_md2[INNER_DIM*MODEL_DIM];
__device__ __half g_f1 [MODEL_DIM*FFN_DIM];
__device__ __half g_f2 [FFN_DIM*MODEL_DIM];

// ---------------- helpers -------------------------------------------------------
__device__ __forceinline__ uint32_t smem_to_u32(const void* p) {
    uint32_t a;
    asm("{ .reg .u64 t; cvta.to.shared.u64 t, %1; cvt.u32.u64 %0, t; }" : "=r"(a) : "l"(p));
    return a;
}
#define SMEM_SWIZZLE_128B(o) ((o) ^ (((o) >> 3) & 0x70))

__device__ __forceinline__ float gelu_f(float v) {
    float t = 0.7978845608028654f * (v + 0.044715f * v * v * v);
    return 0.5f * v * (1.0f + tanhf(t));
}
__device__ __forceinline__ float sigmoid_f(float v) { return 1.0f / (1.0f + expf(-v)); }

__device__ __forceinline__ void mma16816h(float* c, const uint32_t* a, const uint32_t* b) {
    asm volatile("mma.sync.aligned.m16n8k16.row.col.f32.f16.f16.f32 "
        "{%0,%1,%2,%3}, {%4,%5,%6,%7}, {%8,%9}, {%0,%1,%2,%3};"
        : "+f"(c[0]), "+f"(c[1]), "+f"(c[2]), "+f"(c[3])
        : "r"(a[0]), "r"(a[1]), "r"(a[2]), "r"(a[3]), "r"(b[0]), "r"(b[1]));
}
#define LDMATRIX_X4(r0, r1, r2, r3, addr) \
    asm volatile("ldmatrix.sync.aligned.m8n8.x4.shared.b16 {%0,%1,%2,%3}, [%4];" \
        : "=r"(r0), "=r"(r1), "=r"(r2), "=r"(r3) : "r"(addr))
#define CP_ASYNC_16(dst, src) \
    asm volatile("cp.async.cg.shared.global [%0], [%1], 16;" :: "r"(dst), "l"(src))
#define CP_COMMIT()  asm volatile("cp.async.commit_group;" ::: "memory")
#define CP_WAIT(n)   asm volatile("cp.async.wait_group %0;" :: "n"(n) : "memory")

// ---------------- weight transpose: W[K,D] -> T[D,K] fp16, 64x64 tiles ----------
__global__ void transpose_h2(const float* __restrict__ W, __half* __restrict__ T,
                             int K, int D) {
    __shared__ float t[64][65];
    int d0 = blockIdx.x * 64, k0 = blockIdx.y * 64;
    int tx = threadIdx.x, ty = threadIdx.y;     // 32 x 8
    #pragma unroll
    for (int i = 0; i < 64; i += 8) {
        const float* row = W + (size_t)(k0 + ty + i) * D + d0;
        t[ty + i][tx]      = row[tx];
        t[ty + i][tx + 32] = row[tx + 32];
    }
    __syncthreads();
    #pragma unroll
    for (int i = 0; i < 64; i += 8) {
        int dl = ty + i;
        float v0 = t[tx * 2][dl];
        float v1 = t[tx * 2 + 1][dl];
        *(__half2*)(T + (size_t)(d0 + dl) * K + k0 + tx * 2) = __floats2half2_rn(v0, v1);
    }
}

// ---------------- fp32 -> fp16 --------------------------------------------------
__global__ void cvt_h(const float* __restrict__ src, __half* __restrict__ H) {
    size_t i = (size_t)(blockIdx.x * blockDim.x + threadIdx.x);
    float4 v = ((const float4*)src)[i];
    ((__half2*)H)[i * 2 + 0] = __floats2half2_rn(v.x, v.y);
    ((__half2*)H)[i * 2 + 1] = __floats2half2_rn(v.z, v.w);
}

__global__ void concat_bias(const float* __restrict__ a, const float* __restrict__ b) {
    int i = blockIdx.x * blockDim.x + threadIdx.x;
    g_kvbias[i] = (i < MODEL_DIM) ? a[i] : b[i - MODEL_DIM];
}

// ---------------- fp16 HMMA GEMM (exact R7 kernel) --------------------------------
template <int BN>
__device__ __forceinline__ void hg_issue(uint32_t base,
        const __half* Ab, const __half* Bb, int K, int k0, int tid) {
    #pragma unroll
    for (int i = 0; i < 4; i++) {           // A: 128 rows x 8 units
        int idx = tid + i * 256;
        int r = idx >> 3, u = idx & 7;
        uint32_t sw = SMEM_SWIZZLE_128B((uint32_t)(r * 128 + u * 16));
        CP_ASYNC_16(base + sw, Ab + (size_t)r * K + k0 + u * 8);
    }
    #pragma unroll
    for (int i = 0; i < (BN * 8) / 256; i++) {  // B: BN rows x 8 units
        int idx = tid + i * 256;
        int r = idx >> 3, u = idx & 7;
        uint32_t sw = SMEM_SWIZZLE_128B((uint32_t)(r * 128 + u * 16));
        CP_ASYNC_16(base + 16384 + sw, Bb + (size_t)r * K + k0 + u * 8);
    }
    CP_COMMIT();
}

template <int BN, int EPI, bool WF32, bool WPL>
__global__ void __launch_bounds__(256, 1)
hgemm(const __half* __restrict__ A, const __half* __restrict__ Bp,
      const float* __restrict__ bias,
      float* __restrict__ C, __half* __restrict__ PH,
      int K, int Dout, const float* __restrict__ add1, const float* __restrict__ add2) {
    constexpr int NJ = BN / 32;
    constexpr int STAGE = 16384 + BN * 128;
    extern __shared__ __align__(1024) char sm[];
    uint32_t sb = smem_to_u32(sm);
    int tid = threadIdx.x;
    int wid = tid >> 5, lane = tid & 31;
    int wm = wid & 1, wn = wid >> 1;       // 2 (M) x 4 (N) warps

    const __half* Ab = A  + (size_t)blockIdx.y * 128 * K;
    const __half* Bb = Bp + (size_t)blockIdx.x * BN * K;

    float acc[4][NJ][4];
    #pragma unroll
    for (int i = 0; i < 4; i++)
        #pragma unroll
        for (int j = 0; j < NJ; j++)
            #pragma unroll
            for (int q = 0; q < 4; q++) acc[i][j][q] = 0.0f;

    int NS = K >> 6;
    hg_issue<BN>(sb + 0u * STAGE, Ab, Bb, K, 0,   tid);
    hg_issue<BN>(sb + 1u * STAGE, Ab, Bb, K, 64,  tid);
    hg_issue<BN>(sb + 2u * STAGE, Ab, Bb, K, 128, tid);

    for (int s = 0; s < NS; s++) {
        CP_WAIT(2);
        __syncthreads();
        if (s + 3 < NS) hg_issue<BN>(sb + (uint32_t)((s + 3) & 3) * STAGE, Ab, Bb, K, (s + 3) * 64, tid);
        else CP_COMMIT();
        uint32_t aA = sb + (uint32_t)(s & 3) * STAGE;
        uint32_t bB = aA + 16384;
        #pragma unroll
        for (int ks = 0; ks < 4; ks++) {
            uint32_t af[4][4], bf[NJ][2];
            #pragma unroll
            for (int i = 0; i < 4; i++) {
                int row = wm * 64 + i * 16 + (lane & 15);
                int kb = ks * 32 + (lane >> 4) * 16;
                uint32_t sw = SMEM_SWIZZLE_128B((uint32_t)(row * 128 + kb));
                LDMATRIX_X4(af[i][0], af[i][1], af[i][2], af[i][3], aA + sw);
            }
            #pragma unroll
            for (int jp = 0; jp < NJ / 2; jp++) {
                int n = wn * (BN / 4) + jp * 16 + (lane >> 4) * 8 + (lane & 7);
                int kb = ks * 32 + ((lane >> 3) & 1) * 16;
                uint32_t sw = SMEM_SWIZZLE_128B((uint32_t)(n * 128 + kb));
                LDMATRIX_X4(bf[2*jp][0], bf[2*jp][1], bf[2*jp+1][0], bf[2*jp+1][1], bB + sw);
            }
            #pragma unroll
            for (int i = 0; i < 4; i++)
                #pragma unroll
                for (int j = 0; j < NJ; j++) mma16816h(acc[i][j], af[i], bf[j]);
        }
    }

    int gr = lane >> 2;
    int gc = (lane & 3) * 2;
    #pragma unroll
    for (int i = 0; i < 4; i++) {
        int row0 = blockIdx.y * 128 + wm * 64 + i * 16 + gr;
        #pragma unroll
        for (int j = 0; j < NJ; j++) {
            int col = blockIdx.x * BN + wn * (BN / 4) + j * 8 + gc;
            float2 bv = *(const float2*)(bias + col);
            #pragma unroll
            for (int half = 0; half < 2; half++) {
                int row = row0 + half * 8;
                size_t idx = (size_t)row * Dout + col;
                float2 o;
                o.x = acc[i][j][half * 2 + 0] + bv.x;
                o.y = acc[i][j][half * 2 + 1] + bv.y;
                if (EPI == 1) { o.x = gelu_f(o.x); o.y = gelu_f(o.y); }
                if (EPI == 2) {
                    float2 a1 = *(const float2*)(add1 + idx);
                    float2 a2 = *(const float2*)(add2 + idx);
                    o.x += a1.x + a2.x; o.y += a1.y + a2.y;
                }
                if (EPI == 3) {
                    float2 a1 = *(const float2*)(add1 + idx);
                    o.x += a1.x; o.y += a1.y;
                }
                if (WF32) *(float2*)(C + idx) = o;
                if (WPL)  *(__half2*)(PH + idx) = __floats2half2_rn(o.x, o.y);
            }
        }
    }
}

// ---------------- RMSNorm -> fp16 -----------------------------------------------
__global__ void rmsnorm_h(const float* __restrict__ x,
                          const float* __restrict__ w,
                          __half* __restrict__ H) {
    int row = blockIdx.x;
    int t = threadIdx.x;  // 256
    const float4* xr = (const float4*)(x + (size_t)row * MODEL_DIM);
    float4 v0 = xr[t];
    float4 v1 = xr[t + 256];
    float s = v0.x*v0.x + v0.y*v0.y + v0.z*v0.z + v0.w*v0.w
            + v1.x*v1.x + v1.y*v1.y + v1.z*v1.z + v1.w*v1.w;
    #pragma unroll
    for (int o = 16; o > 0; o >>= 1) s += __shfl_xor_sync(0xffffffffu, s, o);
    __shared__ float red[8];
    if ((t & 31) == 0) red[t >> 5] = s;
    __syncthreads();
    float tot = red[0]+red[1]+red[2]+red[3]+red[4]+red[5]+red[6]+red[7];
    float inv = 1.0f / (sqrtf(tot / (float)MODEL_DIM) + EPSV);
    const float4* wr = (const float4*)w;
    float4 w0 = wr[t], w1 = wr[t + 256];
    __half2* Hr = (__half2*)(H + (size_t)row * MODEL_DIM);
    Hr[t*2]       = __floats2half2_rn(w0.x*v0.x*inv, w0.y*v0.y*inv);
    Hr[t*2+1]     = __floats2half2_rn(w0.z*v0.z*inv, w0.w*v0.w*inv);
    Hr[512+t*2]   = __floats2half2_rn(w1.x*v1.x*inv, w1.y*v1.y*inv);
    Hr[512+t*2+1] = __floats2half2_rn(w1.z*v1.z*inv, w1.w*v1.w*inv);
}

// ---------------- gamma / h_t elementwise (+ ht fp16) ----------------------------
__global__ void gamma_ht_kernel(const float* __restrict__ t,
                                const float* __restrict__ m2,
                                const float* __restrict__ z,
                                const float* __restrict__ glin,
                                const float* __restrict__ x,
                                float* __restrict__ gamma,
                                float* __restrict__ ht,
                                __half* __restrict__ hth) {
    size_t i = (size_t)(blockIdx.x * blockDim.x + threadIdx.x);
    float4 tv = ((const float4*)t)[i];
    float4 mv = ((const float4*)m2)[i];
    float4 zv = ((const float4*)z)[i];
    float4 gv = ((const float4*)glin)[i];
    float4 xv = ((const float4*)x)[i];
    float4 gm, h;
    gm.x = sigmoid_f(tv.x + mv.x); gm.y = sigmoid_f(tv.y + mv.y);
    gm.z = sigmoid_f(tv.z + mv.z); gm.w = sigmoid_f(tv.w + mv.w);
    h.x = zv.x * sigmoid_f(gv.x) + gm.x * xv.x;
    h.y = zv.y * sigmoid_f(gv.y) + gm.y * xv.y;
    h.z = zv.z * sigmoid_f(gv.z) + gm.z * xv.z;
    h.w = zv.w * sigmoid_f(gv.w) + gm.w * xv.w;
    ((float4*)gamma)[i] = gm;
    ((float4*)ht)[i] = h;
    ((__half2*)hth)[i*2]   = __floats2half2_rn(h.x, h.y);
    ((__half2*)hth)[i*2+1] = __floats2half2_rn(h.z, h.w);
}

// ---------------- cumprod ---------------------------------------------------------
__global__ void cumprod_local(const float* __restrict__ gamma, float* __restrict__ outp) {
    int c = blockIdx.x, bh = blockIdx.y, d2 = threadIdx.x;
    size_t base = (size_t)bh * SEQ * DH + (size_t)c * CS * DH + d2;
    float p = 1.0f;
    for (int i = 0; i < CS; i++) {
        p *= gamma[base + (size_t)i * DH];
        outp[base + (size_t)i * DH] = p;
    }
    g_cp_tot[(bh * NCHUNK + c) * DH + d2] = p;
}
__global__ void cumprod_scan() {
    int lane = blockIdx.x * blockDim.x + threadIdx.x;
    int bh = lane / DH, d2 = lane % DH;
    float r = 1.0f;
    for (int c = 0; c < NCHUNK; c++) {
        int idx = (bh * NCHUNK + c) * DH + d2;
        g_cp_pref[idx] = r;
        r *= g_cp_tot[idx];
    }
}
__global__ void cumprod_apply(float* __restrict__ outp) {
    int c = blockIdx.x, bh = blockIdx.y, d2 = threadIdx.x;
    if (c == 0) return;
    float pref = g_cp_pref[(bh * NCHUNK + c) * DH + d2];
    size_t base = (size_t)bh * SEQ * DH + (size_t)c * CS * DH + d2;
    for (int i = 0; i < CS; i++) outp[base + (size_t)i * DH] *= pref;
}

// ---------------- tensor-core attention over 64 memory tokens ---------------------
// One batch per launch (pointers pre-offset); grid (SEQ/64, NUM_HEADS, 1).
#define AQ_OFF 0u
#define AK_OFF 16384u
#define AV_OFF 32768u
#define ASC_OFF 49152u
#define APS_OFF (49152u + 64u*68u*4u)
#define ATTN_SMEM2 (49152 + 64*68*4 + 8192)
__global__ void __launch_bounds__(128, 1)
attn_mma(const __half* __restrict__ qah,
         const __half* __restrict__ kvh,
         __half* __restrict__ ctxh) {
    extern __shared__ __align__(1024) char smc[];
    uint32_t sb = smem_to_u32(smc);
    float* sc = (float*)(smc + ASC_OFF);
    int stile = blockIdx.x, h = blockIdx.y, b = blockIdx.z;
    int s0 = stile * 64;
    int tid = threadIdx.x, lane = tid & 31, wid = tid >> 5;
    int wm = wid & 1, wn = wid >> 1;

    #pragma unroll
    for (int i = 0; i < 8; i++) {
        int idx = tid + i * 128;
        int r = idx >> 4, u = idx & 15;
        int c = u >> 3, uc = u & 7;
        uint32_t sw = SMEM_SWIZZLE_128B((uint32_t)(r * 128 + uc * 16));
        CP_ASYNC_16(sb + AQ_OFF + c * 8192 + sw,
                    qah + (size_t)(b * SEQ + s0 + r) * MODEL_DIM + h * 128 + u * 8);
        CP_ASYNC_16(sb + AK_OFF + c * 8192 + sw,
                    kvh + (size_t)(b * MEM_TOKENS + r) * (2 * MODEL_DIM) + h * 128 + u * 8);
    }
    CP_COMMIT();
    for (int idx = tid; idx < 8192; idx += 128) {
        int m = idx >> 7, d = idx & 127;
        __half v = kvh[(size_t)(b * MEM_TOKENS + m) * (2 * MODEL_DIM) + MODEL_DIM + h * 128 + d];
        *(__half*)(smc + AV_OFF + SMEM_SWIZZLE_128B((uint32_t)(d * 128 + m * 2))) = v;
    }
    CP_WAIT(0);
    __syncthreads();

    float acc[2][4][4];
    #pragma unroll
    for (int i = 0; i < 2; i++)
        #pragma unroll
        for (int j = 0; j < 4; j++)
            #pragma unroll
            for (int q = 0; q < 4; q++) acc[i][j][q] = 0.0f;
    #pragma unroll
    for (int c = 0; c < 2; c++) {
        uint32_t qA = sb + AQ_OFF + c * 8192;
        uint32_t kB = sb + AK_OFF + c * 8192;
        #pragma unroll
        for (int ks = 0; ks < 4; ks++) {
            uint32_t af[2][4], bf[4][2];
            #pragma unroll
            for (int i = 0; i < 2; i++) {
                int row = wm * 32 + i * 16 + (lane & 15);
                int kb = ks * 32 + (lane >> 4) * 16;
                LDMATRIX_X4(af[i][0], af[i][1], af[i][2], af[i][3],
                            qA + SMEM_SWIZZLE_128B((uint32_t)(row * 128 + kb)));
            }
            #pragma unroll
            for (int jp = 0; jp < 2; jp++) {
                int n = wn * 32 + jp * 16 + (lane >> 4) * 8 + (lane & 7);
                int kb = ks * 32 + ((lane >> 3) & 1) * 16;
                LDMATRIX_X4(bf[2*jp][0], bf[2*jp][1], bf[2*jp+1][0], bf[2*jp+1][1],
                            kB + SMEM_SWIZZLE_128B((uint32_t)(n * 128 + kb)));
            }
            #pragma unroll
            for (int i = 0; i < 2; i++)
                #pragma unroll
                for (int j = 0; j < 4; j++) mma16816h(acc[i][j], af[i], bf[j]);
        }
    }
    const float scale = 0.08838834764831845f;
    int gr = lane >> 2, gc = (lane & 3) * 2;
    #pragma unroll
    for (int i = 0; i < 2; i++)
        #pragma unroll
        for (int j = 0; j < 4; j++)
            #pragma unroll
            for (int half = 0; half < 2; half++) {
                int row = wm * 32 + i * 16 + gr + half * 8;
                int col = wn * 32 + j * 8 + gc;
                sc[row * 68 + col]     = acc[i][j][half * 2 + 0] * scale;
                sc[row * 68 + col + 1] = acc[i][j][half * 2 + 1] * scale;
            }
    __syncthreads();

    if (tid < 64) {
        float* row = &sc[tid * 68];
        float mx = -1e30f;
        for (int m = 0; m < 64; m++) mx = fmaxf(mx, row[m]);
        float s = 0.0f;
        for (int m = 0; m < 64; m++) { float e = expf(row[m] - mx); row[m] = e; s += e; }
        float inv = 1.0f / s;
        for (int m = 0; m < 64; m++)
            *(__half*)(smc + APS_OFF + SMEM_SWIZZLE_128B((uint32_t)(tid * 128 + m * 2))) =
                __float2half_rn(row[m] * inv);
    }
    __syncthreads();

    float acc2[2][8][4];
    #pragma unroll
    for (int i = 0; i < 2; i++)
        #pragma unroll
        for (int j = 0; j < 8; j++)
            #pragma unroll
            for (int q = 0; q < 4; q++) acc2[i][j][q] = 0.0f;
    #pragma unroll
    for (int ks = 0; ks < 4; ks++) {
        uint32_t af[2][4], bf[8][2];
        #pragma unroll
        for (int i = 0; i < 2; i++) {
            int row = wm * 32 + i * 16 + (lane & 15);
            int kb = ks * 32 + (lane >> 4) * 16;
            LDMATRIX_X4(af[i][0], af[i][1], af[i][2], af[i][3],
                        sb + APS_OFF + SMEM_SWIZZLE_128B((uint32_t)(row * 128 + kb)));
        }
        #pragma unroll
        for (int jp = 0; jp < 4; jp++) {
            int n = wn * 64 + jp * 16 + (lane >> 4) * 8 + (lane & 7);
            int kb = ks * 32 + ((lane >> 3) & 1) * 16;
            LDMATRIX_X4(bf[2*jp][0], bf[2*jp][1], bf[2*jp+1][0], bf[2*jp+1][1],
                        sb + AV_OFF + SMEM_SWIZZLE_128B((uint32_t)(n * 128 + kb)));
        }
        #pragma unroll
        for (int i = 0; i < 2; i++)
            #pragma unroll
            for (int j = 0; j < 8; j++) mma16816h(acc2[i][j], af[i], bf[j]);
    }
    #pragma unroll
    for (int i = 0; i < 2; i++)
        #pragma unroll
        for (int j = 0; j < 8; j++)
            #pragma unroll
            for (int half = 0; half < 2; half++) {
                int row = wm * 32 + i * 16 + gr + half * 8;
                int d = wn * 64 + j * 8 + gc;
                size_t idx = (size_t)(b * SEQ + s0 + row) * MODEL_DIM + h * 128 + d;
                *(__half2*)(ctxh + idx) =
                    __floats2half2_rn(acc2[i][j][half * 2 + 0], acc2[i][j][half * 2 + 1]);
            }
}

// ---------------- one-time stream/event resources --------------------------------
static cudaStream_t g_s1 = nullptr, g_s2 = nullptr;
static cudaEvent_t  ge0, ge_rms, ge_twz, ge_tmd1, ge_tmd2, ge_tmcw, ge_twg, ge_tawq,
                    ge_tawo, ge_tf1, ge_tf2, ge_prep, ge_glin, ge_md2, ge_g0, ge_g1,
                    ge_kv, ge_cum, ge_s2done;

// ---------------- host launcher -----------------------------------------------------
extern "C" void kernel_launch(void* const* d_in, const int* in_sizes, int n_in,
                              void* d_out, int out_size) {
    bool sig = (in_sizes[3] == MODEL_DIM);
    const float *x, *memory, *wk, *bk, *wz, *bz, *wg, *bg, *n1w, *n2w;
    const float *md1, *mb1, *md2, *mb2, *mcw, *mcb;
    const float *awq, *abq, *awk, *abk, *awv, *abv, *awo, *abo;
    const float *f1, *fb1, *f2, *fb2;
    #define IN(i) ((const float*)d_in[(i)])
    if (sig) {
        x = IN(0);  memory = IN(1);
        wk = IN(4);  bk = IN(5);  wz = IN(8);  bz = IN(9);  wg = IN(10); bg = IN(11);
        n1w = IN(12); n2w = IN(13);
        md1 = IN(14); mb1 = IN(15); md2 = IN(16); mb2 = IN(17); mcw = IN(18); mcb = IN(19);
        awq = IN(20); abq = IN(21); awk = IN(22); abk = IN(23); awv = IN(24); abv = IN(25);
        awo = IN(26); abo = IN(27);
        f1 = IN(28); fb1 = IN(29); f2 = IN(30); fb2 = IN(31);
    } else {
        x = IN(0);  memory = IN(1);
        wk = IN(3);  wz = IN(5);  wg = IN(6);
        md1 = IN(7); md2 = IN(8); mcw = IN(9);
        awq = IN(10); awk = IN(11); awv = IN(12); awo = IN(13);
        f1 = IN(14); f2 = IN(15);
        bk = IN(17); bz = IN(19); bg = IN(20);
        mb1 = IN(21); mb2 = IN(22); mcb = IN(23);
        abq = IN(24); abk = IN(25); abv = IN(26); abo = IN(27);
        fb1 = IN(28); fb2 = IN(29);
        n1w = IN(30); n2w = IN(31);
    }
    #undef IN

    float *zb, *glin, *tb, *m2b, *gammab, *htb, *xresb, *kvbias;
    cudaGetSymbolAddress((void**)&zb,    g_z);
    cudaGetSymbolAddress((void**)&glin,  g_glin);
    cudaGetSymbolAddress((void**)&tb,    g_t);
    cudaGetSymbolAddress((void**)&m2b,   g_m2);
    cudaGetSymbolAddress((void**)&gammab,g_gamma);
    cudaGetSymbolAddress((void**)&htb,   g_ht);
    cudaGetSymbolAddress((void**)&xresb, g_xres);
    cudaGetSymbolAddress((void**)&kvbias,g_kvbias);

    __half *xh,*xnh,*zh,*kh,*uh,*hth,*memh,*qah,*kvh,*ctxh,*xn2h,*a1h;
    cudaGetSymbolAddress((void**)&xh,  g_xh);
    cudaGetSymbolAddress((void**)&xnh, g_xnh);
    cudaGetSymbolAddress((void**)&zh,  g_zh);
    cudaGetSymbolAddress((void**)&kh,  g_kh);
    cudaGetSymbolAddress((void**)&uh,  g_uh);
    cudaGetSymbolAddress((void**)&hth, g_hth);
    cudaGetSymbolAddress((void**)&memh,g_memh);
    cudaGetSymbolAddress((void**)&qah, g_qah);
    cudaGetSymbolAddress((void**)&kvh, g_kvh);
    cudaGetSymbolAddress((void**)&ctxh,g_ctxh);
    cudaGetSymbolAddress((void**)&xn2h,g_xn2h);
    cudaGetSymbolAddress((void**)&a1h, g_a1h);

    __half *wkT,*wzT,*wgT,*mcwT,*awqT,*awoT,*awkvT,*md1T,*md2T,*f1T,*f2T;
    cudaGetSymbolAddress((void**)&wkT,  g_wk);
    cudaGetSymbolAddress((void**)&wzT,  g_wz);
    cudaGetSymbolAddress((void**)&wgT,  g_wg);
    cudaGetSymbolAddress((void**)&mcwT, g_mcw);
    cudaGetSymbolAddress((void**)&awqT, g_awq);
    cudaGetSymbolAddress((void**)&awoT, g_awo);
    cudaGetSymbolAddress((void**)&awkvT,g_awkv);
    cudaGetSymbolAddress((void**)&md1T, g_md1);
    cudaGetSymbolAddress((void**)&md2T, g_md2);
    cudaGetSymbolAddress((void**)&f1T,  g_f1);
    cudaGetSymbolAddress((void**)&f2T,  g_f2);

    float* out = (float*)d_out;
    float* cum = out + (size_t)NTOK * MODEL_DIM;

    const int SM256 = 4 * (16384 + 256 * 128);   // 196608
    const int SM128 = 4 * (16384 + 128 * 128);   // 131072
    cudaFuncSetAttribute((const void*)hgemm<256,0,false,true>,  cudaFuncAttributeMaxDynamicSharedMemorySize, SM256);
    cudaFuncSetAttribute((const void*)hgemm<256,0,true,true>,   cudaFuncAttributeMaxDynamicSharedMemorySize, SM256);
    cudaFuncSetAttribute((const void*)hgemm<256,0,true,false>,  cudaFuncAttributeMaxDynamicSharedMemorySize, SM256);
    cudaFuncSetAttribute((const void*)hgemm<256,1,false,true>,  cudaFuncAttributeMaxDynamicSharedMemorySize, SM256);
    cudaFuncSetAttribute((const void*)hgemm<256,2,true,false>,  cudaFuncAttributeMaxDynamicSharedMemorySize, SM256);
    cudaFuncSetAttribute((const void*)hgemm<256,3,true,false>,  cudaFuncAttributeMaxDynamicSharedMemorySize, SM256);
    cudaFuncSetAttribute((const void*)hgemm<128,1,false,true>,  cudaFuncAttributeMaxDynamicSharedMemorySize, SM128);
    cudaFuncSetAttribute((const void*)hgemm<128,0,false,true>,  cudaFuncAttributeMaxDynamicSharedMemorySize, SM128);
    cudaFuncSetAttribute(attn_mma, cudaFuncAttributeMaxDynamicSharedMemorySize, ATTN_SMEM2);

    dim3 tb8(32, 8);
    dim3 gT64(MODEL_DIM / 64, MODEL_DIM / 64);
    dim3 gDD(MODEL_DIM / 256, NTOK / 128);    // (8, 32) full
    dim3 gDDh(MODEL_DIM / 256, HTOK / 128);   // (8, 16) half
    dim3 gDFh(FFN_DIM / 256,  HTOK / 128);    // (32, 16) half

    // pointer offsets for row-halves (half = one batch = 2048 tokens)
    const size_t offD = (size_t)HTOK * MODEL_DIM;
    const size_t offF = (size_t)HTOK * FFN_DIM;
    const size_t offKV = (size_t)MEM_TOKENS * 2 * MODEL_DIM;

    if (g_s1 == nullptr) {
        cudaStreamCreateWithFlags(&g_s1, cudaStreamNonBlocking);
        cudaStreamCreateWithFlags(&g_s2, cudaStreamNonBlocking);
        cudaEvent_t* evs[19] = {&ge0,&ge_rms,&ge_twz,&ge_tmd1,&ge_tmd2,&ge_tmcw,&ge_twg,&ge_tawq,
                                &ge_tawo,&ge_tf1,&ge_tf2,&ge_prep,&ge_glin,&ge_md2,&ge_g0,&ge_g1,
                                &ge_kv,&ge_cum,&ge_s2done};
        for (int i = 0; i < 19; i++) cudaEventCreateWithFlags(evs[i], cudaEventDisableTiming);
    }
    cudaStream_t s1 = g_s1, s2 = g_s2;

    // ---------- fork (every event recorded before any wait on it, in host order)
    cudaEventRecord(ge0, 0);
    cudaStreamWaitEvent(s1, ge0, 0);
    cudaStreamWaitEvent(s2, ge0, 0);

    // ---- s2: prep ----
    cvt_h<<<(NTOK * MODEL_DIM / 4) / 256, 256, 0, s2>>>(x, xh);
    concat_bias<<<(2 * MODEL_DIM) / 256, 256, 0, s2>>>(abk, abv);
    cvt_h<<<(BATCH * MEM_TOKENS * MODEL_DIM / 4) / 64, 64, 0, s2>>>(memory, memh);
    cudaEventRecord(ge_prep, s2);

    // ---- main: rmsnorm ----
    rmsnorm_h<<<NTOK, 256>>>(x, n1w, xnh);
    cudaEventRecord(ge_rms, 0);

    // ---- s1: weight transposes + kv GEMM ----
    transpose_h2<<<gT64, tb8, 0, s1>>>(wk,  wkT,  MODEL_DIM, MODEL_DIM);
    transpose_h2<<<gT64, tb8, 0, s1>>>(wz,  wzT,  MODEL_DIM, MODEL_DIM);
    cudaEventRecord(ge_twz, s1);
    transpose_h2<<<dim3(INNER_DIM / 64, MODEL_DIM / 64), tb8, 0, s1>>>(md1, md1T, MODEL_DIM, INNER_DIM);
    cudaEventRecord(ge_tmd1, s1);
    transpose_h2<<<dim3(MODEL_DIM / 64, INNER_DIM / 64), tb8, 0, s1>>>(md2, md2T, INNER_DIM, MODEL_DIM);
    cudaEventRecord(ge_tmd2, s1);
    transpose_h2<<<gT64, tb8, 0, s1>>>(mcw, mcwT, MODEL_DIM, MODEL_DIM);
    cudaEventRecord(ge_tmcw, s1);
    transpose_h2<<<gT64, tb8, 0, s1>>>(wg,  wgT,  MODEL_DIM, MODEL_DIM);
    cudaEventRecord(ge_twg, s1);
    transpose_h2<<<gT64, tb8, 0, s1>>>(awq, awqT, MODEL_DIM, MODEL_DIM);
    cudaEventRecord(ge_tawq, s1);
    transpose_h2<<<gT64, tb8, 0, s1>>>(awk, awkvT,                               MODEL_DIM, MODEL_DIM);
    transpose_h2<<<gT64, tb8, 0, s1>>>(awv, awkvT + (size_t)MODEL_DIM*MODEL_DIM, MODEL_DIM, MODEL_DIM);
    cudaStreamWaitEvent(s1, ge_prep, 0);
    hgemm<128,0,false,true><<<dim3(2*MODEL_DIM/128, 1), 256, SM128, s1>>>(memh, awkvT, kvbias, nullptr, kvh, MODEL_DIM, 2*MODEL_DIM, nullptr, nullptr);
    cudaEventRecord(ge_kv, s1);
    transpose_h2<<<gT64, tb8, 0, s1>>>(awo, awoT, MODEL_DIM, MODEL_DIM);
    cudaEventRecord(ge_tawo, s1);
    transpose_h2<<<dim3(FFN_DIM / 64,  MODEL_DIM / 64), tb8, 0, s1>>>(f1, f1T, MODEL_DIM, FFN_DIM);
    cudaEventRecord(ge_tf1, s1);
    transpose_h2<<<dim3(MODEL_DIM / 64, FFN_DIM / 64),  tb8, 0, s1>>>(f2, f2T, FFN_DIM, MODEL_DIM);
    cudaEventRecord(ge_tf2, s1);

    // ---- s2: wk GEMM -> mcw GEMM -> wg GEMM ----
    cudaStreamWaitEvent(s2, ge_rms, 0);
    cudaStreamWaitEvent(s2, ge_twz, 0);
    hgemm<256,0,false,true><<<gDD, 256, SM256, s2>>>(xnh, wkT, bk, nullptr, kh, MODEL_DIM, MODEL_DIM, nullptr, nullptr);
    cudaStreamWaitEvent(s2, ge_tmcw, 0);
    hgemm<256,0,true,false><<<gDD, 256, SM256, s2>>>(kh, mcwT, mcb, m2b, nullptr, MODEL_DIM, MODEL_DIM, nullptr, nullptr);
    cudaStreamWaitEvent(s2, ge_twg, 0);
    hgemm<256,0,true,false><<<gDD, 256, SM256, s2>>>(xh, wgT, bg, glin, nullptr, MODEL_DIM, MODEL_DIM, nullptr, nullptr);
    cudaEventRecord(ge_glin, s2);

    // ---- main: wz -> md1 -> md2 ----
    cudaStreamWaitEvent(0, ge_twz, 0);
    hgemm<256,0,true,true><<<gDD, 256, SM256>>>(xnh, wzT, bz, zb, zh, MODEL_DIM, MODEL_DIM, nullptr, nullptr);
    cudaStreamWaitEvent(0, ge_tmd1, 0);
    hgemm<128,1,false,true><<<dim3(INNER_DIM/128, NTOK/128), 256, SM128>>>(zh, md1T, mb1, nullptr, uh, MODEL_DIM, INNER_DIM, nullptr, nullptr);
    cudaStreamWaitEvent(0, ge_tmd2, 0);
    hgemm<256,0,true,false><<<gDD, 256, SM256>>>(uh, md2T, mb2, tb, nullptr, INNER_DIM, MODEL_DIM, nullptr, nullptr);
    cudaEventRecord(ge_md2, 0);

    // ---- main: gamma + h_t (half 0) ----
    cudaStreamWaitEvent(0, ge_glin, 0);
    gamma_ht_kernel<<<(HTOK * MODEL_DIM) / (256 * 4), 256>>>(tb, m2b, zb, glin, x, gammab, htb, hth);
    cudaEventRecord(ge_g0, 0);

    // ---- s2: gamma + h_t (half 1) ----
    cudaStreamWaitEvent(s2, ge_md2, 0);
    gamma_ht_kernel<<<(HTOK * MODEL_DIM) / (256 * 4), 256, 0, s2>>>(
        tb + offD, m2b + offD, zb + offD, glin + offD, x + offD,
        gammab + offD, htb + offD, hth + offD);
    cudaEventRecord(ge_g1, s2);

    // ---- s1: cumprod chain (second output; needs full gamma) ----
    cudaStreamWaitEvent(s1, ge_g0, 0);
    cudaStreamWaitEvent(s1, ge_g1, 0);
    cumprod_local<<<dim3(NCHUNK, NBH), DH, 0, s1>>>(gammab, cum);
    cumprod_scan<<<(NBH * DH) / 256, 256, 0, s1>>>();
    cumprod_apply<<<dim3(NCHUNK, NBH), DH, 0, s1>>>(cum);
    cudaEventRecord(ge_cum, s1);

    // ---- main: half-0 tail chain ----
    cudaStreamWaitEvent(0, ge_tawq, 0);
    hgemm<256,0,false,true><<<gDDh, 256, SM256>>>(hth, awqT, abq, nullptr, qah, MODEL_DIM, MODEL_DIM, nullptr, nullptr);
    cudaStreamWaitEvent(0, ge_kv, 0);
    attn_mma<<<dim3(SEQ / 64, NUM_HEADS, 1), 128, ATTN_SMEM2>>>(qah, kvh, ctxh);
    cudaStreamWaitEvent(0, ge_tawo, 0);
    hgemm<256,2,true,false><<<gDDh, 256, SM256>>>(ctxh, awoT, abo, xresb, nullptr, MODEL_DIM, MODEL_DIM, x, htb);
    rmsnorm_h<<<HTOK, 256>>>(xresb, n2w, xn2h);
    cudaStreamWaitEvent(0, ge_tf1, 0);
    hgemm<256,1,false,true><<<gDFh, 256, SM256>>>(xn2h, f1T, fb1, nullptr, a1h, MODEL_DIM, FFN_DIM, nullptr, nullptr);
    cudaStreamWaitEvent(0, ge_tf2, 0);
    hgemm<256,3,true,false><<<gDDh, 256, SM256>>>(a1h, f2T, fb2, out, nullptr, FFN_DIM, MODEL_DIM, xresb, nullptr);

    // ---- s2: half-1 tail chain ----
    cudaStreamWaitEvent(s2, ge_tawq, 0);
    hgemm<256,0,false,true><<<gDDh, 256, SM256, s2>>>(hth + offD, awqT, abq, nullptr, qah + offD, MODEL_DIM, MODEL_DIM, nullptr, nullptr);
    cudaStreamWaitEvent(s2, ge_kv, 0);
    attn_mma<<<dim3(SEQ / 64, NUM_HEADS, 1), 128, ATTN_SMEM2, s2>>>(qah + offD, kvh + offKV, ctxh + offD);
    cudaStreamWaitEvent(s2, ge_tawo, 0);
    hgemm<256,2,true,false><<<gDDh, 256, SM256, s2>>>(ctxh + offD, awoT, abo, xresb + offD, nullptr, MODEL_DIM, MODEL_DIM, x + offD, htb + offD);
    rmsnorm_h<<<HTOK, 256, 0, s2>>>(xresb + offD, n2w, xn2h + offD);
    cudaStreamWaitEvent(s2, ge_tf1, 0);
    hgemm<256,1,false,true><<<gDFh, 256, SM256, s2>>>(xn2h + offD, f1T, fb1, nullptr, a1h + offF, MODEL_DIM, FFN_DIM, nullptr, nullptr);
    cudaStreamWaitEvent(s2, ge_tf2, 0);
    hgemm<256,3,true,false><<<gDDh, 256, SM256, s2>>>(a1h + offF, f2T, fb2, out + offD, nullptr, FFN_DIM, MODEL_DIM, xresb + offD, nullptr);
    cudaEventRecord(ge_s2done, s2);

    // ---- join ----
    cudaStreamWaitEvent(0, ge_s2done, 0);
    cudaStreamWaitEvent(0, ge_cum, 0);
}

// round 15
// speedup vs baseline: 1.1787x; 1.0098x over previous
#include <cuda_runtime.h>
#include <cuda_fp16.h>
#include <math.h>
#include <stdint.h>

#define MODEL_DIM 2048
#define INNER_DIM 512
#define NUM_HEADS 16
#define FFN_DIM   8192
#define MEM_TOKENS 64
#define BATCH 2
#define SEQ   2048
#define NTOK  (BATCH*SEQ)            // 4096
#define HTOK  (NTOK/2)               // 2048 (one batch)
#define DH    (MODEL_DIM/NUM_HEADS)  // 128
#define EPSV  1e-6f

#define NCHUNK 32
#define CS     (SEQ/NCHUNK)          // 64
#define NBH    (BATCH*NUM_HEADS)     // 32

// ---------------- fp32 scratch -------------------------------------------------
__device__ float g_z    [NTOK*MODEL_DIM];
__device__ float g_glin [NTOK*MODEL_DIM];
__device__ float g_t    [NTOK*MODEL_DIM];
__device__ float g_m2   [NTOK*MODEL_DIM];
__device__ float g_gamma[NTOK*MODEL_DIM];
__device__ float g_ht   [NTOK*MODEL_DIM];
__device__ float g_xres [NTOK*MODEL_DIM];
__device__ float g_kvbias[2*MODEL_DIM];
__device__ float g_cp_tot [NBH*NCHUNK*DH];
__device__ float g_cp_pref[NBH*NCHUNK*DH];

// ---------------- fp16 activations ----------------------------------------------
__device__ __half g_xh  [NTOK*MODEL_DIM];
__device__ __half g_xnh [NTOK*MODEL_DIM];
__device__ __half g_zh  [NTOK*MODEL_DIM];
__device__ __half g_kh  [NTOK*MODEL_DIM];
__device__ __half g_uh  [NTOK*INNER_DIM];
__device__ __half g_hth [NTOK*MODEL_DIM];
__device__ __half g_memh[BATCH*MEM_TOKENS*MODEL_DIM];
__device__ __half g_qah [NTOK*MODEL_DIM];
__device__ __half g_kvh [BATCH*MEM_TOKENS*2*MODEL_DIM];   // [128, 4096] k|v
__device__ __half g_ctxh[NTOK*MODEL_DIM];
__device__ __half g_xn2h[NTOK*MODEL_DIM];
__device__ __half g_a1h [NTOK*FFN_DIM];

// ---------------- fp16 transposed weights [Dout, K] ----------------------------
#define DD (MODEL_DIM*MODEL_DIM)
__device__ __half g_wk [DD], g_wz [DD], g_wg [DD], g_mcw[DD];
__device__ __half g_awq[DD], g_awo[DD];
__device__ __half g_awkv[2*MODEL_DIM*MODEL_DIM];
__device__ __half g_md1[MODEL_DIM*INNER_DIM];
__device__ __half g_md2[INNER_DIM*MODEL_DIM];
__device__ __half g_f1 [MODEL_DIM*FFN_DIM];
__device__ __half g_f2 [FFN_DIM*MODEL_DIM];

// ---------------- helpers -------------------------------------------------------
__device__ __forceinline__ uint32_t smem_to_u32(const void* p) {
    uint32_t a;
    asm("{ .reg .u64 t; cvta.to.shared.u64 t, %1; cvt.u32.u64 %0, t; }" : "=r"(a) : "l"(p));
    return a;
}
#define SMEM_SWIZZLE_128B(o) ((o) ^ (((o) >> 3) & 0x70))

__device__ __forceinline__ float gelu_f(float v) {
    float t = 0.7978845608028654f * (v + 0.044715f * v * v * v);
    return 0.5f * v * (1.0f + tanhf(t));
}
__device__ __forceinline__ float sigmoid_f(float v) { return 1.0f / (1.0f + expf(-v)); }

__device__ __forceinline__ void mma16816h(float* c, const uint32_t* a, const uint32_t* b) {
    asm volatile("mma.sync.aligned.m16n8k16.row.col.f32.f16.f16.f32 "
        "{%0,%1,%2,%3}, {%4,%5,%6,%7}, {%8,%9}, {%0,%1,%2,%3};"
        : "+f"(c[0]), "+f"(c[1]), "+f"(c[2]), "+f"(c[3])
        : "r"(a[0]), "r"(a[1]), "r"(a[2]), "r"(a[3]), "r"(b[0]), "r"(b[1]));
}
#define LDMATRIX_X4(r0, r1, r2, r3, addr) \
    asm volatile("ldmatrix.sync.aligned.m8n8.x4.shared.b16 {%0,%1,%2,%3}, [%4];" \
        : "=r"(r0), "=r"(r1), "=r"(r2), "=r"(r3) : "r"(addr))
#define CP_ASYNC_16(dst, src) \
    asm volatile("cp.async.cg.shared.global [%0], [%1], 16;" :: "r"(dst), "l"(src))
#define CP_COMMIT()  asm volatile("cp.async.commit_group;" ::: "memory")
#define CP_WAIT(n)   asm volatile("cp.async.wait_group %0;" :: "n"(n) : "memory")

// ---------------- weight transpose: W[K,D] -> T[D,K] fp16, 64x64 tiles ----------
__global__ void transpose_h2(const float* __restrict__ W, __half* __restrict__ T,
                             int K, int D) {
    __shared__ float t[64][65];
    int d0 = blockIdx.x * 64, k0 = blockIdx.y * 64;
    int tx = threadIdx.x, ty = threadIdx.y;     // 32 x 8
    #pragma unroll
    for (int i = 0; i < 64; i += 8) {
        const float* row = W + (size_t)(k0 + ty + i) * D + d0;
        t[ty + i][tx]      = row[tx];
        t[ty + i][tx + 32] = row[tx + 32];
    }
    __syncthreads();
    #pragma unroll
    for (int i = 0; i < 64; i += 8) {
        int dl = ty + i;
        float v0 = t[tx * 2][dl];
        float v1 = t[tx * 2 + 1][dl];
        *(__half2*)(T + (size_t)(d0 + dl) * K + k0 + tx * 2) = __floats2half2_rn(v0, v1);
    }
}

// ---------------- fp32 -> fp16 --------------------------------------------------
__global__ void cvt_h(const float* __restrict__ src, __half* __restrict__ H) {
    size_t i = (size_t)(blockIdx.x * blockDim.x + threadIdx.x);
    float4 v = ((const float4*)src)[i];
    ((__half2*)H)[i * 2 + 0] = __floats2half2_rn(v.x, v.y);
    ((__half2*)H)[i * 2 + 1] = __floats2half2_rn(v.z, v.w);
}

__global__ void concat_bias(const float* __restrict__ a, const float* __restrict__ b) {
    int i = blockIdx.x * blockDim.x + threadIdx.x;
    g_kvbias[i] = (i < MODEL_DIM) ? a[i] : b[i - MODEL_DIM];
}

// ---------------- fp16 HMMA GEMM (exact R7 kernel) --------------------------------
template <int BN>
__device__ __forceinline__ void hg_issue(uint32_t base,
        const __half* Ab, const __half* Bb, int K, int k0, int tid) {
    #pragma unroll
    for (int i = 0; i < 4; i++) {           // A: 128 rows x 8 units
        int idx = tid + i * 256;
        int r = idx >> 3, u = idx & 7;
        uint32_t sw = SMEM_SWIZZLE_128B((uint32_t)(r * 128 + u * 16));
        CP_ASYNC_16(base + sw, Ab + (size_t)r * K + k0 + u * 8);
    }
    #pragma unroll
    for (int i = 0; i < (BN * 8) / 256; i++) {  // B: BN rows x 8 units
        int idx = tid + i * 256;
        int r = idx >> 3, u = idx & 7;
        uint32_t sw = SMEM_SWIZZLE_128B((uint32_t)(r * 128 + u * 16));
        CP_ASYNC_16(base + 16384 + sw, Bb + (size_t)r * K + k0 + u * 8);
    }
    CP_COMMIT();
}

template <int BN, int EPI, bool WF32, bool WPL>
__global__ void __launch_bounds__(256, 1)
hgemm(const __half* __restrict__ A, const __half* __restrict__ Bp,
      const float* __restrict__ bias,
      float* __restrict__ C, __half* __restrict__ PH,
      int K, int Dout, const float* __restrict__ add1, const float* __restrict__ add2) {
    constexpr int NJ = BN / 32;
    constexpr int STAGE = 16384 + BN * 128;
    extern __shared__ __align__(1024) char sm[];
    uint32_t sb = smem_to_u32(sm);
    int tid = threadIdx.x;
    int wid = tid >> 5, lane = tid & 31;
    int wm = wid & 1, wn = wid >> 1;       // 2 (M) x 4 (N) warps

    const __half* Ab = A  + (size_t)blockIdx.y * 128 * K;
    const __half* Bb = Bp + (size_t)blockIdx.x * BN * K;

    float acc[4][NJ][4];
    #pragma unroll
    for (int i = 0; i < 4; i++)
        #pragma unroll
        for (int j = 0; j < NJ; j++)
            #pragma unroll
            for (int q = 0; q < 4; q++) acc[i][j][q] = 0.0f;

    int NS = K >> 6;
    hg_issue<BN>(sb + 0u * STAGE, Ab, Bb, K, 0,   tid);
    hg_issue<BN>(sb + 1u * STAGE, Ab, Bb, K, 64,  tid);
    hg_issue<BN>(sb + 2u * STAGE, Ab, Bb, K, 128, tid);

    for (int s = 0; s < NS; s++) {
        CP_WAIT(2);
        __syncthreads();
        if (s + 3 < NS) hg_issue<BN>(sb + (uint32_t)((s + 3) & 3) * STAGE, Ab, Bb, K, (s + 3) * 64, tid);
        else CP_COMMIT();
        uint32_t aA = sb + (uint32_t)(s & 3) * STAGE;
        uint32_t bB = aA + 16384;
        #pragma unroll
        for (int ks = 0; ks < 4; ks++) {
            uint32_t af[4][4], bf[NJ][2];
            #pragma unroll
            for (int i = 0; i < 4; i++) {
                int row = wm * 64 + i * 16 + (lane & 15);
                int kb = ks * 32 + (lane >> 4) * 16;
                uint32_t sw = SMEM_SWIZZLE_128B((uint32_t)(row * 128 + kb));
                LDMATRIX_X4(af[i][0], af[i][1], af[i][2], af[i][3], aA + sw);
            }
            #pragma unroll
            for (int jp = 0; jp < NJ / 2; jp++) {
                int n = wn * (BN / 4) + jp * 16 + (lane >> 4) * 8 + (lane & 7);
                int kb = ks * 32 + ((lane >> 3) & 1) * 16;
                uint32_t sw = SMEM_SWIZZLE_128B((uint32_t)(n * 128 + kb));
                LDMATRIX_X4(bf[2*jp][0], bf[2*jp][1], bf[2*jp+1][0], bf[2*jp+1][1], bB + sw);
            }
            #pragma unroll
            for (int i = 0; i < 4; i++)
                #pragma unroll
                for (int j = 0; j < NJ; j++) mma16816h(acc[i][j], af[i], bf[j]);
        }
    }

    int gr = lane >> 2;
    int gc = (lane & 3) * 2;
    #pragma unroll
    for (int i = 0; i < 4; i++) {
        int row0 = blockIdx.y * 128 + wm * 64 + i * 16 + gr;
        #pragma unroll
        for (int j = 0; j < NJ; j++) {
            int col = blockIdx.x * BN + wn * (BN / 4) + j * 8 + gc;
            float2 bv = *(const float2*)(bias + col);
            #pragma unroll
            for (int half = 0; half < 2; half++) {
                int row = row0 + half * 8;
                size_t idx = (size_t)row * Dout + col;
                float2 o;
                o.x = acc[i][j][half * 2 + 0] + bv.x;
                o.y = acc[i][j][half * 2 + 1] + bv.y;
                if (EPI == 1) { o.x = gelu_f(o.x); o.y = gelu_f(o.y); }
                if (EPI == 2) {
                    float2 a1 = *(const float2*)(add1 + idx);
                    float2 a2 = *(const float2*)(add2 + idx);
                    o.x += a1.x + a2.x; o.y += a1.y + a2.y;
                }
                if (EPI == 3) {
                    float2 a1 = *(const float2*)(add1 + idx);
                    o.x += a1.x; o.y += a1.y;
                }
                if (WF32) *(float2*)(C + idx) = o;
                if (WPL)  *(__half2*)(PH + idx) = __floats2half2_rn(o.x, o.y);
            }
        }
    }
}

// ---------------- RMSNorm -> fp16 -----------------------------------------------
__global__ void rmsnorm_h(const float* __restrict__ x,
                          const float* __restrict__ w,
                          __half* __restrict__ H) {
    int row = blockIdx.x;
    int t = threadIdx.x;  // 256
    const float4* xr = (const float4*)(x + (size_t)row * MODEL_DIM);
    float4 v0 = xr[t];
    float4 v1 = xr[t + 256];
    float s = v0.x*v0.x + v0.y*v0.y + v0.z*v0.z + v0.w*v0.w
            + v1.x*v1.x + v1.y*v1.y + v1.z*v1.z + v1.w*v1.w;
    #pragma unroll
    for (int o = 16; o > 0; o >>= 1) s += __shfl_xor_sync(0xffffffffu, s, o);
    __shared__ float red[8];
    if ((t & 31) == 0) red[t >> 5] = s;
    __syncthreads();
    float tot = red[0]+red[1]+red[2]+red[3]+red[4]+red[5]+red[6]+red[7];
    float inv = 1.0f / (sqrtf(tot / (float)MODEL_DIM) + EPSV);
    const float4* wr = (const float4*)w;
    float4 w0 = wr[t], w1 = wr[t + 256];
    __half2* Hr = (__half2*)(H + (size_t)row * MODEL_DIM);
    Hr[t*2]       = __floats2half2_rn(w0.x*v0.x*inv, w0.y*v0.y*inv);
    Hr[t*2+1]     = __floats2half2_rn(w0.z*v0.z*inv, w0.w*v0.w*inv);
    Hr[512+t*2]   = __floats2half2_rn(w1.x*v1.x*inv, w1.y*v1.y*inv);
    Hr[512+t*2+1] = __floats2half2_rn(w1.z*v1.z*inv, w1.w*v1.w*inv);
}

// ---------------- gamma / h_t elementwise (+ ht fp16) ----------------------------
__global__ void gamma_ht_kernel(const float* __restrict__ t,
                                const float* __restrict__ m2,
                                const float* __restrict__ z,
                                const float* __restrict__ glin,
                                const float* __restrict__ x,
                                float* __restrict__ gamma,
                                float* __restrict__ ht,
                                __half* __restrict__ hth) {
    size_t i = (size_t)(blockIdx.x * blockDim.x + threadIdx.x);
    float4 tv = ((const float4*)t)[i];
    float4 mv = ((const float4*)m2)[i];
    float4 zv = ((const float4*)z)[i];
    float4 gv = ((const float4*)glin)[i];
    float4 xv = ((const float4*)x)[i];
    float4 gm, h;
    gm.x = sigmoid_f(tv.x + mv.x); gm.y = sigmoid_f(tv.y + mv.y);
    gm.z = sigmoid_f(tv.z + mv.z); gm.w = sigmoid_f(tv.w + mv.w);
    h.x = zv.x * sigmoid_f(gv.x) + gm.x * xv.x;
    h.y = zv.y * sigmoid_f(gv.y) + gm.y * xv.y;
    h.z = zv.z * sigmoid_f(gv.z) + gm.z * xv.z;
    h.w = zv.w * sigmoid_f(gv.w) + gm.w * xv.w;
    ((float4*)gamma)[i] = gm;
    ((float4*)ht)[i] = h;
    ((__half2*)hth)[i*2]   = __floats2half2_rn(h.x, h.y);
    ((__half2*)hth)[i*2+1] = __floats2half2_rn(h.z, h.w);
}

// ---------------- cumprod ---------------------------------------------------------
__global__ void cumprod_local(const float* __restrict__ gamma, float* __restrict__ outp) {
    int c = blockIdx.x, bh = blockIdx.y, d2 = threadIdx.x;
    size_t base = (size_t)bh * SEQ * DH + (size_t)c * CS * DH + d2;
    float p = 1.0f;
    for (int i = 0; i < CS; i++) {
        p *= gamma[base + (size_t)i * DH];
        outp[base + (size_t)i * DH] = p;
    }
    g_cp_tot[(bh * NCHUNK + c) * DH + d2] = p;
}
__global__ void cumprod_scan() {
    int lane = blockIdx.x * blockDim.x + threadIdx.x;
    int bh = lane / DH, d2 = lane % DH;
    float r = 1.0f;
    for (int c = 0; c < NCHUNK; c++) {
        int idx = (bh * NCHUNK + c) * DH + d2;
        g_cp_pref[idx] = r;
        r *= g_cp_tot[idx];
    }
}
__global__ void cumprod_apply(float* __restrict__ outp) {
    int c = blockIdx.x, bh = blockIdx.y, d2 = threadIdx.x;
    if (c == 0) return;
    float pref = g_cp_pref[(bh * NCHUNK + c) * DH + d2];
    size_t base = (size_t)bh * SEQ * DH + (size_t)c * CS * DH + d2;
    for (int i = 0; i < CS; i++) outp[base + (size_t)i * DH] *= pref;
}

// ---------------- tensor-core attention over 64 memory tokens ---------------------
#define AQ_OFF 0u
#define AK_OFF 16384u
#define AV_OFF 32768u
#define ASC_OFF 49152u
#define APS_OFF (49152u + 64u*68u*4u)
#define ATTN_SMEM2 (49152 + 64*68*4 + 8192)
__global__ void __launch_bounds__(128, 1)
attn_mma(const __half* __restrict__ qah,
         const __half* __restrict__ kvh,
         __half* __restrict__ ctxh) {
    extern __shared__ __align__(1024) char smc[];
    uint32_t sb = smem_to_u32(smc);
    float* sc = (float*)(smc + ASC_OFF);
    int stile = blockIdx.x, h = blockIdx.y, b = blockIdx.z;
    int s0 = stile * 64;
    int tid = threadIdx.x, lane = tid & 31, wid = tid >> 5;
    int wm = wid & 1, wn = wid >> 1;

    #pragma unroll
    for (int i = 0; i < 8; i++) {
        int idx = tid + i * 128;
        int r = idx >> 4, u = idx & 15;
        int c = u >> 3, uc = u & 7;
        uint32_t sw = SMEM_SWIZZLE_128B((uint32_t)(r * 128 + uc * 16));
        CP_ASYNC_16(sb + AQ_OFF + c * 8192 + sw,
                    qah + (size_t)(b * SEQ + s0 + r) * MODEL_DIM + h * 128 + u * 8);
        CP_ASYNC_16(sb + AK_OFF + c * 8192 + sw,
                    kvh + (size_t)(b * MEM_TOKENS + r) * (2 * MODEL_DIM) + h * 128 + u * 8);
    }
    CP_COMMIT();
    for (int idx = tid; idx < 8192; idx += 128) {
        int m = idx >> 7, d = idx & 127;
        __half v = kvh[(size_t)(b * MEM_TOKENS + m) * (2 * MODEL_DIM) + MODEL_DIM + h * 128 + d];
        *(__half*)(smc + AV_OFF + SMEM_SWIZZLE_128B((uint32_t)(d * 128 + m * 2))) = v;
    }
    CP_WAIT(0);
    __syncthreads();

    float acc[2][4][4];
    #pragma unroll
    for (int i = 0; i < 2; i++)
        #pragma unroll
        for (int j = 0; j < 4; j++)
            #pragma unroll
            for (int q = 0; q < 4; q++) acc[i][j][q] = 0.0f;
    #pragma unroll
    for (int c = 0; c < 2; c++) {
        uint32_t qA = sb + AQ_OFF + c * 8192;
        uint32_t kB = sb + AK_OFF + c * 8192;
        #pragma unroll
        for (int ks = 0; ks < 4; ks++) {
            uint32_t af[2][4], bf[4][2];
            #pragma unroll
            for (int i = 0; i < 2; i++) {
                int row = wm * 32 + i * 16 + (lane & 15);
                int kb = ks * 32 + (lane >> 4) * 16;
                LDMATRIX_X4(af[i][0], af[i][1], af[i][2], af[i][3],
                            qA + SMEM_SWIZZLE_128B((uint32_t)(row * 128 + kb)));
            }
            #pragma unroll
            for (int jp = 0; jp < 2; jp++) {
                int n = wn * 32 + jp * 16 + (lane >> 4) * 8 + (lane & 7);
                int kb = ks * 32 + ((lane >> 3) & 1) * 16;
                LDMATRIX_X4(bf[2*jp][0], bf[2*jp][1], bf[2*jp+1][0], bf[2*jp+1][1],
                            kB + SMEM_SWIZZLE_128B((uint32_t)(n * 128 + kb)));
            }
            #pragma unroll
            for (int i = 0; i < 2; i++)
                #pragma unroll
                for (int j = 0; j < 4; j++) mma16816h(acc[i][j], af[i], bf[j]);
        }
    }
    const float scale = 0.08838834764831845f;
    int gr = lane >> 2, gc = (lane & 3) * 2;
    #pragma unroll
    for (int i = 0; i < 2; i++)
        #pragma unroll
        for (int j = 0; j < 4; j++)
            #pragma unroll
            for (int half = 0; half < 2; half++) {
                int row = wm * 32 + i * 16 + gr + half * 8;
                int col = wn * 32 + j * 8 + gc;
                sc[row * 68 + col]     = acc[i][j][half * 2 + 0] * scale;
                sc[row * 68 + col + 1] = acc[i][j][half * 2 + 1] * scale;
            }
    __syncthreads();

    if (tid < 64) {
        float* row = &sc[tid * 68];
        float mx = -1e30f;
        for (int m = 0; m < 64; m++) mx = fmaxf(mx, row[m]);
        float s = 0.0f;
        for (int m = 0; m < 64; m++) { float e = expf(row[m] - mx); row[m] = e; s += e; }
        float inv = 1.0f / s;
        for (int m = 0; m < 64; m++)
            *(__half*)(smc + APS_OFF + SMEM_SWIZZLE_128B((uint32_t)(tid * 128 + m * 2))) =
                __float2half_rn(row[m] * inv);
    }
    __syncthreads();

    float acc2[2][8][4];
    #pragma unroll
    for (int i = 0; i < 2; i++)
        #pragma unroll
        for (int j = 0; j < 8; j++)
            #pragma unroll
            for (int q = 0; q < 4; q++) acc2[i][j][q] = 0.0f;
    #pragma unroll
    for (int ks = 0; ks < 4; ks++) {
        uint32_t af[2][4], bf[8][2];
        #pragma unroll
        for (int i = 0; i < 2; i++) {
            int row = wm * 32 + i * 16 + (lane & 15);
            int kb = ks * 32 + (lane >> 4) * 16;
            LDMATRIX_X4(af[i][0], af[i][1], af[i][2], af[i][3],
                        sb + APS_OFF + SMEM_SWIZZLE_128B((uint32_t)(row * 128 + kb)));
        }
        #pragma unroll
        for (int jp = 0; jp < 4; jp++) {
            int n = wn * 64 + jp * 16 + (lane >> 4) * 8 + (lane & 7);
            int kb = ks * 32 + ((lane >> 3) & 1) * 16;
            LDMATRIX_X4(bf[2*jp][0], bf[2*jp][1], bf[2*jp+1][0], bf[2*jp+1][1],
                        sb + AV_OFF + SMEM_SWIZZLE_128B((uint32_t)(n * 128 + kb)));
        }
        #pragma unroll
        for (int i = 0; i < 2; i++)
            #pragma unroll
            for (int j = 0; j < 8; j++) mma16816h(acc2[i][j], af[i], bf[j]);
    }
    #pragma unroll
    for (int i = 0; i < 2; i++)
        #pragma unroll
        for (int j = 0; j < 8; j++)
            #pragma unroll
            for (int half = 0; half < 2; half++) {
                int row = wm * 32 + i * 16 + gr + half * 8;
                int d = wn * 64 + j * 8 + gc;
                size_t idx = (size_t)(b * SEQ + s0 + row) * MODEL_DIM + h * 128 + d;
                *(__half2*)(ctxh + idx) =
                    __floats2half2_rn(acc2[i][j][half * 2 + 0], acc2[i][j][half * 2 + 1]);
            }
}

// ---------------- one-time stream/event resources --------------------------------
static cudaStream_t g_s1 = nullptr, g_s2 = nullptr;
static cudaEvent_t  ge0, ge_rms, ge_twz, ge_tmd1, ge_tmd2, ge_tmcw, ge_twg, ge_tawq,
                    ge_tawo, ge_tf1, ge_tf2, ge_prep, ge_mcw, ge_md2, ge_g0, ge_g1,
                    ge_kv, ge_cum, ge_s2done;

// ---------------- host launcher -----------------------------------------------------
extern "C" void kernel_launch(void* const* d_in, const int* in_sizes, int n_in,
                              void* d_out, int out_size) {
    bool sig = (in_sizes[3] == MODEL_DIM);
    const float *x, *memory, *wk, *bk, *wz, *bz, *wg, *bg, *n1w, *n2w;
    const float *md1, *mb1, *md2, *mb2, *mcw, *mcb;
    const float *awq, *abq, *awk, *abk, *awv, *abv, *awo, *abo;
    const float *f1, *fb1, *f2, *fb2;
    #define IN(i) ((const float*)d_in[(i)])
    if (sig) {
        x = IN(0);  memory = IN(1);
        wk = IN(4);  bk = IN(5);  wz = IN(8);  bz = IN(9);  wg = IN(10); bg = IN(11);
        n1w = IN(12); n2w = IN(13);
        md1 = IN(14); mb1 = IN(15); md2 = IN(16); mb2 = IN(17); mcw = IN(18); mcb = IN(19);
        awq = IN(20); abq = IN(21); awk = IN(22); abk = IN(23); awv = IN(24); abv = IN(25);
        awo = IN(26); abo = IN(27);
        f1 = IN(28); fb1 = IN(29); f2 = IN(30); fb2 = IN(31);
    } else {
        x = IN(0);  memory = IN(1);
        wk = IN(3);  wz = IN(5);  wg = IN(6);
        md1 = IN(7); md2 = IN(8); mcw = IN(9);
        awq = IN(10); awk = IN(11); awv = IN(12); awo = IN(13);
        f1 = IN(14); f2 = IN(15);
        bk = IN(17); bz = IN(19); bg = IN(20);
        mb1 = IN(21); mb2 = IN(22); mcb = IN(23);
        abq = IN(24); abk = IN(25); abv = IN(26); abo = IN(27);
        fb1 = IN(28); fb2 = IN(29);
        n1w = IN(30); n2w = IN(31);
    }
    #undef IN

    float *zb, *glin, *tb, *m2b, *gammab, *htb, *xresb, *kvbias;
    cudaGetSymbolAddress((void**)&zb,    g_z);
    cudaGetSymbolAddress((void**)&glin,  g_glin);
    cudaGetSymbolAddress((void**)&tb,    g_t);
    cudaGetSymbolAddress((void**)&m2b,   g_m2);
    cudaGetSymbolAddress((void**)&gammab,g_gamma);
    cudaGetSymbolAddress((void**)&htb,   g_ht);
    cudaGetSymbolAddress((void**)&xresb, g_xres);
    cudaGetSymbolAddress((void**)&kvbias,g_kvbias);

    __half *xh,*xnh,*zh,*kh,*uh,*hth,*memh,*qah,*kvh,*ctxh,*xn2h,*a1h;
    cudaGetSymbolAddress((void**)&xh,  g_xh);
    cudaGetSymbolAddress((void**)&xnh, g_xnh);
    cudaGetSymbolAddress((void**)&zh,  g_zh);
    cudaGetSymbolAddress((void**)&kh,  g_kh);
    cudaGetSymbolAddress((void**)&uh,  g_uh);
    cudaGetSymbolAddress((void**)&hth, g_hth);
    cudaGetSymbolAddress((void**)&memh,g_memh);
    cudaGetSymbolAddress((void**)&qah, g_qah);
    cudaGetSymbolAddress((void**)&kvh, g_kvh);
    cudaGetSymbolAddress((void**)&ctxh,g_ctxh);
    cudaGetSymbolAddress((void**)&xn2h,g_xn2h);
    cudaGetSymbolAddress((void**)&a1h, g_a1h);

    __half *wkT,*wzT,*wgT,*mcwT,*awqT,*awoT,*awkvT,*md1T,*md2T,*f1T,*f2T;
    cudaGetSymbolAddress((void**)&wkT,  g_wk);
    cudaGetSymbolAddress((void**)&wzT,  g_wz);
    cudaGetSymbolAddress((void**)&wgT,  g_wg);
    cudaGetSymbolAddress((void**)&mcwT, g_mcw);
    cudaGetSymbolAddress((void**)&awqT, g_awq);
    cudaGetSymbolAddress((void**)&awoT, g_awo);
    cudaGetSymbolAddress((void**)&awkvT,g_awkv);
    cudaGetSymbolAddress((void**)&md1T, g_md1);
    cudaGetSymbolAddress((void**)&md2T, g_md2);
    cudaGetSymbolAddress((void**)&f1T,  g_f1);
    cudaGetSymbolAddress((void**)&f2T,  g_f2);

    float* out = (float*)d_out;
    float* cum = out + (size_t)NTOK * MODEL_DIM;

    const int SM256 = 4 * (16384 + 256 * 128);   // 196608
    const int SM128 = 4 * (16384 + 128 * 128);   // 131072
    cudaFuncSetAttribute((const void*)hgemm<256,0,false,true>,  cudaFuncAttributeMaxDynamicSharedMemorySize, SM256);
    cudaFuncSetAttribute((const void*)hgemm<256,0,true,true>,   cudaFuncAttributeMaxDynamicSharedMemorySize, SM256);
    cudaFuncSetAttribute((const void*)hgemm<256,0,true,false>,  cudaFuncAttributeMaxDynamicSharedMemorySize, SM256);
    cudaFuncSetAttribute((const void*)hgemm<256,1,false,true>,  cudaFuncAttributeMaxDynamicSharedMemorySize, SM256);
    cudaFuncSetAttribute((const void*)hgemm<256,2,true,false>,  cudaFuncAttributeMaxDynamicSharedMemorySize, SM256);
    cudaFuncSetAttribute((const void*)hgemm<256,3,true,false>,  cudaFuncAttributeMaxDynamicSharedMemorySize, SM256);
    cudaFuncSetAttribute((const void*)hgemm<128,1,false,true>,  cudaFuncAttributeMaxDynamicSharedMemorySize, SM128);
    cudaFuncSetAttribute((const void*)hgemm<128,0,false,true>,  cudaFuncAttributeMaxDynamicSharedMemorySize, SM128);
    cudaFuncSetAttribute(attn_mma, cudaFuncAttributeMaxDynamicSharedMemorySize, ATTN_SMEM2);

    dim3 tb8(32, 8);
    dim3 gT64(MODEL_DIM / 64, MODEL_DIM / 64);
    dim3 gDD(MODEL_DIM / 256, NTOK / 128);    // (8, 32) full
    dim3 gDDh(MODEL_DIM / 256, HTOK / 128);   // (8, 16) half
    dim3 gDFh(FFN_DIM / 256,  HTOK / 128);    // (32, 16) half

    const size_t offD = (size_t)HTOK * MODEL_DIM;
    const size_t offF = (size_t)HTOK * FFN_DIM;
    const size_t offKV = (size_t)MEM_TOKENS * 2 * MODEL_DIM;

    if (g_s1 == nullptr) {
        cudaStreamCreateWithFlags(&g_s1, cudaStreamNonBlocking);
        cudaStreamCreateWithFlags(&g_s2, cudaStreamNonBlocking);
        cudaEvent_t* evs[19] = {&ge0,&ge_rms,&ge_twz,&ge_tmd1,&ge_tmd2,&ge_tmcw,&ge_twg,&ge_tawq,
                                &ge_tawo,&ge_tf1,&ge_tf2,&ge_prep,&ge_mcw,&ge_md2,&ge_g0,&ge_g1,
                                &ge_kv,&ge_cum,&ge_s2done};
        for (int i = 0; i < 19; i++) cudaEventCreateWithFlags(evs[i], cudaEventDisableTiming);
    }
    cudaStream_t s1 = g_s1, s2 = g_s2;

    // ---------- fork (every event recorded before any wait on it, in host order)
    cudaEventRecord(ge0, 0);
    cudaStreamWaitEvent(s1, ge0, 0);
    cudaStreamWaitEvent(s2, ge0, 0);

    // ---- s2: prep ----
    cvt_h<<<(NTOK * MODEL_DIM / 4) / 256, 256, 0, s2>>>(x, xh);
    concat_bias<<<(2 * MODEL_DIM) / 256, 256, 0, s2>>>(abk, abv);
    cvt_h<<<(BATCH * MEM_TOKENS * MODEL_DIM / 4) / 64, 64, 0, s2>>>(memory, memh);
    cudaEventRecord(ge_prep, s2);

    // ---- main: rmsnorm ----
    rmsnorm_h<<<NTOK, 256>>>(x, n1w, xnh);
    cudaEventRecord(ge_rms, 0);

    // ---- s1: weight transposes + kv GEMM ----
    transpose_h2<<<gT64, tb8, 0, s1>>>(wk,  wkT,  MODEL_DIM, MODEL_DIM);
    transpose_h2<<<gT64, tb8, 0, s1>>>(wz,  wzT,  MODEL_DIM, MODEL_DIM);
    cudaEventRecord(ge_twz, s1);
    transpose_h2<<<dim3(INNER_DIM / 64, MODEL_DIM / 64), tb8, 0, s1>>>(md1, md1T, MODEL_DIM, INNER_DIM);
    cudaEventRecord(ge_tmd1, s1);
    transpose_h2<<<dim3(MODEL_DIM / 64, INNER_DIM / 64), tb8, 0, s1>>>(md2, md2T, INNER_DIM, MODEL_DIM);
    cudaEventRecord(ge_tmd2, s1);
    transpose_h2<<<gT64, tb8, 0, s1>>>(mcw, mcwT, MODEL_DIM, MODEL_DIM);
    cudaEventRecord(ge_tmcw, s1);
    transpose_h2<<<gT64, tb8, 0, s1>>>(wg,  wgT,  MODEL_DIM, MODEL_DIM);
    cudaEventRecord(ge_twg, s1);
    transpose_h2<<<gT64, tb8, 0, s1>>>(awq, awqT, MODEL_DIM, MODEL_DIM);
    cudaEventRecord(ge_tawq, s1);
    transpose_h2<<<gT64, tb8, 0, s1>>>(awk, awkvT,                               MODEL_DIM, MODEL_DIM);
    transpose_h2<<<gT64, tb8, 0, s1>>>(awv, awkvT + (size_t)MODEL_DIM*MODEL_DIM, MODEL_DIM, MODEL_DIM);
    cudaStreamWaitEvent(s1, ge_prep, 0);
    hgemm<128,0,false,true><<<dim3(2*MODEL_DIM/128, 1), 256, SM128, s1>>>(memh, awkvT, kvbias, nullptr, kvh, MODEL_DIM, 2*MODEL_DIM, nullptr, nullptr);
    cudaEventRecord(ge_kv, s1);
    transpose_h2<<<gT64, tb8, 0, s1>>>(awo, awoT, MODEL_DIM, MODEL_DIM);
    cudaEventRecord(ge_tawo, s1);
    transpose_h2<<<dim3(FFN_DIM / 64,  MODEL_DIM / 64), tb8, 0, s1>>>(f1, f1T, MODEL_DIM, FFN_DIM);
    cudaEventRecord(ge_tf1, s1);
    transpose_h2<<<dim3(MODEL_DIM / 64, FFN_DIM / 64),  tb8, 0, s1>>>(f2, f2T, FFN_DIM, MODEL_DIM);
    cudaEventRecord(ge_tf2, s1);

    // ---- s2: wk GEMM -> mcw GEMM [ge_mcw] -> wg GEMM (half 1) ----
    cudaStreamWaitEvent(s2, ge_rms, 0);
    cudaStreamWaitEvent(s2, ge_twz, 0);
    hgemm<256,0,false,true><<<gDD, 256, SM256, s2>>>(xnh, wkT, bk, nullptr, kh, MODEL_DIM, MODEL_DIM, nullptr, nullptr);
    cudaStreamWaitEvent(s2, ge_tmcw, 0);
    hgemm<256,0,true,false><<<gDD, 256, SM256, s2>>>(kh, mcwT, mcb, m2b, nullptr, MODEL_DIM, MODEL_DIM, nullptr, nullptr);
    cudaEventRecord(ge_mcw, s2);
    cudaStreamWaitEvent(s2, ge_twg, 0);
    hgemm<256,0,true,false><<<gDDh, 256, SM256, s2>>>(xh + offD, wgT, bg, glin + offD, nullptr, MODEL_DIM, MODEL_DIM, nullptr, nullptr);

    // ---- main: wz -> md1 -> md2 [ge_md2] -> wg (half 0) ----
    cudaStreamWaitEvent(0, ge_twz, 0);
    hgemm<256,0,true,true><<<gDD, 256, SM256>>>(xnh, wzT, bz, zb, zh, MODEL_DIM, MODEL_DIM, nullptr, nullptr);
    cudaStreamWaitEvent(0, ge_tmd1, 0);
    hgemm<128,1,false,true><<<dim3(INNER_DIM/128, NTOK/128), 256, SM128>>>(zh, md1T, mb1, nullptr, uh, MODEL_DIM, INNER_DIM, nullptr, nullptr);
    cudaStreamWaitEvent(0, ge_tmd2, 0);
    hgemm<256,0,true,false><<<gDD, 256, SM256>>>(uh, md2T, mb2, tb, nullptr, INNER_DIM, MODEL_DIM, nullptr, nullptr);
    cudaEventRecord(ge_md2, 0);
    cudaStreamWaitEvent(0, ge_prep, 0);
    cudaStreamWaitEvent(0, ge_twg, 0);
    hgemm<256,0,true,false><<<gDDh, 256, SM256>>>(xh, wgT, bg, glin, nullptr, MODEL_DIM, MODEL_DIM, nullptr, nullptr);

    // ---- main: gamma + h_t (half 0)  [needs m2b h0 <- ge_mcw; rest same-stream] ----
    cudaStreamWaitEvent(0, ge_mcw, 0);
    gamma_ht_kernel<<<(HTOK * MODEL_DIM) / (256 * 4), 256>>>(tb, m2b, zb, glin, x, gammab, htb, hth);
    cudaEventRecord(ge_g0, 0);

    // ---- s2: gamma + h_t (half 1)  [needs tb/zb <- ge_md2; glin h1 same-stream] ----
    cudaStreamWaitEvent(s2, ge_md2, 0);
    gamma_ht_kernel<<<(HTOK * MODEL_DIM) / (256 * 4), 256, 0, s2>>>(
        tb + offD, m2b + offD, zb + offD, glin + offD, x + offD,
        gammab + offD, htb + offD, hth + offD);
    cudaEventRecord(ge_g1, s2);

    // ---- s1: cumprod chain (second output; needs full gamma) ----
    cudaStreamWaitEvent(s1, ge_g0, 0);
    cudaStreamWaitEvent(s1, ge_g1, 0);
    cumprod_local<<<dim3(NCHUNK, NBH), DH, 0, s1>>>(gammab, cum);
    cumprod_scan<<<(NBH * DH) / 256, 256, 0, s1>>>();
    cumprod_apply<<<dim3(NCHUNK, NBH), DH, 0, s1>>>(cum);
    cudaEventRecord(ge_cum, s1);

    // ---- main: half-0 tail chain ----
    cudaStreamWaitEvent(0, ge_tawq, 0);
    hgemm<256,0,false,true><<<gDDh, 256, SM256>>>(hth, awqT, abq, nullptr, qah, MODEL_DIM, MODEL_DIM, nullptr, nullptr);
    cudaStreamWaitEvent(0, ge_kv, 0);
    attn_mma<<<dim3(SEQ / 64, NUM_HEADS, 1), 128, ATTN_SMEM2>>>(qah, kvh, ctxh);
    cudaStreamWaitEvent(0, ge_tawo, 0);
    hgemm<256,2,true,false><<<gDDh, 256, SM256>>>(ctxh, awoT, abo, xresb, nullptr, MODEL_DIM, MODEL_DIM, x, htb);
    rmsnorm_h<<<HTOK, 256>>>(xresb, n2w, xn2h);
    cudaStreamWaitEvent(0, ge_tf1, 0);
    hgemm<256,1,false,true><<<gDFh, 256, SM256>>>(xn2h, f1T, fb1, nullptr, a1h, MODEL_DIM, FFN_DIM, nullptr, nullptr);
    cudaStreamWaitEvent(0, ge_tf2, 0);
    hgemm<256,3,true,false><<<gDDh, 256, SM256>>>(a1h, f2T, fb2, out, nullptr, FFN_DIM, MODEL_DIM, xresb, nullptr);

    // ---- s2: half-1 tail chain ----
    cudaStreamWaitEvent(s2, ge_tawq, 0);
    hgemm<256,0,false,true><<<gDDh, 256, SM256, s2>>>(hth + offD, awqT, abq, nullptr, qah + offD, MODEL_DIM, MODEL_DIM, nullptr, nullptr);
    cudaStreamWaitEvent(s2, ge_kv, 0);
    attn_mma<<<dim3(SEQ / 64, NUM_HEADS, 1), 128, ATTN_SMEM2, s2>>>(qah + offD, kvh + offKV, ctxh + offD);
    cudaStreamWaitEvent(s2, ge_tawo, 0);
    hgemm<256,2,true,false><<<gDDh, 256, SM256, s2>>>(ctxh + offD, awoT, abo, xresb + offD, nullptr, MODEL_DIM, MODEL_DIM, x + offD, htb + offD);
    rmsnorm_h<<<HTOK, 256, 0, s2>>>(xresb + offD, n2w, xn2h + offD);
    cudaStreamWaitEvent(s2, ge_tf1, 0);
    hgemm<256,1,false,true><<<gDFh, 256, SM256, s2>>>(xn2h + offD, f1T, fb1, nullptr, a1h + offF, MODEL_DIM, FFN_DIM, nullptr, nullptr);
    cudaStreamWaitEvent(s2, ge_tf2, 0);
    hgemm<256,3,true,false><<<gDDh, 256, SM256, s2>>>(a1h + offF, f2T, fb2, out + offD, nullptr, FFN_DIM, MODEL_DIM, xresb + offD, nullptr);
    cudaEventRecord(ge_s2done, s2);

    // ---- join ----
    cudaStreamWaitEvent(0, ge_s2done, 0);
    cudaStreamWaitEvent(0, ge_cum, 0);
}

// round 16
// speedup vs baseline: 1.1856x; 1.0059x over previous
#include <cuda_runtime.h>
#include <cuda_fp16.h>
#include <math.h>
#include <stdint.h>

#define MODEL_DIM 2048
#define INNER_DIM 512
#define NUM_HEADS 16
#define FFN_DIM   8192
#define MEM_TOKENS 64
#define BATCH 2
#define SEQ   2048
#define NTOK  (BATCH*SEQ)            // 4096
#define HTOK  (NTOK/2)               // 2048 (one batch)
#define DH    (MODEL_DIM/NUM_HEADS)  // 128
#define EPSV  1e-6f

#define NCHUNK 32
#define CS     (SEQ/NCHUNK)          // 64
#define NBH    (BATCH*NUM_HEADS)     // 32

// ---------------- fp32 scratch -------------------------------------------------
__device__ float g_z    [NTOK*MODEL_DIM];
__device__ float g_glin [NTOK*MODEL_DIM];
__device__ float g_t    [NTOK*MODEL_DIM];
__device__ float g_m2   [NTOK*MODEL_DIM];
__device__ float g_gamma[NTOK*MODEL_DIM];
__device__ float g_ht   [NTOK*MODEL_DIM];
__device__ float g_xres [NTOK*MODEL_DIM];
__device__ float g_kvbias[2*MODEL_DIM];
__device__ float g_cp_tot [NBH*NCHUNK*DH];
__device__ float g_cp_pref[NBH*NCHUNK*DH];

// ---------------- fp16 activations ----------------------------------------------
__device__ __half g_xh  [NTOK*MODEL_DIM];
__device__ __half g_xnh [NTOK*MODEL_DIM];
__device__ __half g_zh  [NTOK*MODEL_DIM];
__device__ __half g_kh  [NTOK*MODEL_DIM];
__device__ __half g_uh  [NTOK*INNER_DIM];
__device__ __half g_hth [NTOK*MODEL_DIM];
__device__ __half g_memh[BATCH*MEM_TOKENS*MODEL_DIM];
__device__ __half g_qah [NTOK*MODEL_DIM];
__device__ __half g_kvh [BATCH*MEM_TOKENS*2*MODEL_DIM];   // [128, 4096] k|v
__device__ __half g_ctxh[NTOK*MODEL_DIM];
__device__ __half g_xn2h[NTOK*MODEL_DIM];
__device__ __half g_a1h [NTOK*FFN_DIM];

// ---------------- fp16 transposed weights [Dout, K] ----------------------------
#define DD (MODEL_DIM*MODEL_DIM)
__device__ __half g_wk [DD], g_wz [DD], g_wg [DD], g_mcw[DD];
__device__ __half g_awq[DD], g_awo[DD];
__device__ __half g_awkv[2*MODEL_DIM*MODEL_DIM];
__device__ __half g_md1[MODEL_DIM*INNER_DIM];
__device__ __half g_md2[INNER_DIM*MODEL_DIM];
__device__ __half g_f1 [MODEL_DIM*FFN_DIM];
__device__ __half g_f2 [FFN_DIM*MODEL_DIM];

// ---------------- helpers -------------------------------------------------------
__device__ __forceinline__ uint32_t smem_to_u32(const void* p) {
    uint32_t a;
    asm("{ .reg .u64 t; cvta.to.shared.u64 t, %1; cvt.u32.u64 %0, t; }" : "=r"(a) : "l"(p));
    return a;
}
#define SMEM_SWIZZLE_128B(o) ((o) ^ (((o) >> 3) & 0x70))

__device__ __forceinline__ float gelu_f(float v) {
    float t = 0.7978845608028654f * (v + 0.044715f * v * v * v);
    return 0.5f * v * (1.0f + tanhf(t));
}
__device__ __forceinline__ float sigmoid_f(float v) { return 1.0f / (1.0f + expf(-v)); }

__device__ __forceinline__ void mma16816h(float* c, const uint32_t* a, const uint32_t* b) {
    asm volatile("mma.sync.aligned.m16n8k16.row.col.f32.f16.f16.f32 "
        "{%0,%1,%2,%3}, {%4,%5,%6,%7}, {%8,%9}, {%0,%1,%2,%3};"
        : "+f"(c[0]), "+f"(c[1]), "+f"(c[2]), "+f"(c[3])
        : "r"(a[0]), "r"(a[1]), "r"(a[2]), "r"(a[3]), "r"(b[0]), "r"(b[1]));
}
#define LDMATRIX_X4(r0, r1, r2, r3, addr) \
    asm volatile("ldmatrix.sync.aligned.m8n8.x4.shared.b16 {%0,%1,%2,%3}, [%4];" \
        : "=r"(r0), "=r"(r1), "=r"(r2), "=r"(r3) : "r"(addr))
#define CP_ASYNC_16(dst, src) \
    asm volatile("cp.async.cg.shared.global [%0], [%1], 16;" :: "r"(dst), "l"(src))
#define CP_COMMIT()  asm volatile("cp.async.commit_group;" ::: "memory")
#define CP_WAIT(n)   asm volatile("cp.async.wait_group %0;" :: "n"(n) : "memory")

// ---------------- weight transpose: W[K,D] -> T[D,K] fp16, 64x64 tiles ----------
__global__ void transpose_h2(const float* __restrict__ W, __half* __restrict__ T,
                             int K, int D) {
    __shared__ float t[64][65];
    int d0 = blockIdx.x * 64, k0 = blockIdx.y * 64;
    int tx = threadIdx.x, ty = threadIdx.y;     // 32 x 8
    #pragma unroll
    for (int i = 0; i < 64; i += 8) {
        const float* row = W + (size_t)(k0 + ty + i) * D + d0;
        t[ty + i][tx]      = row[tx];
        t[ty + i][tx + 32] = row[tx + 32];
    }
    __syncthreads();
    #pragma unroll
    for (int i = 0; i < 64; i += 8) {
        int dl = ty + i;
        float v0 = t[tx * 2][dl];
        float v1 = t[tx * 2 + 1][dl];
        *(__half2*)(T + (size_t)(d0 + dl) * K + k0 + tx * 2) = __floats2half2_rn(v0, v1);
    }
}

// ---------------- fp32 -> fp16 --------------------------------------------------
__global__ void cvt_h(const float* __restrict__ src, __half* __restrict__ H) {
    size_t i = (size_t)(blockIdx.x * blockDim.x + threadIdx.x);
    float4 v = ((const float4*)src)[i];
    ((__half2*)H)[i * 2 + 0] = __floats2half2_rn(v.x, v.y);
    ((__half2*)H)[i * 2 + 1] = __floats2half2_rn(v.z, v.w);
}

__global__ void concat_bias(const float* __restrict__ a, const float* __restrict__ b) {
    int i = blockIdx.x * blockDim.x + threadIdx.x;
    g_kvbias[i] = (i < MODEL_DIM) ? a[i] : b[i - MODEL_DIM];
}

// ---------------- fp16 HMMA GEMM (exact R7 kernel) --------------------------------
template <int BN>
__device__ __forceinline__ void hg_issue(uint32_t base,
        const __half* Ab, const __half* Bb, int K, int k0, int tid) {
    #pragma unroll
    for (int i = 0; i < 4; i++) {           // A: 128 rows x 8 units
        int idx = tid + i * 256;
        int r = idx >> 3, u = idx & 7;
        uint32_t sw = SMEM_SWIZZLE_128B((uint32_t)(r * 128 + u * 16));
        CP_ASYNC_16(base + sw, Ab + (size_t)r * K + k0 + u * 8);
    }
    #pragma unroll
    for (int i = 0; i < (BN * 8) / 256; i++) {  // B: BN rows x 8 units
        int idx = tid + i * 256;
        int r = idx >> 3, u = idx & 7;
        uint32_t sw = SMEM_SWIZZLE_128B((uint32_t)(r * 128 + u * 16));
        CP_ASYNC_16(base + 16384 + sw, Bb + (size_t)r * K + k0 + u * 8);
    }
    CP_COMMIT();
}

template <int BN, int EPI, bool WF32, bool WPL>
__global__ void __launch_bounds__(256, 1)
hgemm(const __half* __restrict__ A, const __half* __restrict__ Bp,
      const float* __restrict__ bias,
      float* __restrict__ C, __half* __restrict__ PH,
      int K, int Dout, const float* __restrict__ add1, const float* __restrict__ add2) {
    constexpr int NJ = BN / 32;
    constexpr int STAGE = 16384 + BN * 128;
    extern __shared__ __align__(1024) char sm[];
    uint32_t sb = smem_to_u32(sm);
    int tid = threadIdx.x;
    int wid = tid >> 5, lane = tid & 31;
    int wm = wid & 1, wn = wid >> 1;       // 2 (M) x 4 (N) warps

    const __half* Ab = A  + (size_t)blockIdx.y * 128 * K;
    const __half* Bb = Bp + (size_t)blockIdx.x * BN * K;

    float acc[4][NJ][4];
    #pragma unroll
    for (int i = 0; i < 4; i++)
        #pragma unroll
        for (int j = 0; j < NJ; j++)
            #pragma unroll
            for (int q = 0; q < 4; q++) acc[i][j][q] = 0.0f;

    int NS = K >> 6;
    hg_issue<BN>(sb + 0u * STAGE, Ab, Bb, K, 0,   tid);
    hg_issue<BN>(sb + 1u * STAGE, Ab, Bb, K, 64,  tid);
    hg_issue<BN>(sb + 2u * STAGE, Ab, Bb, K, 128, tid);

    for (int s = 0; s < NS; s++) {
        CP_WAIT(2);
        __syncthreads();
        if (s + 3 < NS) hg_issue<BN>(sb + (uint32_t)((s + 3) & 3) * STAGE, Ab, Bb, K, (s + 3) * 64, tid);
        else CP_COMMIT();
        uint32_t aA = sb + (uint32_t)(s & 3) * STAGE;
        uint32_t bB = aA + 16384;
        #pragma unroll
        for (int ks = 0; ks < 4; ks++) {
            uint32_t af[4][4], bf[NJ][2];
            #pragma unroll
            for (int i = 0; i < 4; i++) {
                int row = wm * 64 + i * 16 + (lane & 15);
                int kb = ks * 32 + (lane >> 4) * 16;
                uint32_t sw = SMEM_SWIZZLE_128B((uint32_t)(row * 128 + kb));
                LDMATRIX_X4(af[i][0], af[i][1], af[i][2], af[i][3], aA + sw);
            }
            #pragma unroll
            for (int jp = 0; jp < NJ / 2; jp++) {
                int n = wn * (BN / 4) + jp * 16 + (lane >> 4) * 8 + (lane & 7);
                int kb = ks * 32 + ((lane >> 3) & 1) * 16;
                uint32_t sw = SMEM_SWIZZLE_128B((uint32_t)(n * 128 + kb));
                LDMATRIX_X4(bf[2*jp][0], bf[2*jp][1], bf[2*jp+1][0], bf[2*jp+1][1], bB + sw);
            }
            #pragma unroll
            for (int i = 0; i < 4; i++)
                #pragma unroll
                for (int j = 0; j < NJ; j++) mma16816h(acc[i][j], af[i], bf[j]);
        }
    }

    int gr = lane >> 2;
    int gc = (lane & 3) * 2;
    #pragma unroll
    for (int i = 0; i < 4; i++) {
        int row0 = blockIdx.y * 128 + wm * 64 + i * 16 + gr;
        #pragma unroll
        for (int j = 0; j < NJ; j++) {
            int col = blockIdx.x * BN + wn * (BN / 4) + j * 8 + gc;
            float2 bv = *(const float2*)(bias + col);
            #pragma unroll
            for (int half = 0; half < 2; half++) {
                int row = row0 + half * 8;
                size_t idx = (size_t)row * Dout + col;
                float2 o;
                o.x = acc[i][j][half * 2 + 0] + bv.x;
                o.y = acc[i][j][half * 2 + 1] + bv.y;
                if (EPI == 1) { o.x = gelu_f(o.x); o.y = gelu_f(o.y); }
                if (EPI == 2) {
                    float2 a1 = *(const float2*)(add1 + idx);
                    float2 a2 = *(const float2*)(add2 + idx);
                    o.x += a1.x + a2.x; o.y += a1.y + a2.y;
                }
                if (EPI == 3) {
                    float2 a1 = *(const float2*)(add1 + idx);
                    o.x += a1.x; o.y += a1.y;
                }
                if (WF32) *(float2*)(C + idx) = o;
                if (WPL)  *(__half2*)(PH + idx) = __floats2half2_rn(o.x, o.y);
            }
        }
    }
}

// ---------------- RMSNorm -> fp16 -----------------------------------------------
__global__ void rmsnorm_h(const float* __restrict__ x,
                          const float* __restrict__ w,
                          __half* __restrict__ H) {
    int row = blockIdx.x;
    int t = threadIdx.x;  // 256
    const float4* xr = (const float4*)(x + (size_t)row * MODEL_DIM);
    float4 v0 = xr[t];
    float4 v1 = xr[t + 256];
    float s = v0.x*v0.x + v0.y*v0.y + v0.z*v0.z + v0.w*v0.w
            + v1.x*v1.x + v1.y*v1.y + v1.z*v1.z + v1.w*v1.w;
    #pragma unroll
    for (int o = 16; o > 0; o >>= 1) s += __shfl_xor_sync(0xffffffffu, s, o);
    __shared__ float red[8];
    if ((t & 31) == 0) red[t >> 5] = s;
    __syncthreads();
    float tot = red[0]+red[1]+red[2]+red[3]+red[4]+red[5]+red[6]+red[7];
    float inv = 1.0f / (sqrtf(tot / (float)MODEL_DIM) + EPSV);
    const float4* wr = (const float4*)w;
    float4 w0 = wr[t], w1 = wr[t + 256];
    __half2* Hr = (__half2*)(H + (size_t)row * MODEL_DIM);
    Hr[t*2]       = __floats2half2_rn(w0.x*v0.x*inv, w0.y*v0.y*inv);
    Hr[t*2+1]     = __floats2half2_rn(w0.z*v0.z*inv, w0.w*v0.w*inv);
    Hr[512+t*2]   = __floats2half2_rn(w1.x*v1.x*inv, w1.y*v1.y*inv);
    Hr[512+t*2+1] = __floats2half2_rn(w1.z*v1.z*inv, w1.w*v1.w*inv);
}

// ---------------- gamma / h_t elementwise (+ ht fp16) ----------------------------
__global__ void gamma_ht_kernel(const float* __restrict__ t,
                                const float* __restrict__ m2,
                                const float* __restrict__ z,
                                const float* __restrict__ glin,
                                const float* __restrict__ x,
                                float* __restrict__ gamma,
                                float* __restrict__ ht,
                                __half* __restrict__ hth) {
    size_t i = (size_t)(blockIdx.x * blockDim.x + threadIdx.x);
    float4 tv = ((const float4*)t)[i];
    float4 mv = ((const float4*)m2)[i];
    float4 zv = ((const float4*)z)[i];
    float4 gv = ((const float4*)glin)[i];
    float4 xv = ((const float4*)x)[i];
    float4 gm, h;
    gm.x = sigmoid_f(tv.x + mv.x); gm.y = sigmoid_f(tv.y + mv.y);
    gm.z = sigmoid_f(tv.z + mv.z); gm.w = sigmoid_f(tv.w + mv.w);
    h.x = zv.x * sigmoid_f(gv.x) + gm.x * xv.x;
    h.y = zv.y * sigmoid_f(gv.y) + gm.y * xv.y;
    h.z = zv.z * sigmoid_f(gv.z) + gm.z * xv.z;
    h.w = zv.w * sigmoid_f(gv.w) + gm.w * xv.w;
    ((float4*)gamma)[i] = gm;
    ((float4*)ht)[i] = h;
    ((__half2*)hth)[i*2]   = __floats2half2_rn(h.x, h.y);
    ((__half2*)hth)[i*2+1] = __floats2half2_rn(h.z, h.w);
}

// ---------------- cumprod ---------------------------------------------------------
__global__ void cumprod_local(const float* __restrict__ gamma, float* __restrict__ outp) {
    int c = blockIdx.x, bh = blockIdx.y, d2 = threadIdx.x;
    size_t base = (size_t)bh * SEQ * DH + (size_t)c * CS * DH + d2;
    float p = 1.0f;
    for (int i = 0; i < CS; i++) {
        p *= gamma[base + (size_t)i * DH];
        outp[base + (size_t)i * DH] = p;
    }
    g_cp_tot[(bh * NCHUNK + c) * DH + d2] = p;
}
__global__ void cumprod_scan() {
    int lane = blockIdx.x * blockDim.x + threadIdx.x;
    int bh = lane / DH, d2 = lane % DH;
    float r = 1.0f;
    for (int c = 0; c < NCHUNK; c++) {
        int idx = (bh * NCHUNK + c) * DH + d2;
        g_cp_pref[idx] = r;
        r *= g_cp_tot[idx];
    }
}
__global__ void cumprod_apply(float* __restrict__ outp) {
    int c = blockIdx.x, bh = blockIdx.y, d2 = threadIdx.x;
    if (c == 0) return;
    float pref = g_cp_pref[(bh * NCHUNK + c) * DH + d2];
    size_t base = (size_t)bh * SEQ * DH + (size_t)c * CS * DH + d2;
    for (int i = 0; i < CS; i++) outp[base + (size_t)i * DH] *= pref;
}

// ---------------- tensor-core attention over 64 memory tokens ---------------------
#define AQ_OFF 0u
#define AK_OFF 16384u
#define AV_OFF 32768u
#define ASC_OFF 49152u
#define APS_OFF (49152u + 64u*68u*4u)
#define ATTN_SMEM2 (49152 + 64*68*4 + 8192)
__global__ void __launch_bounds__(128, 1)
attn_mma(const __half* __restrict__ qah,
         const __half* __restrict__ kvh,
         __half* __restrict__ ctxh) {
    extern __shared__ __align__(1024) char smc[];
    uint32_t sb = smem_to_u32(smc);
    float* sc = (float*)(smc + ASC_OFF);
    int stile = blockIdx.x, h = blockIdx.y, b = blockIdx.z;
    int s0 = stile * 64;
    int tid = threadIdx.x, lane = tid & 31, wid = tid >> 5;
    int wm = wid & 1, wn = wid >> 1;

    #pragma unroll
    for (int i = 0; i < 8; i++) {
        int idx = tid + i * 128;
        int r = idx >> 4, u = idx & 15;
        int c = u >> 3, uc = u & 7;
        uint32_t sw = SMEM_SWIZZLE_128B((uint32_t)(r * 128 + uc * 16));
        CP_ASYNC_16(sb + AQ_OFF + c * 8192 + sw,
                    qah + (size_t)(b * SEQ + s0 + r) * MODEL_DIM + h * 128 + u * 8);
        CP_ASYNC_16(sb + AK_OFF + c * 8192 + sw,
                    kvh + (size_t)(b * MEM_TOKENS + r) * (2 * MODEL_DIM) + h * 128 + u * 8);
    }
    CP_COMMIT();
    for (int idx = tid; idx < 8192; idx += 128) {
        int m = idx >> 7, d = idx & 127;
        __half v = kvh[(size_t)(b * MEM_TOKENS + m) * (2 * MODEL_DIM) + MODEL_DIM + h * 128 + d];
        *(__half*)(smc + AV_OFF + SMEM_SWIZZLE_128B((uint32_t)(d * 128 + m * 2))) = v;
    }
    CP_WAIT(0);
    __syncthreads();

    float acc[2][4][4];
    #pragma unroll
    for (int i = 0; i < 2; i++)
        #pragma unroll
        for (int j = 0; j < 4; j++)
            #pragma unroll
            for (int q = 0; q < 4; q++) acc[i][j][q] = 0.0f;
    #pragma unroll
    for (int c = 0; c < 2; c++) {
        uint32_t qA = sb + AQ_OFF + c * 8192;
        uint32_t kB = sb + AK_OFF + c * 8192;
        #pragma unroll
        for (int ks = 0; ks < 4; ks++) {
            uint32_t af[2][4], bf[4][2];
            #pragma unroll
            for (int i = 0; i < 2; i++) {
                int row = wm * 32 + i * 16 + (lane & 15);
                int kb = ks * 32 + (lane >> 4) * 16;
                LDMATRIX_X4(af[i][0], af[i][1], af[i][2], af[i][3],
                            qA + SMEM_SWIZZLE_128B((uint32_t)(row * 128 + kb)));
            }
            #pragma unroll
            for (int jp = 0; jp < 2; jp++) {
                int n = wn * 32 + jp * 16 + (lane >> 4) * 8 + (lane & 7);
                int kb = ks * 32 + ((lane >> 3) & 1) * 16;
                LDMATRIX_X4(bf[2*jp][0], bf[2*jp][1], bf[2*jp+1][0], bf[2*jp+1][1],
                            kB + SMEM_SWIZZLE_128B((uint32_t)(n * 128 + kb)));
            }
            #pragma unroll
            for (int i = 0; i < 2; i++)
                #pragma unroll
                for (int j = 0; j < 4; j++) mma16816h(acc[i][j], af[i], bf[j]);
        }
    }
    const float scale = 0.08838834764831845f;
    int gr = lane >> 2, gc = (lane & 3) * 2;
    #pragma unroll
    for (int i = 0; i < 2; i++)
        #pragma unroll
        for (int j = 0; j < 4; j++)
            #pragma unroll
            for (int half = 0; half < 2; half++) {
                int row = wm * 32 + i * 16 + gr + half * 8;
                int col = wn * 32 + j * 8 + gc;
                sc[row * 68 + col]     = acc[i][j][half * 2 + 0] * scale;
                sc[row * 68 + col + 1] = acc[i][j][half * 2 + 1] * scale;
            }
    __syncthreads();

    if (tid < 64) {
        float* row = &sc[tid * 68];
        float mx = -1e30f;
        for (int m = 0; m < 64; m++) mx = fmaxf(mx, row[m]);
        float s = 0.0f;
        for (int m = 0; m < 64; m++) { float e = expf(row[m] - mx); row[m] = e; s += e; }
        float inv = 1.0f / s;
        for (int m = 0; m < 64; m++)
            *(__half*)(smc + APS_OFF + SMEM_SWIZZLE_128B((uint32_t)(tid * 128 + m * 2))) =
                __float2half_rn(row[m] * inv);
    }
    __syncthreads();

    float acc2[2][8][4];
    #pragma unroll
    for (int i = 0; i < 2; i++)
        #pragma unroll
        for (int j = 0; j < 8; j++)
            #pragma unroll
            for (int q = 0; q < 4; q++) acc2[i][j][q] = 0.0f;
    #pragma unroll
    for (int ks = 0; ks < 4; ks++) {
        uint32_t af[2][4], bf[8][2];
        #pragma unroll
        for (int i = 0; i < 2; i++) {
            int row = wm * 32 + i * 16 + (lane & 15);
            int kb = ks * 32 + (lane >> 4) * 16;
            LDMATRIX_X4(af[i][0], af[i][1], af[i][2], af[i][3],
                        sb + APS_OFF + SMEM_SWIZZLE_128B((uint32_t)(row * 128 + kb)));
        }
        #pragma unroll
        for (int jp = 0; jp < 4; jp++) {
            int n = wn * 64 + jp * 16 + (lane >> 4) * 8 + (lane & 7);
            int kb = ks * 32 + ((lane >> 3) & 1) * 16;
            LDMATRIX_X4(bf[2*jp][0], bf[2*jp][1], bf[2*jp+1][0], bf[2*jp+1][1],
                        sb + AV_OFF + SMEM_SWIZZLE_128B((uint32_t)(n * 128 + kb)));
        }
        #pragma unroll
        for (int i = 0; i < 2; i++)
            #pragma unroll
            for (int j = 0; j < 8; j++) mma16816h(acc2[i][j], af[i], bf[j]);
    }
    #pragma unroll
    for (int i = 0; i < 2; i++)
        #pragma unroll
        for (int j = 0; j < 8; j++)
            #pragma unroll
            for (int half = 0; half < 2; half++) {
                int row = wm * 32 + i * 16 + gr + half * 8;
                int d = wn * 64 + j * 8 + gc;
                size_t idx = (size_t)(b * SEQ + s0 + row) * MODEL_DIM + h * 128 + d;
                *(__half2*)(ctxh + idx) =
                    __floats2half2_rn(acc2[i][j][half * 2 + 0], acc2[i][j][half * 2 + 1]);
            }
}

// ---------------- one-time stream/event resources --------------------------------
static cudaStream_t g_s1 = nullptr, g_s2 = nullptr;
static cudaEvent_t  ge0, ge_prep, ge_rms, ge_twz, ge_tmd1, ge_tmd2, ge_twk, ge_tmcw,
                    ge_twg, ge_tawq, ge_kv, ge_tawo, ge_tf1, ge_tf2,
                    ge_g0, ge_g1, ge_cum, ge_s2done;

// ---------------- host launcher -----------------------------------------------------
extern "C" void kernel_launch(void* const* d_in, const int* in_sizes, int n_in,
                              void* d_out, int out_size) {
    bool sig = (in_sizes[3] == MODEL_DIM);
    const float *x, *memory, *wk, *bk, *wz, *bz, *wg, *bg, *n1w, *n2w;
    const float *md1, *mb1, *md2, *mb2, *mcw, *mcb;
    const float *awq, *abq, *awk, *abk, *awv, *abv, *awo, *abo;
    const float *f1, *fb1, *f2, *fb2;
    #define IN(i) ((const float*)d_in[(i)])
    if (sig) {
        x = IN(0);  memory = IN(1);
        wk = IN(4);  bk = IN(5);  wz = IN(8);  bz = IN(9);  wg = IN(10); bg = IN(11);
        n1w = IN(12); n2w = IN(13);
        md1 = IN(14); mb1 = IN(15); md2 = IN(16); mb2 = IN(17); mcw = IN(18); mcb = IN(19);
        awq = IN(20); abq = IN(21); awk = IN(22); abk = IN(23); awv = IN(24); abv = IN(25);
        awo = IN(26); abo = IN(27);
        f1 = IN(28); fb1 = IN(29); f2 = IN(30); fb2 = IN(31);
    } else {
        x = IN(0);  memory = IN(1);
        wk = IN(3);  wz = IN(5);  wg = IN(6);
        md1 = IN(7); md2 = IN(8); mcw = IN(9);
        awq = IN(10); awk = IN(11); awv = IN(12); awo = IN(13);
        f1 = IN(14); f2 = IN(15);
        bk = IN(17); bz = IN(19); bg = IN(20);
        mb1 = IN(21); mb2 = IN(22); mcb = IN(23);
        abq = IN(24); abk = IN(25); abv = IN(26); abo = IN(27);
        fb1 = IN(28); fb2 = IN(29);
        n1w = IN(30); n2w = IN(31);
    }
    #undef IN

    float *zb, *glin, *tb, *m2b, *gammab, *htb, *xresb, *kvbias;
    cudaGetSymbolAddress((void**)&zb,    g_z);
    cudaGetSymbolAddress((void**)&glin,  g_glin);
    cudaGetSymbolAddress((void**)&tb,    g_t);
    cudaGetSymbolAddress((void**)&m2b,   g_m2);
    cudaGetSymbolAddress((void**)&gammab,g_gamma);
    cudaGetSymbolAddress((void**)&htb,   g_ht);
    cudaGetSymbolAddress((void**)&xresb, g_xres);
    cudaGetSymbolAddress((void**)&kvbias,g_kvbias);

    __half *xh,*xnh,*zh,*kh,*uh,*hth,*memh,*qah,*kvh,*ctxh,*xn2h,*a1h;
    cudaGetSymbolAddress((void**)&xh,  g_xh);
    cudaGetSymbolAddress((void**)&xnh, g_xnh);
    cudaGetSymbolAddress((void**)&zh,  g_zh);
    cudaGetSymbolAddress((void**)&kh,  g_kh);
    cudaGetSymbolAddress((void**)&uh,  g_uh);
    cudaGetSymbolAddress((void**)&hth, g_hth);
    cudaGetSymbolAddress((void**)&memh,g_memh);
    cudaGetSymbolAddress((void**)&qah, g_qah);
    cudaGetSymbolAddress((void**)&kvh, g_kvh);
    cudaGetSymbolAddress((void**)&ctxh,g_ctxh);
    cudaGetSymbolAddress((void**)&xn2h,g_xn2h);
    cudaGetSymbolAddress((void**)&a1h, g_a1h);

    __half *wkT,*wzT,*wgT,*mcwT,*awqT,*awoT,*awkvT,*md1T,*md2T,*f1T,*f2T;
    cudaGetSymbolAddress((void**)&wkT,  g_wk);
    cudaGetSymbolAddress((void**)&wzT,  g_wz);
    cudaGetSymbolAddress((void**)&wgT,  g_wg);
    cudaGetSymbolAddress((void**)&mcwT, g_mcw);
    cudaGetSymbolAddress((void**)&awqT, g_awq);
    cudaGetSymbolAddress((void**)&awoT, g_awo);
    cudaGetSymbolAddress((void**)&awkvT,g_awkv);
    cudaGetSymbolAddress((void**)&md1T, g_md1);
    cudaGetSymbolAddress((void**)&md2T, g_md2);
    cudaGetSymbolAddress((void**)&f1T,  g_f1);
    cudaGetSymbolAddress((void**)&f2T,  g_f2);

    float* out = (float*)d_out;
    float* cum = out + (size_t)NTOK * MODEL_DIM;

    const int SM256 = 4 * (16384 + 256 * 128);   // 196608
    const int SM128 = 4 * (16384 + 128 * 128);   // 131072
    cudaFuncSetAttribute((const void*)hgemm<256,0,false,true>,  cudaFuncAttributeMaxDynamicSharedMemorySize, SM256);
    cudaFuncSetAttribute((const void*)hgemm<256,0,true,true>,   cudaFuncAttributeMaxDynamicSharedMemorySize, SM256);
    cudaFuncSetAttribute((const void*)hgemm<256,0,true,false>,  cudaFuncAttributeMaxDynamicSharedMemorySize, SM256);
    cudaFuncSetAttribute((const void*)hgemm<256,1,false,true>,  cudaFuncAttributeMaxDynamicSharedMemorySize, SM256);
    cudaFuncSetAttribute((const void*)hgemm<256,2,true,false>,  cudaFuncAttributeMaxDynamicSharedMemorySize, SM256);
    cudaFuncSetAttribute((const void*)hgemm<256,3,true,false>,  cudaFuncAttributeMaxDynamicSharedMemorySize, SM256);
    cudaFuncSetAttribute((const void*)hgemm<128,1,false,true>,  cudaFuncAttributeMaxDynamicSharedMemorySize, SM128);
    cudaFuncSetAttribute((const void*)hgemm<128,0,false,true>,  cudaFuncAttributeMaxDynamicSharedMemorySize, SM128);
    cudaFuncSetAttribute(attn_mma, cudaFuncAttributeMaxDynamicSharedMemorySize, ATTN_SMEM2);

    dim3 tb8(32, 8);
    dim3 gT64(MODEL_DIM / 64, MODEL_DIM / 64);
    dim3 gDDh(MODEL_DIM / 256, HTOK / 128);   // (8, 16) half
    dim3 gDIh(INNER_DIM / 128, HTOK / 128);   // (4, 16) half, BN=128
    dim3 gDFh(FFN_DIM / 256,  HTOK / 128);    // (32, 16) half

    const size_t offD = (size_t)HTOK * MODEL_DIM;
    const size_t offI = (size_t)HTOK * INNER_DIM;
    const size_t offF = (size_t)HTOK * FFN_DIM;
    const size_t offKV = (size_t)MEM_TOKENS * 2 * MODEL_DIM;

    if (g_s1 == nullptr) {
        cudaStreamCreateWithFlags(&g_s1, cudaStreamNonBlocking);
        cudaStreamCreateWithFlags(&g_s2, cudaStreamNonBlocking);
        cudaEvent_t* evs[18] = {&ge0,&ge_prep,&ge_rms,&ge_twz,&ge_tmd1,&ge_tmd2,&ge_twk,&ge_tmcw,
                                &ge_twg,&ge_tawq,&ge_kv,&ge_tawo,&ge_tf1,&ge_tf2,
                                &ge_g0,&ge_g1,&ge_cum,&ge_s2done};
        for (int i = 0; i < 18; i++) cudaEventCreateWithFlags(evs[i], cudaEventDisableTiming);
    }
    cudaStream_t s1 = g_s1, s2 = g_s2;

    // ---------- fork (every event recorded before any wait on it, in host order)
    cudaEventRecord(ge0, 0);
    cudaStreamWaitEvent(s1, ge0, 0);
    cudaStreamWaitEvent(s2, ge0, 0);

    // ---- s2: prep ----
    cvt_h<<<(NTOK * MODEL_DIM / 4) / 256, 256, 0, s2>>>(x, xh);
    concat_bias<<<(2 * MODEL_DIM) / 256, 256, 0, s2>>>(abk, abv);
    cvt_h<<<(BATCH * MEM_TOKENS * MODEL_DIM / 4) / 64, 64, 0, s2>>>(memory, memh);
    cudaEventRecord(ge_prep, s2);

    // ---- main: rmsnorm (full) ----
    rmsnorm_h<<<NTOK, 256>>>(x, n1w, xnh);
    cudaEventRecord(ge_rms, 0);

    // ---- s1: weight transposes (consumption order) + kv GEMM ----
    transpose_h2<<<gT64, tb8, 0, s1>>>(wz,  wzT,  MODEL_DIM, MODEL_DIM);
    cudaEventRecord(ge_twz, s1);
    transpose_h2<<<dim3(INNER_DIM / 64, MODEL_DIM / 64), tb8, 0, s1>>>(md1, md1T, MODEL_DIM, INNER_DIM);
    cudaEventRecord(ge_tmd1, s1);
    transpose_h2<<<dim3(MODEL_DIM / 64, INNER_DIM / 64), tb8, 0, s1>>>(md2, md2T, INNER_DIM, MODEL_DIM);
    cudaEventRecord(ge_tmd2, s1);
    transpose_h2<<<gT64, tb8, 0, s1>>>(wk,  wkT,  MODEL_DIM, MODEL_DIM);
    cudaEventRecord(ge_twk, s1);
    transpose_h2<<<gT64, tb8, 0, s1>>>(mcw, mcwT, MODEL_DIM, MODEL_DIM);
    cudaEventRecord(ge_tmcw, s1);
    transpose_h2<<<gT64, tb8, 0, s1>>>(wg,  wgT,  MODEL_DIM, MODEL_DIM);
    cudaEventRecord(ge_twg, s1);
    transpose_h2<<<gT64, tb8, 0, s1>>>(awq, awqT, MODEL_DIM, MODEL_DIM);
    cudaEventRecord(ge_tawq, s1);
    transpose_h2<<<gT64, tb8, 0, s1>>>(awk, awkvT,                               MODEL_DIM, MODEL_DIM);
    transpose_h2<<<gT64, tb8, 0, s1>>>(awv, awkvT + (size_t)MODEL_DIM*MODEL_DIM, MODEL_DIM, MODEL_DIM);
    cudaStreamWaitEvent(s1, ge_prep, 0);
    hgemm<128,0,false,true><<<dim3(2*MODEL_DIM/128, 1), 256, SM128, s1>>>(memh, awkvT, kvbias, nullptr, kvh, MODEL_DIM, 2*MODEL_DIM, nullptr, nullptr);
    cudaEventRecord(ge_kv, s1);
    transpose_h2<<<gT64, tb8, 0, s1>>>(awo, awoT, MODEL_DIM, MODEL_DIM);
    cudaEventRecord(ge_tawo, s1);
    transpose_h2<<<dim3(FFN_DIM / 64,  MODEL_DIM / 64), tb8, 0, s1>>>(f1, f1T, MODEL_DIM, FFN_DIM);
    cudaEventRecord(ge_tf1, s1);
    transpose_h2<<<dim3(MODEL_DIM / 64, FFN_DIM / 64),  tb8, 0, s1>>>(f2, f2T, FFN_DIM, MODEL_DIM);
    cudaEventRecord(ge_tf2, s1);

    // ---- main: half-0 pipeline (head fully same-stream after waits on transposes) ----
    cudaStreamWaitEvent(0, ge_twz, 0);
    hgemm<256,0,true,true><<<gDDh, 256, SM256>>>(xnh, wzT, bz, zb, zh, MODEL_DIM, MODEL_DIM, nullptr, nullptr);
    cudaStreamWaitEvent(0, ge_tmd1, 0);
    hgemm<128,1,false,true><<<gDIh, 256, SM128>>>(zh, md1T, mb1, nullptr, uh, MODEL_DIM, INNER_DIM, nullptr, nullptr);
    cudaStreamWaitEvent(0, ge_tmd2, 0);
    hgemm<256,0,true,false><<<gDDh, 256, SM256>>>(uh, md2T, mb2, tb, nullptr, INNER_DIM, MODEL_DIM, nullptr, nullptr);
    cudaStreamWaitEvent(0, ge_twk, 0);
    hgemm<256,0,false,true><<<gDDh, 256, SM256>>>(xnh, wkT, bk, nullptr, kh, MODEL_DIM, MODEL_DIM, nullptr, nullptr);
    cudaStreamWaitEvent(0, ge_tmcw, 0);
    hgemm<256,0,true,false><<<gDDh, 256, SM256>>>(kh, mcwT, mcb, m2b, nullptr, MODEL_DIM, MODEL_DIM, nullptr, nullptr);
    cudaStreamWaitEvent(0, ge_prep, 0);
    cudaStreamWaitEvent(0, ge_twg, 0);
    hgemm<256,0,true,false><<<gDDh, 256, SM256>>>(xh, wgT, bg, glin, nullptr, MODEL_DIM, MODEL_DIM, nullptr, nullptr);
    gamma_ht_kernel<<<(HTOK * MODEL_DIM) / (256 * 4), 256>>>(tb, m2b, zb, glin, x, gammab, htb, hth);
    cudaEventRecord(ge_g0, 0);

    // ---- s2: half-1 pipeline ----
    cudaStreamWaitEvent(s2, ge_rms, 0);
    cudaStreamWaitEvent(s2, ge_twz, 0);
    hgemm<256,0,true,true><<<gDDh, 256, SM256, s2>>>(xnh + offD, wzT, bz, zb + offD, zh + offD, MODEL_DIM, MODEL_DIM, nullptr, nullptr);
    cudaStreamWaitEvent(s2, ge_tmd1, 0);
    hgemm<128,1,false,true><<<gDIh, 256, SM128, s2>>>(zh + offD, md1T, mb1, nullptr, uh + offI, MODEL_DIM, INNER_DIM, nullptr, nullptr);
    cudaStreamWaitEvent(s2, ge_tmd2, 0);
    hgemm<256,0,true,false><<<gDDh, 256, SM256, s2>>>(uh + offI, md2T, mb2, tb + offD, nullptr, INNER_DIM, MODEL_DIM, nullptr, nullptr);
    cudaStreamWaitEvent(s2, ge_twk, 0);
    hgemm<256,0,false,true><<<gDDh, 256, SM256, s2>>>(xnh + offD, wkT, bk, nullptr, kh + offD, MODEL_DIM, MODEL_DIM, nullptr, nullptr);
    cudaStreamWaitEvent(s2, ge_tmcw, 0);
    hgemm<256,0,true,false><<<gDDh, 256, SM256, s2>>>(kh + offD, mcwT, mcb, m2b + offD, nullptr, MODEL_DIM, MODEL_DIM, nullptr, nullptr);
    cudaStreamWaitEvent(s2, ge_twg, 0);
    hgemm<256,0,true,false><<<gDDh, 256, SM256, s2>>>(xh + offD, wgT, bg, glin + offD, nullptr, MODEL_DIM, MODEL_DIM, nullptr, nullptr);
    gamma_ht_kernel<<<(HTOK * MODEL_DIM) / (256 * 4), 256, 0, s2>>>(
        tb + offD, m2b + offD, zb + offD, glin + offD, x + offD,
        gammab + offD, htb + offD, hth + offD);
    cudaEventRecord(ge_g1, s2);

    // ---- s1: cumprod chain (second output; needs full gamma) ----
    cudaStreamWaitEvent(s1, ge_g0, 0);
    cudaStreamWaitEvent(s1, ge_g1, 0);
    cumprod_local<<<dim3(NCHUNK, NBH), DH, 0, s1>>>(gammab, cum);
    cumprod_scan<<<(NBH * DH) / 256, 256, 0, s1>>>();
    cumprod_apply<<<dim3(NCHUNK, NBH), DH, 0, s1>>>(cum);
    cudaEventRecord(ge_cum, s1);

    // ---- main: half-0 tail chain ----
    cudaStreamWaitEvent(0, ge_tawq, 0);
    hgemm<256,0,false,true><<<gDDh, 256, SM256>>>(hth, awqT, abq, nullptr, qah, MODEL_DIM, MODEL_DIM, nullptr, nullptr);
    cudaStreamWaitEvent(0, ge_kv, 0);
    attn_mma<<<dim3(SEQ / 64, NUM_HEADS, 1), 128, ATTN_SMEM2>>>(qah, kvh, ctxh);
    cudaStreamWaitEvent(0, ge_tawo, 0);
    hgemm<256,2,true,false><<<gDDh, 256, SM256>>>(ctxh, awoT, abo, xresb, nullptr, MODEL_DIM, MODEL_DIM, x, htb);
    rmsnorm_h<<<HTOK, 256>>>(xresb, n2w, xn2h);
    cudaStreamWaitEvent(0, ge_tf1, 0);
    hgemm<256,1,false,true><<<gDFh, 256, SM256>>>(xn2h, f1T, fb1, nullptr, a1h, MODEL_DIM, FFN_DIM, nullptr, nullptr);
    cudaStreamWaitEvent(0, ge_tf2, 0);
    hgemm<256,3,true,false><<<gDDh, 256, SM256>>>(a1h, f2T, fb2, out, nullptr, FFN_DIM, MODEL_DIM, xresb, nullptr);

    // ---- s2: half-1 tail chain ----
    cudaStreamWaitEvent(s2, ge_tawq, 0);
    hgemm<256,0,false,true><<<gDDh, 256, SM256, s2>>>(hth + offD, awqT, abq, nullptr, qah + offD, MODEL_DIM, MODEL_DIM, nullptr, nullptr);
    cudaStreamWaitEvent(s2, ge_kv, 0);
    attn_mma<<<dim3(SEQ / 64, NUM_HEADS, 1), 128, ATTN_SMEM2, s2>>>(qah + offD, kvh + offKV, ctxh + offD);
    cudaStreamWaitEvent(s2, ge_tawo, 0);
    hgemm<256,2,true,false><<<gDDh, 256, SM256, s2>>>(ctxh + offD, awoT, abo, xresb + offD, nullptr, MODEL_DIM, MODEL_DIM, x + offD, htb + offD);
    rmsnorm_h<<<HTOK, 256, 0, s2>>>(xresb + offD, n2w, xn2h + offD);
    cudaStreamWaitEvent(s2, ge_tf1, 0);
    hgemm<256,1,false,true><<<gDFh, 256, SM256, s2>>>(xn2h + offD, f1T, fb1, nullptr, a1h + offF, MODEL_DIM, FFN_DIM, nullptr, nullptr);
    cudaStreamWaitEvent(s2, ge_tf2, 0);
    hgemm<256,3,true,false><<<gDDh, 256, SM256, s2>>>(a1h + offF, f2T, fb2, out + offD, nullptr, FFN_DIM, MODEL_DIM, xresb + offD, nullptr);
    cudaEventRecord(ge_s2done, s2);

    // ---- join ----
    cudaStreamWaitEvent(0, ge_s2done, 0);
    cudaStreamWaitEvent(0, ge_cum, 0);
}

// round 17
// speedup vs baseline: 1.1874x; 1.0015x over previous
#include <cuda_runtime.h>
#include <cuda_fp16.h>
#include <math.h>
#include <stdint.h>

#define MODEL_DIM 2048
#define INNER_DIM 512
#define NUM_HEADS 16
#define FFN_DIM   8192
#define MEM_TOKENS 64
#define BATCH 2
#define SEQ   2048
#define NTOK  (BATCH*SEQ)            // 4096
#define HTOK  (NTOK/2)               // 2048 (one batch)
#define DH    (MODEL_DIM/NUM_HEADS)  // 128
#define EPSV  1e-6f

#define NCHUNK 32
#define CS     (SEQ/NCHUNK)          // 64
#define NBH    (BATCH*NUM_HEADS)     // 32

// ---------------- fp32 scratch -------------------------------------------------
__device__ float g_z    [NTOK*MODEL_DIM];
__device__ float g_glin [NTOK*MODEL_DIM];
__device__ float g_t    [NTOK*MODEL_DIM];
__device__ float g_m2   [NTOK*MODEL_DIM];
__device__ float g_gamma[NTOK*MODEL_DIM];
__device__ float g_ht   [NTOK*MODEL_DIM];
__device__ float g_xres [NTOK*MODEL_DIM];
__device__ float g_kvbias[2*MODEL_DIM];
__device__ float g_cp_tot [NBH*NCHUNK*DH];
__device__ float g_cp_pref[NBH*NCHUNK*DH];

// ---------------- fp16 activations ----------------------------------------------
__device__ __half g_xh  [NTOK*MODEL_DIM];
__device__ __half g_xnh [NTOK*MODEL_DIM];
__device__ __half g_zh  [NTOK*MODEL_DIM];
__device__ __half g_kh  [NTOK*MODEL_DIM];
__device__ __half g_uh  [NTOK*INNER_DIM];
__device__ __half g_hth [NTOK*MODEL_DIM];
__device__ __half g_memh[BATCH*MEM_TOKENS*MODEL_DIM];
__device__ __half g_qah [NTOK*MODEL_DIM];
__device__ __half g_kvh [BATCH*MEM_TOKENS*2*MODEL_DIM];   // [128, 4096] k|v
__device__ __half g_ctxh[NTOK*MODEL_DIM];
__device__ __half g_xn2h[NTOK*MODEL_DIM];
__device__ __half g_a1h [NTOK*FFN_DIM];

// ---------------- fp16 transposed weights [Dout, K] ----------------------------
#define DD (MODEL_DIM*MODEL_DIM)
__device__ __half g_wk [DD], g_wz [DD], g_wg [DD], g_mcw[DD];
__device__ __half g_awq[DD], g_awo[DD];
__device__ __half g_awkv[2*MODEL_DIM*MODEL_DIM];
__device__ __half g_md1[MODEL_DIM*INNER_DIM];
__device__ __half g_md2[INNER_DIM*MODEL_DIM];
__device__ __half g_f1 [MODEL_DIM*FFN_DIM];
__device__ __half g_f2 [FFN_DIM*MODEL_DIM];

// ---------------- helpers -------------------------------------------------------
__device__ __forceinline__ uint32_t smem_to_u32(const void* p) {
    uint32_t a;
    asm("{ .reg .u64 t; cvta.to.shared.u64 t, %1; cvt.u32.u64 %0, t; }" : "=r"(a) : "l"(p));
    return a;
}
#define SMEM_SWIZZLE_128B(o) ((o) ^ (((o) >> 3) & 0x70))

__device__ __forceinline__ float gelu_f(float v) {
    float t = 0.7978845608028654f * (v + 0.044715f * v * v * v);
    return 0.5f * v * (1.0f + tanhf(t));
}
__device__ __forceinline__ float sigmoid_f(float v) { return 1.0f / (1.0f + expf(-v)); }

__device__ __forceinline__ void mma16816h(float* c, const uint32_t* a, const uint32_t* b) {
    asm volatile("mma.sync.aligned.m16n8k16.row.col.f32.f16.f16.f32 "
        "{%0,%1,%2,%3}, {%4,%5,%6,%7}, {%8,%9}, {%0,%1,%2,%3};"
        : "+f"(c[0]), "+f"(c[1]), "+f"(c[2]), "+f"(c[3])
        : "r"(a[0]), "r"(a[1]), "r"(a[2]), "r"(a[3]), "r"(b[0]), "r"(b[1]));
}
#define LDMATRIX_X4(r0, r1, r2, r3, addr) \
    asm volatile("ldmatrix.sync.aligned.m8n8.x4.shared.b16 {%0,%1,%2,%3}, [%4];" \
        : "=r"(r0), "=r"(r1), "=r"(r2), "=r"(r3) : "r"(addr))
#define CP_ASYNC_16(dst, src) \
    asm volatile("cp.async.cg.shared.global [%0], [%1], 16;" :: "r"(dst), "l"(src))
#define CP_COMMIT()  asm volatile("cp.async.commit_group;" ::: "memory")
#define CP_WAIT(n)   asm volatile("cp.async.wait_group %0;" :: "n"(n) : "memory")

// ---------------- weight transpose: W[K,D] -> T[D,K] fp16, 64x64 tiles ----------
__global__ void transpose_h2(const float* __restrict__ W, __half* __restrict__ T,
                             int K, int D) {
    __shared__ float t[64][65];
    int d0 = blockIdx.x * 64, k0 = blockIdx.y * 64;
    int tx = threadIdx.x, ty = threadIdx.y;     // 32 x 8
    #pragma unroll
    for (int i = 0; i < 64; i += 8) {
        const float* row = W + (size_t)(k0 + ty + i) * D + d0;
        t[ty + i][tx]      = row[tx];
        t[ty + i][tx + 32] = row[tx + 32];
    }
    __syncthreads();
    #pragma unroll
    for (int i = 0; i < 64; i += 8) {
        int dl = ty + i;
        float v0 = t[tx * 2][dl];
        float v1 = t[tx * 2 + 1][dl];
        *(__half2*)(T + (size_t)(d0 + dl) * K + k0 + tx * 2) = __floats2half2_rn(v0, v1);
    }
}

// ---------------- fp32 -> fp16 --------------------------------------------------
__global__ void cvt_h(const float* __restrict__ src, __half* __restrict__ H) {
    size_t i = (size_t)(blockIdx.x * blockDim.x + threadIdx.x);
    float4 v = ((const float4*)src)[i];
    ((__half2*)H)[i * 2 + 0] = __floats2half2_rn(v.x, v.y);
    ((__half2*)H)[i * 2 + 1] = __floats2half2_rn(v.z, v.w);
}

__global__ void concat_bias(const float* __restrict__ a, const float* __restrict__ b) {
    int i = blockIdx.x * blockDim.x + threadIdx.x;
    g_kvbias[i] = (i < MODEL_DIM) ? a[i] : b[i - MODEL_DIM];
}

// ---------------- fp16 HMMA GEMM (exact R7 kernel) --------------------------------
template <int BN>
__device__ __forceinline__ void hg_issue(uint32_t base,
        const __half* Ab, const __half* Bb, int K, int k0, int tid) {
    #pragma unroll
    for (int i = 0; i < 4; i++) {           // A: 128 rows x 8 units
        int idx = tid + i * 256;
        int r = idx >> 3, u = idx & 7;
        uint32_t sw = SMEM_SWIZZLE_128B((uint32_t)(r * 128 + u * 16));
        CP_ASYNC_16(base + sw, Ab + (size_t)r * K + k0 + u * 8);
    }
    #pragma unroll
    for (int i = 0; i < (BN * 8) / 256; i++) {  // B: BN rows x 8 units
        int idx = tid + i * 256;
        int r = idx >> 3, u = idx & 7;
        uint32_t sw = SMEM_SWIZZLE_128B((uint32_t)(r * 128 + u * 16));
        CP_ASYNC_16(base + 16384 + sw, Bb + (size_t)r * K + k0 + u * 8);
    }
    CP_COMMIT();
}

template <int BN, int EPI, bool WF32, bool WPL>
__global__ void __launch_bounds__(256, 1)
hgemm(const __half* __restrict__ A, const __half* __restrict__ Bp,
      const float* __restrict__ bias,
      float* __restrict__ C, __half* __restrict__ PH,
      int K, int Dout, const float* __restrict__ add1, const float* __restrict__ add2) {
    constexpr int NJ = BN / 32;
    constexpr int STAGE = 16384 + BN * 128;
    extern __shared__ __align__(1024) char sm[];
    uint32_t sb = smem_to_u32(sm);
    int tid = threadIdx.x;
    int wid = tid >> 5, lane = tid & 31;
    int wm = wid & 1, wn = wid >> 1;       // 2 (M) x 4 (N) warps

    const __half* Ab = A  + (size_t)blockIdx.y * 128 * K;
    const __half* Bb = Bp + (size_t)blockIdx.x * BN * K;

    float acc[4][NJ][4];
    #pragma unroll
    for (int i = 0; i < 4; i++)
        #pragma unroll
        for (int j = 0; j < NJ; j++)
            #pragma unroll
            for (int q = 0; q < 4; q++) acc[i][j][q] = 0.0f;

    int NS = K >> 6;
    hg_issue<BN>(sb + 0u * STAGE, Ab, Bb, K, 0,   tid);
    hg_issue<BN>(sb + 1u * STAGE, Ab, Bb, K, 64,  tid);
    hg_issue<BN>(sb + 2u * STAGE, Ab, Bb, K, 128, tid);

    for (int s = 0; s < NS; s++) {
        CP_WAIT(2);
        __syncthreads();
        if (s + 3 < NS) hg_issue<BN>(sb + (uint32_t)((s + 3) & 3) * STAGE, Ab, Bb, K, (s + 3) * 64, tid);
        else CP_COMMIT();
        uint32_t aA = sb + (uint32_t)(s & 3) * STAGE;
        uint32_t bB = aA + 16384;
        #pragma unroll
        for (int ks = 0; ks < 4; ks++) {
            uint32_t af[4][4], bf[NJ][2];
            #pragma unroll
            for (int i = 0; i < 4; i++) {
                int row = wm * 64 + i * 16 + (lane & 15);
                int kb = ks * 32 + (lane >> 4) * 16;
                uint32_t sw = SMEM_SWIZZLE_128B((uint32_t)(row * 128 + kb));
                LDMATRIX_X4(af[i][0], af[i][1], af[i][2], af[i][3], aA + sw);
            }
            #pragma unroll
            for (int jp = 0; jp < NJ / 2; jp++) {
                int n = wn * (BN / 4) + jp * 16 + (lane >> 4) * 8 + (lane & 7);
                int kb = ks * 32 + ((lane >> 3) & 1) * 16;
                uint32_t sw = SMEM_SWIZZLE_128B((uint32_t)(n * 128 + kb));
                LDMATRIX_X4(bf[2*jp][0], bf[2*jp][1], bf[2*jp+1][0], bf[2*jp+1][1], bB + sw);
            }
            #pragma unroll
            for (int i = 0; i < 4; i++)
                #pragma unroll
                for (int j = 0; j < NJ; j++) mma16816h(acc[i][j], af[i], bf[j]);
        }
    }

    int gr = lane >> 2;
    int gc = (lane & 3) * 2;
    #pragma unroll
    for (int i = 0; i < 4; i++) {
        int row0 = blockIdx.y * 128 + wm * 64 + i * 16 + gr;
        #pragma unroll
        for (int j = 0; j < NJ; j++) {
            int col = blockIdx.x * BN + wn * (BN / 4) + j * 8 + gc;
            float2 bv = *(const float2*)(bias + col);
            #pragma unroll
            for (int half = 0; half < 2; half++) {
                int row = row0 + half * 8;
                size_t idx = (size_t)row * Dout + col;
                float2 o;
                o.x = acc[i][j][half * 2 + 0] + bv.x;
                o.y = acc[i][j][half * 2 + 1] + bv.y;
                if (EPI == 1) { o.x = gelu_f(o.x); o.y = gelu_f(o.y); }
                if (EPI == 2) {
                    float2 a1 = *(const float2*)(add1 + idx);
                    float2 a2 = *(const float2*)(add2 + idx);
                    o.x += a1.x + a2.x; o.y += a1.y + a2.y;
                }
                if (EPI == 3) {
                    float2 a1 = *(const float2*)(add1 + idx);
                    o.x += a1.x; o.y += a1.y;
                }
                if (WF32) *(float2*)(C + idx) = o;
                if (WPL)  *(__half2*)(PH + idx) = __floats2half2_rn(o.x, o.y);
            }
        }
    }
}

// ---------------- RMSNorm -> fp16 -----------------------------------------------
__global__ void rmsnorm_h(const float* __restrict__ x,
                          const float* __restrict__ w,
                          __half* __restrict__ H) {
    int row = blockIdx.x;
    int t = threadIdx.x;  // 256
    const float4* xr = (const float4*)(x + (size_t)row * MODEL_DIM);
    float4 v0 = xr[t];
    float4 v1 = xr[t + 256];
    float s = v0.x*v0.x + v0.y*v0.y + v0.z*v0.z + v0.w*v0.w
            + v1.x*v1.x + v1.y*v1.y + v1.z*v1.z + v1.w*v1.w;
    #pragma unroll
    for (int o = 16; o > 0; o >>= 1) s += __shfl_xor_sync(0xffffffffu, s, o);
    __shared__ float red[8];
    if ((t & 31) == 0) red[t >> 5] = s;
    __syncthreads();
    float tot = red[0]+red[1]+red[2]+red[3]+red[4]+red[5]+red[6]+red[7];
    float inv = 1.0f / (sqrtf(tot / (float)MODEL_DIM) + EPSV);
    const float4* wr = (const float4*)w;
    float4 w0 = wr[t], w1 = wr[t + 256];
    __half2* Hr = (__half2*)(H + (size_t)row * MODEL_DIM);
    Hr[t*2]       = __floats2half2_rn(w0.x*v0.x*inv, w0.y*v0.y*inv);
    Hr[t*2+1]     = __floats2half2_rn(w0.z*v0.z*inv, w0.w*v0.w*inv);
    Hr[512+t*2]   = __floats2half2_rn(w1.x*v1.x*inv, w1.y*v1.y*inv);
    Hr[512+t*2+1] = __floats2half2_rn(w1.z*v1.z*inv, w1.w*v1.w*inv);
}

// ---------------- gamma / h_t elementwise (+ ht fp16) ----------------------------
__global__ void gamma_ht_kernel(const float* __restrict__ t,
                                const float* __restrict__ m2,
                                const float* __restrict__ z,
                                const float* __restrict__ glin,
                                const float* __restrict__ x,
                                float* __restrict__ gamma,
                                float* __restrict__ ht,
                                __half* __restrict__ hth) {
    size_t i = (size_t)(blockIdx.x * blockDim.x + threadIdx.x);
    float4 tv = ((const float4*)t)[i];
    float4 mv = ((const float4*)m2)[i];
    float4 zv = ((const float4*)z)[i];
    float4 gv = ((const float4*)glin)[i];
    float4 xv = ((const float4*)x)[i];
    float4 gm, h;
    gm.x = sigmoid_f(tv.x + mv.x); gm.y = sigmoid_f(tv.y + mv.y);
    gm.z = sigmoid_f(tv.z + mv.z); gm.w = sigmoid_f(tv.w + mv.w);
    h.x = zv.x * sigmoid_f(gv.x) + gm.x * xv.x;
    h.y = zv.y * sigmoid_f(gv.y) + gm.y * xv.y;
    h.z = zv.z * sigmoid_f(gv.z) + gm.z * xv.z;
    h.w = zv.w * sigmoid_f(gv.w) + gm.w * xv.w;
    ((float4*)gamma)[i] = gm;
    ((float4*)ht)[i] = h;
    ((__half2*)hth)[i*2]   = __floats2half2_rn(h.x, h.y);
    ((__half2*)hth)[i*2+1] = __floats2half2_rn(h.z, h.w);
}

// ---------------- cumprod ---------------------------------------------------------
__global__ void cumprod_local(const float* __restrict__ gamma, float* __restrict__ outp) {
    int c = blockIdx.x, bh = blockIdx.y, d2 = threadIdx.x;
    size_t base = (size_t)bh * SEQ * DH + (size_t)c * CS * DH + d2;
    float p = 1.0f;
    for (int i = 0; i < CS; i++) {
        p *= gamma[base + (size_t)i * DH];
        outp[base + (size_t)i * DH] = p;
    }
    g_cp_tot[(bh * NCHUNK + c) * DH + d2] = p;
}
__global__ void cumprod_scan() {
    int lane = blockIdx.x * blockDim.x + threadIdx.x;
    int bh = lane / DH, d2 = lane % DH;
    float r = 1.0f;
    for (int c = 0; c < NCHUNK; c++) {
        int idx = (bh * NCHUNK + c) * DH + d2;
        g_cp_pref[idx] = r;
        r *= g_cp_tot[idx];
    }
}
__global__ void cumprod_apply(float* __restrict__ outp) {
    int c = blockIdx.x, bh = blockIdx.y, d2 = threadIdx.x;
    if (c == 0) return;
    float pref = g_cp_pref[(bh * NCHUNK + c) * DH + d2];
    size_t base = (size_t)bh * SEQ * DH + (size_t)c * CS * DH + d2;
    for (int i = 0; i < CS; i++) outp[base + (size_t)i * DH] *= pref;
}

// ---------------- tensor-core attention over 64 memory tokens ---------------------
#define AQ_OFF 0u
#define AK_OFF 16384u
#define AV_OFF 32768u
#define ASC_OFF 49152u
#define APS_OFF (49152u + 64u*68u*4u)
#define ATTN_SMEM2 (49152 + 64*68*4 + 8192)
__global__ void __launch_bounds__(128, 1)
attn_mma(const __half* __restrict__ qah,
         const __half* __restrict__ kvh,
         __half* __restrict__ ctxh) {
    extern __shared__ __align__(1024) char smc[];
    uint32_t sb = smem_to_u32(smc);
    float* sc = (float*)(smc + ASC_OFF);
    int stile = blockIdx.x, h = blockIdx.y, b = blockIdx.z;
    int s0 = stile * 64;
    int tid = threadIdx.x, lane = tid & 31, wid = tid >> 5;
    int wm = wid & 1, wn = wid >> 1;

    #pragma unroll
    for (int i = 0; i < 8; i++) {
        int idx = tid + i * 128;
        int r = idx >> 4, u = idx & 15;
        int c = u >> 3, uc = u & 7;
        uint32_t sw = SMEM_SWIZZLE_128B((uint32_t)(r * 128 + uc * 16));
        CP_ASYNC_16(sb + AQ_OFF + c * 8192 + sw,
                    qah + (size_t)(b * SEQ + s0 + r) * MODEL_DIM + h * 128 + u * 8);
        CP_ASYNC_16(sb + AK_OFF + c * 8192 + sw,
                    kvh + (size_t)(b * MEM_TOKENS + r) * (2 * MODEL_DIM) + h * 128 + u * 8);
    }
    CP_COMMIT();
    for (int idx = tid; idx < 8192; idx += 128) {
        int m = idx >> 7, d = idx & 127;
        __half v = kvh[(size_t)(b * MEM_TOKENS + m) * (2 * MODEL_DIM) + MODEL_DIM + h * 128 + d];
        *(__half*)(smc + AV_OFF + SMEM_SWIZZLE_128B((uint32_t)(d * 128 + m * 2))) = v;
    }
    CP_WAIT(0);
    __syncthreads();

    float acc[2][4][4];
    #pragma unroll
    for (int i = 0; i < 2; i++)
        #pragma unroll
        for (int j = 0; j < 4; j++)
            #pragma unroll
            for (int q = 0; q < 4; q++) acc[i][j][q] = 0.0f;
    #pragma unroll
    for (int c = 0; c < 2; c++) {
        uint32_t qA = sb + AQ_OFF + c * 8192;
        uint32_t kB = sb + AK_OFF + c * 8192;
        #pragma unroll
        for (int ks = 0; ks < 4; ks++) {
            uint32_t af[2][4], bf[4][2];
            #pragma unroll
            for (int i = 0; i < 2; i++) {
                int row = wm * 32 + i * 16 + (lane & 15);
                int kb = ks * 32 + (lane >> 4) * 16;
                LDMATRIX_X4(af[i][0], af[i][1], af[i][2], af[i][3],
                            qA + SMEM_SWIZZLE_128B((uint32_t)(row * 128 + kb)));
            }
            #pragma unroll
            for (int jp = 0; jp < 2; jp++) {
                int n = wn * 32 + jp * 16 + (lane >> 4) * 8 + (lane & 7);
                int kb = ks * 32 + ((lane >> 3) & 1) * 16;
                LDMATRIX_X4(bf[2*jp][0], bf[2*jp][1], bf[2*jp+1][0], bf[2*jp+1][1],
                            kB + SMEM_SWIZZLE_128B((uint32_t)(n * 128 + kb)));
            }
            #pragma unroll
            for (int i = 0; i < 2; i++)
                #pragma unroll
                for (int j = 0; j < 4; j++) mma16816h(acc[i][j], af[i], bf[j]);
        }
    }
    const float scale = 0.08838834764831845f;
    int gr = lane >> 2, gc = (lane & 3) * 2;
    #pragma unroll
    for (int i = 0; i < 2; i++)
        #pragma unroll
        for (int j = 0; j < 4; j++)
            #pragma unroll
            for (int half = 0; half < 2; half++) {
                int row = wm * 32 + i * 16 + gr + half * 8;
                int col = wn * 32 + j * 8 + gc;
                sc[row * 68 + col]     = acc[i][j][half * 2 + 0] * scale;
                sc[row * 68 + col + 1] = acc[i][j][half * 2 + 1] * scale;
            }
    __syncthreads();

    if (tid < 64) {
        float* row = &sc[tid * 68];
        float mx = -1e30f;
        for (int m = 0; m < 64; m++) mx = fmaxf(mx, row[m]);
        float s = 0.0f;
        for (int m = 0; m < 64; m++) { float e = expf(row[m] - mx); row[m] = e; s += e; }
        float inv = 1.0f / s;
        for (int m = 0; m < 64; m++)
            *(__half*)(smc + APS_OFF + SMEM_SWIZZLE_128B((uint32_t)(tid * 128 + m * 2))) =
                __float2half_rn(row[m] * inv);
    }
    __syncthreads();

    float acc2[2][8][4];
    #pragma unroll
    for (int i = 0; i < 2; i++)
        #pragma unroll
        for (int j = 0; j < 8; j++)
            #pragma unroll
            for (int q = 0; q < 4; q++) acc2[i][j][q] = 0.0f;
    #pragma unroll
    for (int ks = 0; ks < 4; ks++) {
        uint32_t af[2][4], bf[8][2];
        #pragma unroll
        for (int i = 0; i < 2; i++) {
            int row = wm * 32 + i * 16 + (lane & 15);
            int kb = ks * 32 + (lane >> 4) * 16;
            LDMATRIX_X4(af[i][0], af[i][1], af[i][2], af[i][3],
                        sb + APS_OFF + SMEM_SWIZZLE_128B((uint32_t)(row * 128 + kb)));
        }
        #pragma unroll
        for (int jp = 0; jp < 4; jp++) {
            int n = wn * 64 + jp * 16 + (lane >> 4) * 8 + (lane & 7);
            int kb = ks * 32 + ((lane >> 3) & 1) * 16;
            LDMATRIX_X4(bf[2*jp][0], bf[2*jp][1], bf[2*jp+1][0], bf[2*jp+1][1],
                        sb + AV_OFF + SMEM_SWIZZLE_128B((uint32_t)(n * 128 + kb)));
        }
        #pragma unroll
        for (int i = 0; i < 2; i++)
            #pragma unroll
            for (int j = 0; j < 8; j++) mma16816h(acc2[i][j], af[i], bf[j]);
    }
    #pragma unroll
    for (int i = 0; i < 2; i++)
        #pragma unroll
        for (int j = 0; j < 8; j++)
            #pragma unroll
            for (int half = 0; half < 2; half++) {
                int row = wm * 32 + i * 16 + gr + half * 8;
                int d = wn * 64 + j * 8 + gc;
                size_t idx = (size_t)(b * SEQ + s0 + row) * MODEL_DIM + h * 128 + d;
                *(__half2*)(ctxh + idx) =
                    __floats2half2_rn(acc2[i][j][half * 2 + 0], acc2[i][j][half * 2 + 1]);
            }
}

// ---------------- one-time stream/event resources --------------------------------
static cudaStream_t g_s1 = nullptr, g_s2 = nullptr;
static cudaEvent_t  ge0, ge_prep, ge_twz, ge_tmd1, ge_tmd2, ge_twk, ge_tmcw,
                    ge_twg, ge_tawq, ge_kv, ge_tawo, ge_tf1, ge_tf2,
                    ge_g0, ge_g1, ge_cum, ge_s2done;

// ---------------- host launcher -----------------------------------------------------
extern "C" void kernel_launch(void* const* d_in, const int* in_sizes, int n_in,
                              void* d_out, int out_size) {
    bool sig = (in_sizes[3] == MODEL_DIM);
    const float *x, *memory, *wk, *bk, *wz, *bz, *wg, *bg, *n1w, *n2w;
    const float *md1, *mb1, *md2, *mb2, *mcw, *mcb;
    const float *awq, *abq, *awk, *abk, *awv, *abv, *awo, *abo;
    const float *f1, *fb1, *f2, *fb2;
    #define IN(i) ((const float*)d_in[(i)])
    if (sig) {
        x = IN(0);  memory = IN(1);
        wk = IN(4);  bk = IN(5);  wz = IN(8);  bz = IN(9);  wg = IN(10); bg = IN(11);
        n1w = IN(12); n2w = IN(13);
        md1 = IN(14); mb1 = IN(15); md2 = IN(16); mb2 = IN(17); mcw = IN(18); mcb = IN(19);
        awq = IN(20); abq = IN(21); awk = IN(22); abk = IN(23); awv = IN(24); abv = IN(25);
        awo = IN(26); abo = IN(27);
        f1 = IN(28); fb1 = IN(29); f2 = IN(30); fb2 = IN(31);
    } else {
        x = IN(0);  memory = IN(1);
        wk = IN(3);  wz = IN(5);  wg = IN(6);
        md1 = IN(7); md2 = IN(8); mcw = IN(9);
        awq = IN(10); awk = IN(11); awv = IN(12); awo = IN(13);
        f1 = IN(14); f2 = IN(15);
        bk = IN(17); bz = IN(19); bg = IN(20);
        mb1 = IN(21); mb2 = IN(22); mcb = IN(23);
        abq = IN(24); abk = IN(25); abv = IN(26); abo = IN(27);
        fb1 = IN(28); fb2 = IN(29);
        n1w = IN(30); n2w = IN(31);
    }
    #undef IN

    float *zb, *glin, *tb, *m2b, *gammab, *htb, *xresb, *kvbias;
    cudaGetSymbolAddress((void**)&zb,    g_z);
    cudaGetSymbolAddress((void**)&glin,  g_glin);
    cudaGetSymbolAddress((void**)&tb,    g_t);
    cudaGetSymbolAddress((void**)&m2b,   g_m2);
    cudaGetSymbolAddress((void**)&gammab,g_gamma);
    cudaGetSymbolAddress((void**)&htb,   g_ht);
    cudaGetSymbolAddress((void**)&xresb, g_xres);
    cudaGetSymbolAddress((void**)&kvbias,g_kvbias);

    __half *xh,*xnh,*zh,*kh,*uh,*hth,*memh,*qah,*kvh,*ctxh,*xn2h,*a1h;
    cudaGetSymbolAddress((void**)&xh,  g_xh);
    cudaGetSymbolAddress((void**)&xnh, g_xnh);
    cudaGetSymbolAddress((void**)&zh,  g_zh);
    cudaGetSymbolAddress((void**)&kh,  g_kh);
    cudaGetSymbolAddress((void**)&uh,  g_uh);
    cudaGetSymbolAddress((void**)&hth, g_hth);
    cudaGetSymbolAddress((void**)&memh,g_memh);
    cudaGetSymbolAddress((void**)&qah, g_qah);
    cudaGetSymbolAddress((void**)&kvh, g_kvh);
    cudaGetSymbolAddress((void**)&ctxh,g_ctxh);
    cudaGetSymbolAddress((void**)&xn2h,g_xn2h);
    cudaGetSymbolAddress((void**)&a1h, g_a1h);

    __half *wkT,*wzT,*wgT,*mcwT,*awqT,*awoT,*awkvT,*md1T,*md2T,*f1T,*f2T;
    cudaGetSymbolAddress((void**)&wkT,  g_wk);
    cudaGetSymbolAddress((void**)&wzT,  g_wz);
    cudaGetSymbolAddress((void**)&wgT,  g_wg);
    cudaGetSymbolAddress((void**)&mcwT, g_mcw);
    cudaGetSymbolAddress((void**)&awqT, g_awq);
    cudaGetSymbolAddress((void**)&awoT, g_awo);
    cudaGetSymbolAddress((void**)&awkvT,g_awkv);
    cudaGetSymbolAddress((void**)&md1T, g_md1);
    cudaGetSymbolAddress((void**)&md2T, g_md2);
    cudaGetSymbolAddress((void**)&f1T,  g_f1);
    cudaGetSymbolAddress((void**)&f2T,  g_f2);

    float* out = (float*)d_out;
    float* cum = out + (size_t)NTOK * MODEL_DIM;

    const int SM256 = 4 * (16384 + 256 * 128);   // 196608
    const int SM128 = 4 * (16384 + 128 * 128);   // 131072
    cudaFuncSetAttribute((const void*)hgemm<256,0,false,true>,  cudaFuncAttributeMaxDynamicSharedMemorySize, SM256);
    cudaFuncSetAttribute((const void*)hgemm<256,0,true,true>,   cudaFuncAttributeMaxDynamicSharedMemorySize, SM256);
    cudaFuncSetAttribute((const void*)hgemm<256,0,true,false>,  cudaFuncAttributeMaxDynamicSharedMemorySize, SM256);
    cudaFuncSetAttribute((const void*)hgemm<256,1,false,true>,  cudaFuncAttributeMaxDynamicSharedMemorySize, SM256);
    cudaFuncSetAttribute((const void*)hgemm<256,2,true,false>,  cudaFuncAttributeMaxDynamicSharedMemorySize, SM256);
    cudaFuncSetAttribute((const void*)hgemm<256,3,true,false>,  cudaFuncAttributeMaxDynamicSharedMemorySize, SM256);
    cudaFuncSetAttribute((const void*)hgemm<128,1,false,true>,  cudaFuncAttributeMaxDynamicSharedMemorySize, SM128);
    cudaFuncSetAttribute((const void*)hgemm<128,0,false,true>,  cudaFuncAttributeMaxDynamicSharedMemorySize, SM128);
    cudaFuncSetAttribute(attn_mma, cudaFuncAttributeMaxDynamicSharedMemorySize, ATTN_SMEM2);

    dim3 tb8(32, 8);
    dim3 gT64(MODEL_DIM / 64, MODEL_DIM / 64);
    dim3 gDDh(MODEL_DIM / 256, HTOK / 128);   // (8, 16) half
    dim3 gDIh(INNER_DIM / 128, HTOK / 128);   // (4, 16) half, BN=128
    dim3 gDFh(FFN_DIM / 256,  HTOK / 128);    // (32, 16) half

    const size_t offD = (size_t)HTOK * MODEL_DIM;
    const size_t offI = (size_t)HTOK * INNER_DIM;
    const size_t offF = (size_t)HTOK * FFN_DIM;
    const size_t offKV = (size_t)MEM_TOKENS * 2 * MODEL_DIM;

    if (g_s1 == nullptr) {
        cudaStreamCreateWithFlags(&g_s1, cudaStreamNonBlocking);
        cudaStreamCreateWithFlags(&g_s2, cudaStreamNonBlocking);
        cudaEvent_t* evs[17] = {&ge0,&ge_prep,&ge_twz,&ge_tmd1,&ge_tmd2,&ge_twk,&ge_tmcw,
                                &ge_twg,&ge_tawq,&ge_kv,&ge_tawo,&ge_tf1,&ge_tf2,
                                &ge_g0,&ge_g1,&ge_cum,&ge_s2done};
        for (int i = 0; i < 17; i++) cudaEventCreateWithFlags(evs[i], cudaEventDisableTiming);
    }
    cudaStream_t s1 = g_s1, s2 = g_s2;

    // ---------- fork (every event recorded before any wait on it, in host order)
    cudaEventRecord(ge0, 0);
    cudaStreamWaitEvent(s1, ge0, 0);
    cudaStreamWaitEvent(s2, ge0, 0);

    // ---- s2: prep + rmsnorm (half 1) ----
    cvt_h<<<(NTOK * MODEL_DIM / 4) / 256, 256, 0, s2>>>(x, xh);
    concat_bias<<<(2 * MODEL_DIM) / 256, 256, 0, s2>>>(abk, abv);
    cvt_h<<<(BATCH * MEM_TOKENS * MODEL_DIM / 4) / 64, 64, 0, s2>>>(memory, memh);
    cudaEventRecord(ge_prep, s2);
    rmsnorm_h<<<HTOK, 256, 0, s2>>>(x + offD, n1w, xnh + offD);

    // ---- main: rmsnorm (half 0) ----
    rmsnorm_h<<<HTOK, 256>>>(x, n1w, xnh);

    // ---- s1: weight transposes (consumption order) + kv GEMM ----
    transpose_h2<<<gT64, tb8, 0, s1>>>(wz,  wzT,  MODEL_DIM, MODEL_DIM);
    cudaEventRecord(ge_twz, s1);
    transpose_h2<<<dim3(INNER_DIM / 64, MODEL_DIM / 64), tb8, 0, s1>>>(md1, md1T, MODEL_DIM, INNER_DIM);
    cudaEventRecord(ge_tmd1, s1);
    transpose_h2<<<dim3(MODEL_DIM / 64, INNER_DIM / 64), tb8, 0, s1>>>(md2, md2T, INNER_DIM, MODEL_DIM);
    cudaEventRecord(ge_tmd2, s1);
    transpose_h2<<<gT64, tb8, 0, s1>>>(wk,  wkT,  MODEL_DIM, MODEL_DIM);
    cudaEventRecord(ge_twk, s1);
    transpose_h2<<<gT64, tb8, 0, s1>>>(mcw, mcwT, MODEL_DIM, MODEL_DIM);
    cudaEventRecord(ge_tmcw, s1);
    transpose_h2<<<gT64, tb8, 0, s1>>>(wg,  wgT,  MODEL_DIM, MODEL_DIM);
    cudaEventRecord(ge_twg, s1);
    transpose_h2<<<gT64, tb8, 0, s1>>>(awq, awqT, MODEL_DIM, MODEL_DIM);
    cudaEventRecord(ge_tawq, s1);
    transpose_h2<<<gT64, tb8, 0, s1>>>(awk, awkvT,                               MODEL_DIM, MODEL_DIM);
    transpose_h2<<<gT64, tb8, 0, s1>>>(awv, awkvT + (size_t)MODEL_DIM*MODEL_DIM, MODEL_DIM, MODEL_DIM);
    cudaStreamWaitEvent(s1, ge_prep, 0);
    hgemm<128,0,false,true><<<dim3(2*MODEL_DIM/128, 1), 256, SM128, s1>>>(memh, awkvT, kvbias, nullptr, kvh, MODEL_DIM, 2*MODEL_DIM, nullptr, nullptr);
    cudaEventRecord(ge_kv, s1);
    transpose_h2<<<gT64, tb8, 0, s1>>>(awo, awoT, MODEL_DIM, MODEL_DIM);
    cudaEventRecord(ge_tawo, s1);
    transpose_h2<<<dim3(FFN_DIM / 64,  MODEL_DIM / 64), tb8, 0, s1>>>(f1, f1T, MODEL_DIM, FFN_DIM);
    cudaEventRecord(ge_tf1, s1);
    transpose_h2<<<dim3(MODEL_DIM / 64, FFN_DIM / 64),  tb8, 0, s1>>>(f2, f2T, FFN_DIM, MODEL_DIM);
    cudaEventRecord(ge_tf2, s1);

    // ---- main: half-0 pipeline (same-stream after transpose waits) ----
    cudaStreamWaitEvent(0, ge_twz, 0);
    hgemm<256,0,true,true><<<gDDh, 256, SM256>>>(xnh, wzT, bz, zb, zh, MODEL_DIM, MODEL_DIM, nullptr, nullptr);
    cudaStreamWaitEvent(0, ge_tmd1, 0);
    hgemm<128,1,false,true><<<gDIh, 256, SM128>>>(zh, md1T, mb1, nullptr, uh, MODEL_DIM, INNER_DIM, nullptr, nullptr);
    cudaStreamWaitEvent(0, ge_tmd2, 0);
    hgemm<256,0,true,false><<<gDDh, 256, SM256>>>(uh, md2T, mb2, tb, nullptr, INNER_DIM, MODEL_DIM, nullptr, nullptr);
    cudaStreamWaitEvent(0, ge_twk, 0);
    hgemm<256,0,false,true><<<gDDh, 256, SM256>>>(xnh, wkT, bk, nullptr, kh, MODEL_DIM, MODEL_DIM, nullptr, nullptr);
    cudaStreamWaitEvent(0, ge_tmcw, 0);
    hgemm<256,0,true,false><<<gDDh, 256, SM256>>>(kh, mcwT, mcb, m2b, nullptr, MODEL_DIM, MODEL_DIM, nullptr, nullptr);
    cudaStreamWaitEvent(0, ge_prep, 0);
    cudaStreamWaitEvent(0, ge_twg, 0);
    hgemm<256,0,true,false><<<gDDh, 256, SM256>>>(xh, wgT, bg, glin, nullptr, MODEL_DIM, MODEL_DIM, nullptr, nullptr);
    gamma_ht_kernel<<<(HTOK * MODEL_DIM) / (256 * 4), 256>>>(tb, m2b, zb, glin, x, gammab, htb, hth);
    cudaEventRecord(ge_g0, 0);

    // ---- s2: half-1 pipeline ----
    cudaStreamWaitEvent(s2, ge_twz, 0);
    hgemm<256,0,true,true><<<gDDh, 256, SM256, s2>>>(xnh + offD, wzT, bz, zb + offD, zh + offD, MODEL_DIM, MODEL_DIM, nullptr, nullptr);
    cudaStreamWaitEvent(s2, ge_tmd1, 0);
    hgemm<128,1,false,true><<<gDIh, 256, SM128, s2>>>(zh + offD, md1T, mb1, nullptr, uh + offI, MODEL_DIM, INNER_DIM, nullptr, nullptr);
    cudaStreamWaitEvent(s2, ge_tmd2, 0);
    hgemm<256,0,true,false><<<gDDh, 256, SM256, s2>>>(uh + offI, md2T, mb2, tb + offD, nullptr, INNER_DIM, MODEL_DIM, nullptr, nullptr);
    cudaStreamWaitEvent(s2, ge_twk, 0);
    hgemm<256,0,false,true><<<gDDh, 256, SM256, s2>>>(xnh + offD, wkT, bk, nullptr, kh + offD, MODEL_DIM, MODEL_DIM, nullptr, nullptr);
    cudaStreamWaitEvent(s2, ge_tmcw, 0);
    hgemm<256,0,true,false><<<gDDh, 256, SM256, s2>>>(kh + offD, mcwT, mcb, m2b + offD, nullptr, MODEL_DIM, MODEL_DIM, nullptr, nullptr);
    cudaStreamWaitEvent(s2, ge_twg, 0);
    hgemm<256,0,true,false><<<gDDh, 256, SM256, s2>>>(xh + offD, wgT, bg, glin + offD, nullptr, MODEL_DIM, MODEL_DIM, nullptr, nullptr);
    gamma_ht_kernel<<<(HTOK * MODEL_DIM) / (256 * 4), 256, 0, s2>>>(
        tb + offD, m2b + offD, zb + offD, glin + offD, x + offD,
        gammab + offD, htb + offD, hth + offD);
    cudaEventRecord(ge_g1, s2);

    // ---- s1: cumprod chain (second output; needs full gamma) ----
    cudaStreamWaitEvent(s1, ge_g0, 0);
    cudaStreamWaitEvent(s1, ge_g1, 0);
    cumprod_local<<<dim3(NCHUNK, NBH), DH, 0, s1>>>(gammab, cum);
    cumprod_scan<<<(NBH * DH) / 256, 256, 0, s1>>>();
    cumprod_apply<<<dim3(NCHUNK, NBH), DH, 0, s1>>>(cum);
    cudaEventRecord(ge_cum, s1);

    // ---- main: half-0 tail chain ----
    cudaStreamWaitEvent(0, ge_tawq, 0);
    hgemm<256,0,false,true><<<gDDh, 256, SM256>>>(hth, awqT, abq, nullptr, qah, MODEL_DIM, MODEL_DIM, nullptr, nullptr);
    cudaStreamWaitEvent(0, ge_kv, 0);
    attn_mma<<<dim3(SEQ / 64, NUM_HEADS, 1), 128, ATTN_SMEM2>>>(qah, kvh, ctxh);
    cudaStreamWaitEvent(0, ge_tawo, 0);
    hgemm<256,2,true,false><<<gDDh, 256, SM256>>>(ctxh, awoT, abo, xresb, nullptr, MODEL_DIM, MODEL_DIM, x, htb);
    rmsnorm_h<<<HTOK, 256>>>(xresb, n2w, xn2h);
    cudaStreamWaitEvent(0, ge_tf1, 0);
    hgemm<256,1,false,true><<<gDFh, 256, SM256>>>(xn2h, f1T, fb1, nullptr, a1h, MODEL_DIM, FFN_DIM, nullptr, nullptr);
    cudaStreamWaitEvent(0, ge_tf2, 0);
    hgemm<256,3,true,false><<<gDDh, 256, SM256>>>(a1h, f2T, fb2, out, nullptr, FFN_DIM, MODEL_DIM, xresb, nullptr);

    // ---- s2: half-1 tail chain ----
    cudaStreamWaitEvent(s2, ge_tawq, 0);
    hgemm<256,0,false,true><<<gDDh, 256, SM256, s2>>>(hth + offD, awqT, abq, nullptr, qah + offD, MODEL_DIM, MODEL_DIM, nullptr, nullptr);
    cudaStreamWaitEvent(s2, ge_kv, 0);
    attn_mma<<<dim3(SEQ / 64, NUM_HEADS, 1), 128, ATTN_SMEM2, s2>>>(qah + offD, kvh + offKV, ctxh + offD);
    cudaStreamWaitEvent(s2, ge_tawo, 0);
    hgemm<256,2,true,false><<<gDDh, 256, SM256, s2>>>(ctxh + offD, awoT, abo, xresb + offD, nullptr, MODEL_DIM, MODEL_DIM, x + offD, htb + offD);
    rmsnorm_h<<<HTOK, 256, 0, s2>>>(xresb + offD, n2w, xn2h + offD);
    cudaStreamWaitEvent(s2, ge_tf1, 0);
    hgemm<256,1,false,true><<<gDFh, 256, SM256, s2>>>(xn2h + offD, f1T, fb1, nullptr, a1h + offF, MODEL_DIM, FFN_DIM, nullptr, nullptr);
    cudaStreamWaitEvent(s2, ge_tf2, 0);
    hgemm<256,3,true,false><<<gDDh, 256, SM256, s2>>>(a1h + offF, f2T, fb2, out + offD, nullptr, FFN_DIM, MODEL_DIM, xresb + offD, nullptr);
    cudaEventRecord(ge_s2done, s2);

    // ---- join ----
    cudaStreamWaitEvent(0, ge_s2done, 0);
    cudaStreamWaitEvent(0, ge_cum, 0);
}